// round 5
// baseline (speedup 1.0000x reference)
#include <cuda_runtime.h>
#include <cstdint>
#include <cstddef>
#include <math.h>

typedef unsigned short u16;

constexpr int B_ = 2, T_ = 1024, H_ = 2048, NH_ = 8, NKV_ = 2, HD_ = 256;
constexpr int FF_ = 8192, LR_ = 64;
constexpr int BT_ = B_ * T_;
constexpr size_t BTH_ = (size_t)BT_ * H_;
constexpr size_t KVSZ_ = (size_t)BT_ * NKV_ * HD_;
constexpr size_t SCSZ_ = (size_t)B_ * NH_ * T_ * T_;
constexpr size_t FFSZ_ = (size_t)BT_ * FF_;
constexpr float EPS_ = 1e-6f;

struct __align__(128) Scratch {
    // fp32 working buffers
    float pred[4 * BTH_];
    float xnorm[BTH_];
    float lrpart[8 * BT_ * LR_];
    float laurel[BTH_];
    float qraw[BTH_];
    float kraw[KVSZ_];
    float vraw[KVSZ_];
    float scores[SCSZ_];
    float attnproj[BTH_];
    float attnlaurel[BTH_];
    float gate[FFSZ_];
    float up[FFSZ_];
    float ffw[BTH_];
    float act[BTH_];
    float m[BT_ * 4];
    float mc[BT_ * 4];
    // bf16 hi/lo planes (GEMM operands)
    u16 xnH[BTH_], xnL[BTH_];
    u16 hnH[BTH_], hnL[BTH_];
    u16 lrbH[BT_ * LR_], lrbL[BT_ * LR_];
    u16 qH[BTH_], qL[BTH_];
    u16 kH[KVSZ_], kL[KVSZ_];
    u16 vTH[KVSZ_], vTL[KVSZ_];
    u16 pbH[SCSZ_], pbL[SCSZ_];
    u16 aoH[BTH_], aoL[BTH_];
    u16 gpH[FFSZ_], gpL[FFSZ_];
    // weight planes
    u16 wqH[(size_t)NH_ * HD_ * H_], wqL[(size_t)NH_ * HD_ * H_];
    u16 wkH[(size_t)NKV_ * HD_ * H_], wkL[(size_t)NKV_ * HD_ * H_];
    u16 wvH[(size_t)NKV_ * HD_ * H_], wvL[(size_t)NKV_ * HD_ * H_];
    u16 woH[(size_t)H_ * NH_ * HD_], woL[(size_t)H_ * NH_ * HD_];
    u16 gwH[(size_t)FF_ * H_], gwL[(size_t)FF_ * H_];
    u16 uwH[(size_t)FF_ * H_], uwL[(size_t)FF_ * H_];
    u16 dwH[(size_t)H_ * FF_], dwL[(size_t)H_ * FF_];
    u16 lwH[(size_t)H_ * LR_], lwL[(size_t)H_ * LR_];
};
__device__ Scratch g_scratch;

// ---------- bf16 bit helpers ----------
__device__ __forceinline__ uint32_t f2bf(float x) {
    uint32_t u = __float_as_uint(x);
    return (u + 0x7FFFu + ((u >> 16) & 1u)) >> 16;
}
__device__ __forceinline__ float bf2f(uint32_t b) {
    return __uint_as_float(b << 16);
}
__device__ __forceinline__ void storePair(u16* H, u16* L, size_t off, float a, float b) {
    uint32_t ha = f2bf(a), hb = f2bf(b);
    uint32_t la = f2bf(a - bf2f(ha)), lb = f2bf(b - bf2f(hb));
    *reinterpret_cast<uint32_t*>(&H[off]) = ha | (hb << 16);
    *reinterpret_cast<uint32_t*>(&L[off]) = la | (lb << 16);
}

// ---------- reductions ----------
__device__ __forceinline__ float warpSum(float v) {
#pragma unroll
    for (int o = 16; o > 0; o >>= 1) v += __shfl_xor_sync(0xffffffffu, v, o);
    return v;
}
__device__ __forceinline__ float warpMax(float v) {
#pragma unroll
    for (int o = 16; o > 0; o >>= 1) v = fmaxf(v, __shfl_xor_sync(0xffffffffu, v, o));
    return v;
}
__device__ __forceinline__ float blockSum(float v, float* red) {
    v = warpSum(v);
    int lane = threadIdx.x & 31, w = threadIdx.x >> 5;
    if (lane == 0) red[w] = v;
    __syncthreads();
    int nw = (blockDim.x + 31) >> 5;
    float r = (lane < nw) ? red[lane] : 0.f;
    if (w == 0) {
        r = warpSum(r);
        if (lane == 0) red[0] = r;
    }
    __syncthreads();
    r = red[0];
    __syncthreads();
    return r;
}
__device__ __forceinline__ float blockMax(float v, float* red) {
    v = warpMax(v);
    int lane = threadIdx.x & 31, w = threadIdx.x >> 5;
    if (lane == 0) red[w] = v;
    __syncthreads();
    int nw = (blockDim.x + 31) >> 5;
    float r = (lane < nw) ? red[lane] : -INFINITY;
    if (w == 0) {
        r = warpMax(r);
        if (lane == 0) red[0] = r;
    }
    __syncthreads();
    r = red[0];
    __syncthreads();
    return r;
}

// ---------- LN: dst = scale*(LN(a)*w + add1? + add2?), optional bf16 planes ----------
__global__ void ln_kernel(const float* __restrict__ a, const float* __restrict__ w,
                          const float* __restrict__ add1, const float* __restrict__ add2,
                          float scale, float* __restrict__ dst,
                          u16* __restrict__ dstH, u16* __restrict__ dstL) {
    __shared__ float sx[H_];
    __shared__ float red[32];
    size_t off = (size_t)blockIdx.x * H_;
    int tid = threadIdx.x;
    float ls = 0.f;
    for (int i = tid; i < H_; i += blockDim.x) {
        float v = a[off + i];
        sx[i] = v;
        ls += v;
    }
    float mean = blockSum(ls, red) * (1.f / H_);
    float lv = 0.f;
    for (int i = tid; i < H_; i += blockDim.x) {
        float d = sx[i] - mean;
        lv += d * d;
    }
    float var = blockSum(lv, red) * (1.f / H_);
    float rs = rsqrtf(var + EPS_);
    for (int i = tid; i < H_; i += blockDim.x) {
        float v = (sx[i] - mean) * rs * w[i];
        if (add1) v += add1[off + i];
        if (add2) v += add2[off + i];
        v *= scale;
        if (dst) dst[off + i] = v;
        if (dstH) {
            uint32_t h = f2bf(v);
            dstH[off + i] = (u16)h;
            dstL[off + i] = (u16)f2bf(v - bf2f(h));
        }
    }
}

__global__ void router_kernel(const float* __restrict__ x, const float* __restrict__ nw,
                              const float* __restrict__ rw, float* __restrict__ m) {
    __shared__ float sx[H_];
    __shared__ float red[32];
    size_t off = (size_t)blockIdx.x * H_;
    int tid = threadIdx.x;
    float ls = 0.f;
    for (int i = tid; i < H_; i += blockDim.x) {
        float v = x[off + i];
        sx[i] = v;
        ls += v;
    }
    float mean = blockSum(ls, red) * (1.f / H_);
    float lv = 0.f;
    for (int i = tid; i < H_; i += blockDim.x) {
        float d = sx[i] - mean;
        lv += d * d;
    }
    float rs = rsqrtf(blockSum(lv, red) * (1.f / H_) + EPS_);
    float a0 = 0.f, a1 = 0.f, a2 = 0.f, a3 = 0.f;
    for (int i = tid; i < H_; i += blockDim.x) {
        float r = (sx[i] - mean) * rs * nw[i] * (1.f / H_);
        a0 += r * rw[i];
        a1 += r * rw[H_ + i];
        a2 += r * rw[2 * H_ + i];
        a3 += r * rw[3 * H_ + i];
    }
    float t0 = blockSum(a0, red);
    float t1 = blockSum(a1, red);
    float t2 = blockSum(a2, red);
    float t3 = blockSum(a3, red);
    if (tid == 0) {
        m[blockIdx.x * 4 + 0] = tanhf(t0);
        m[blockIdx.x * 4 + 1] = tanhf(t1);
        m[blockIdx.x * 4 + 2] = tanhf(t2);
        m[blockIdx.x * 4 + 3] = tanhf(t3);
    }
}

__global__ void predict_kernel(const float* __restrict__ hs, const float* __restrict__ m,
                               const float* __restrict__ pcw, float* __restrict__ pred) {
    __shared__ float cf[16];
    int token = blockIdx.x, tid = threadIdx.x;
    if (tid < 16) {
        float s = 0.f;
#pragma unroll
        for (int i = 0; i < 4; i++) s += m[token * 4 + i] * pcw[tid * 4 + i];
        cf[tid] = s;
    }
    __syncthreads();
    size_t off = (size_t)token * H_;
    for (int f = tid; f < H_; f += blockDim.x) {
        float h0 = hs[off + f];
        float h1 = hs[BTH_ + off + f];
        float h2 = hs[2 * BTH_ + off + f];
        float h3 = hs[3 * BTH_ + off + f];
        pred[off + f]            = h0 + h0 * cf[0]  + h1 * cf[1]  + h2 * cf[2]  + h3 * cf[3];
        pred[BTH_ + off + f]     = h1 + h0 * cf[4]  + h1 * cf[5]  + h2 * cf[6]  + h3 * cf[7];
        pred[2 * BTH_ + off + f] = h2 + h0 * cf[8]  + h1 * cf[9]  + h2 * cf[10] + h3 * cf[11];
        pred[3 * BTH_ + off + f] = h3 + h0 * cf[12] + h1 * cf[13] + h2 * cf[14] + h3 * cf[15];
    }
}

__global__ void correct_kernel(const float* __restrict__ act, const float* __restrict__ pred,
                               const float* __restrict__ mc, const float* __restrict__ ccw,
                               const float* __restrict__ cscale, float* __restrict__ out) {
    __shared__ float cc[4];
    int token = blockIdx.x, tid = threadIdx.x;
    if (tid < 4) {
        float s = 1.f;
#pragma unroll
        for (int i = 0; i < 4; i++) s += mc[token * 4 + i] * ccw[tid * 4 + i];
        cc[tid] = s;
    }
    __syncthreads();
    size_t off = (size_t)token * H_;
    for (int f = tid; f < H_; f += blockDim.x) {
        float p0 = pred[off + f];
        float inno = act[off + f] - p0;
        out[off + f]            = (inno * cc[0] + p0) * cscale[f];
        out[BTH_ + off + f]     = inno * cc[1] + pred[BTH_ + off + f];
        out[2 * BTH_ + off + f] = inno * cc[2] + pred[2 * BTH_ + off + f];
        out[3 * BTH_ + off + f] = inno * cc[3] + pred[3 * BTH_ + off + f];
    }
}

// per-head LN (+rope), writes bf16 planes
__global__ void qkvpost_kernel(const float* __restrict__ raw, const float* __restrict__ nw,
                               const float* __restrict__ cosb, const float* __restrict__ sinb,
                               u16* __restrict__ outH, u16* __restrict__ outL,
                               int nheads, int do_rope, int trans) {
    __shared__ float sx[HD_];
    __shared__ float red[32];
    int idx = blockIdx.x;
    int h = idx % nheads;
    int bt = idx / nheads;
    int t = bt % T_, b = bt / T_;
    int d = threadIdx.x;
    float v = raw[(size_t)bt * nheads * HD_ + h * HD_ + d];
    float mean = blockSum(v, red) * (1.f / HD_);
    float c = v - mean;
    float var = blockSum(c * c, red) * (1.f / HD_);
    float ln = c * rsqrtf(var + EPS_) * (nw ? nw[d] : 1.f);
    sx[d] = ln;
    __syncthreads();
    float o = ln;
    if (do_rope) {
        float cs = cosb[(size_t)bt * HD_ + d];
        float sn = sinb[(size_t)bt * HD_ + d];
        float rot = (d < 128) ? -sx[d + 128] : sx[d - 128];
        o = ln * cs + rot * sn;
    }
    size_t oidx;
    if (trans) oidx = ((size_t)(b * nheads + h) * HD_ + d) * T_ + t;
    else       oidx = ((size_t)(b * nheads + h) * T_ + t) * HD_ + d;
    uint32_t hh = f2bf(o);
    outH[oidx] = (u16)hh;
    outL[oidx] = (u16)f2bf(o - bf2f(hh));
}

// causal softmax -> bf16 planes
__global__ void softmax_kernel(const float* __restrict__ scores,
                               u16* __restrict__ pH, u16* __restrict__ pL) {
    __shared__ float sx[T_];
    __shared__ float red[32];
    int q = blockIdx.x % T_;
    size_t off = (size_t)blockIdx.x * T_;
    int tid = threadIdx.x;
    int n = q + 1;
    float lm = -INFINITY;
    for (int i = tid; i < n; i += blockDim.x) {
        float v = scores[off + i];
        sx[i] = v;
        lm = fmaxf(lm, v);
    }
    float gm = blockMax(lm, red);
    float lsum = 0.f;
    for (int i = tid; i < n; i += blockDim.x) {
        float e = __expf(sx[i] - gm);
        sx[i] = e;
        lsum += e;
    }
    float inv = 1.f / blockSum(lsum, red);
    for (int i = tid; i < T_; i += blockDim.x) {
        float p = (i < n) ? sx[i] * inv : 0.f;
        uint32_t h = f2bf(p);
        pH[off + i] = (u16)h;
        pL[off + i] = (u16)f2bf(p - bf2f(h));
    }
}

__device__ __forceinline__ float gelu_tanh(float x) {
    return 0.5f * x * (1.f + tanhf(0.7978845608028654f * (x + 0.044715f * x * x * x)));
}

// gelu(g)*u -> bf16 planes
__global__ void gelumul_kernel(const float* __restrict__ g, const float* __restrict__ u,
                               u16* __restrict__ oH, u16* __restrict__ oL, int n4) {
    int i = blockIdx.x * blockDim.x + threadIdx.x;
    if (i >= n4) return;
    float4 a = reinterpret_cast<const float4*>(g)[i];
    float4 b = reinterpret_cast<const float4*>(u)[i];
    a.x = gelu_tanh(a.x) * b.x;
    a.y = gelu_tanh(a.y) * b.y;
    a.z = gelu_tanh(a.z) * b.z;
    a.w = gelu_tanh(a.w) * b.w;
    storePair(oH, oL, (size_t)i * 4, a.x, a.y);
    storePair(oH, oL, (size_t)i * 4 + 2, a.z, a.w);
}

// fp32 -> bf16 hi/lo planes (weights)
__global__ void split_kernel(const float* __restrict__ in, u16* __restrict__ h,
                             u16* __restrict__ l, int n4) {
    int i = blockIdx.x * blockDim.x + threadIdx.x;
    if (i >= n4) return;
    float4 v = reinterpret_cast<const float4*>(in)[i];
    storePair(h, l, (size_t)i * 4, v.x, v.y);
    storePair(h, l, (size_t)i * 4 + 2, v.z, v.w);
}

// ===== pipelined bf16-split tensor-core GEMM: C = A[M,K]@B[N,K]^T =====
// A,B given as bf16 hi/lo planes. 128x128 tiles, k16 stages, cp.async x2 buffers.
constexpr int PLW = 12;                 // 12 words = 48B padded row (conflict-free)
constexpr int STAGE_BYTES = 128 * PLW * 4 * 4;   // 4 planes = 24576 B

struct PStage {
    uint32_t Ah[128][PLW];
    uint32_t Al[128][PLW];
    uint32_t Bh[128][PLW];
    uint32_t Bl[128][PLW];
};

__device__ __forceinline__ void cpa16(uint32_t dst, const void* src) {
    asm volatile("cp.async.cg.shared.global [%0], [%1], 16;" :: "r"(dst), "l"(src));
}
__device__ __forceinline__ void cp_commit() {
    asm volatile("cp.async.commit_group;");
}
__device__ __forceinline__ void ldsm4(uint32_t* r, uint32_t addr) {
    asm volatile("ldmatrix.sync.aligned.m8n8.x4.shared.b16 {%0,%1,%2,%3}, [%4];"
                 : "=r"(r[0]), "=r"(r[1]), "=r"(r[2]), "=r"(r[3]) : "r"(addr));
}
__device__ __forceinline__ void mma16816(float* d, const uint32_t* a, uint32_t b0, uint32_t b1) {
    asm volatile("mma.sync.aligned.m16n8k16.row.col.f32.bf16.bf16.f32 "
                 "{%0,%1,%2,%3}, {%4,%5,%6,%7}, {%8,%9}, {%0,%1,%2,%3};"
                 : "+f"(d[0]), "+f"(d[1]), "+f"(d[2]), "+f"(d[3])
                 : "r"(a[0]), "r"(a[1]), "r"(a[2]), "r"(a[3]), "r"(b0), "r"(b1));
}

__device__ __forceinline__ void stage_load(
    uint32_t sbase, const u16* AH, const u16* AL, const u16* BH, const u16* BL,
    int bm, int bn, int k0, int lda, int ldb, int tid)
{
    int row = tid >> 1;
    int half = tid & 1;
    uint32_t dOff = (uint32_t)(row * 48 + half * 16);
    size_t aoff = (size_t)(bm + row) * lda + k0 + half * 8;
    size_t boff = (size_t)(bn + row) * ldb + k0 + half * 8;
    cpa16(sbase + dOff,                          AH + aoff);
    cpa16(sbase + 128 * PLW * 4 + dOff,          AL + aoff);
    cpa16(sbase + 2 * 128 * PLW * 4 + dOff,      BH + boff);
    cpa16(sbase + 3 * 128 * PLW * 4 + dOff,      BL + boff);
}

__device__ __forceinline__ void pcore(
    const u16* __restrict__ AH, const u16* __restrict__ AL,
    const u16* __restrict__ BH, const u16* __restrict__ BL,
    float* __restrict__ C, u16* __restrict__ CH, u16* __restrict__ CL,
    int K, int lda, int ldb, int ldc, int bm, int bn, uint32_t sb)
{
    const int tid = threadIdx.x;
    const int lane = tid & 31, wid = tid >> 5;
    const int wm = wid & 3, wn = wid >> 2;

    float acc[2][8][4];
#pragma unroll
    for (int i = 0; i < 2; i++)
#pragma unroll
        for (int j = 0; j < 8; j++)
#pragma unroll
            for (int e = 0; e < 4; e++) acc[i][j][e] = 0.f;

    const int arow = wm * 32 + (lane & 15);
    const int acol = (lane >> 4) * 8;
    const int brow = wn * 64 + (lane & 7) + ((lane >> 4) << 3);
    const int bcol = ((lane >> 3) & 1) << 3;

    const int KT = K >> 4;
    stage_load(sb, AH, AL, BH, BL, bm, bn, 0, lda, ldb, tid);
    cp_commit();

    for (int kt = 0; kt < KT; kt++) {
        uint32_t cs = sb + (uint32_t)(kt & 1) * STAGE_BYTES;
        if (kt + 1 < KT) {
            stage_load(sb + (uint32_t)((kt + 1) & 1) * STAGE_BYTES,
                       AH, AL, BH, BL, bm, bn, (kt + 1) << 4, lda, ldb, tid);
            cp_commit();
            asm volatile("cp.async.wait_group 1;");
        } else {
            asm volatile("cp.async.wait_group 0;");
        }
        __syncthreads();

        uint32_t ah[2][4], al[2][4];
#pragma unroll
        for (int mf = 0; mf < 2; mf++) {
            uint32_t ao = (uint32_t)((arow + mf * 16) * 48 + acol * 2);
            ldsm4(ah[mf], cs + ao);
            ldsm4(al[mf], cs + 128 * PLW * 4 + ao);
        }
#pragma unroll
        for (int np = 0; np < 4; np++) {
            uint32_t bh[4], bl[4];
            uint32_t bo = (uint32_t)((brow + np * 16) * 48 + bcol * 2);
            ldsm4(bh, cs + 2 * 128 * PLW * 4 + bo);
            ldsm4(bl, cs + 3 * 128 * PLW * 4 + bo);
#pragma unroll
            for (int j = 0; j < 2; j++) {
                int nf = np * 2 + j;
#pragma unroll
                for (int mf = 0; mf < 2; mf++) {
                    mma16816(acc[mf][nf], ah[mf], bh[j * 2], bh[j * 2 + 1]);
                    mma16816(acc[mf][nf], al[mf], bh[j * 2], bh[j * 2 + 1]);
                    mma16816(acc[mf][nf], ah[mf], bl[j * 2], bl[j * 2 + 1]);
                }
            }
        }
        __syncthreads();
    }

#pragma unroll
    for (int mf = 0; mf < 2; mf++) {
        int row = bm + wm * 32 + mf * 16 + (lane >> 2);
#pragma unroll
        for (int nf = 0; nf < 8; nf++) {
            int col = bn + wn * 64 + nf * 8 + (lane & 3) * 2;
            if (CH) {
                storePair(CH, CL, (size_t)row * ldc + col, acc[mf][nf][0], acc[mf][nf][1]);
                storePair(CH, CL, (size_t)(row + 8) * ldc + col, acc[mf][nf][2], acc[mf][nf][3]);
            } else {
                *reinterpret_cast<float2*>(&C[(size_t)row * ldc + col]) =
                    make_float2(acc[mf][nf][0], acc[mf][nf][1]);
                *reinterpret_cast<float2*>(&C[(size_t)(row + 8) * ldc + col]) =
                    make_float2(acc[mf][nf][2], acc[mf][nf][3]);
            }
        }
    }
}

__global__ void __launch_bounds__(256, 2)
mma_nt(const u16* __restrict__ AH, const u16* __restrict__ AL,
       const u16* __restrict__ BH, const u16* __restrict__ BL,
       float* __restrict__ C, u16* __restrict__ CH, u16* __restrict__ CL,
       int K, int lda, int ldb, int ldc) {
    __shared__ PStage st[2];
    uint32_t sb = (uint32_t)__cvta_generic_to_shared(st);
    pcore(AH, AL, BH, BL, C, CH, CL, K, lda, ldb, ldc,
          blockIdx.x * 128, blockIdx.y * 128, sb);
}

__global__ void __launch_bounds__(256, 2)
mma_scores(const u16* __restrict__ qH, const u16* __restrict__ qL,
           const u16* __restrict__ kH, const u16* __restrict__ kL,
           float* __restrict__ sc) {
    if (blockIdx.y > blockIdx.x) return;
    int z = blockIdx.z;
    int b = z >> 3, h = z & 7;
    size_t qo = (size_t)z * T_ * HD_;
    size_t ko = (size_t)(b * NKV_ + (h >> 2)) * T_ * HD_;
    __shared__ PStage st[2];
    uint32_t sb = (uint32_t)__cvta_generic_to_shared(st);
    pcore(qH + qo, qL + qo, kH + ko, kL + ko,
          sc + (size_t)z * T_ * T_, (u16*)0, (u16*)0,
          HD_, HD_, HD_, T_, blockIdx.x * 128, blockIdx.y * 128, sb);
}

__global__ void __launch_bounds__(256, 2)
mma_attnv(const u16* __restrict__ pH, const u16* __restrict__ pL,
          const u16* __restrict__ vH, const u16* __restrict__ vL,
          u16* __restrict__ oH, u16* __restrict__ oL) {
    int z = blockIdx.z;
    int b = z >> 3, h = z & 7;
    size_t po = (size_t)z * T_ * T_;
    size_t vo = (size_t)(b * NKV_ + (h >> 2)) * HD_ * T_;
    size_t co = (size_t)b * T_ * H_ + (size_t)h * HD_;
    int bm = blockIdx.x * 128;
    __shared__ PStage st[2];
    uint32_t sb = (uint32_t)__cvta_generic_to_shared(st);
    pcore(pH + po, pL + po, vH + vo, vL + vo,
          (float*)0, oH + co, oL + co,
          bm + 128, T_, T_, H_, bm, blockIdx.y * 128, sb);
}

// laurel1: P[ks] = A[2048,2048(slice)] @ B[64,2048]^T, split-K x8
__global__ void __launch_bounds__(256)
laurel1_kernel(const float* __restrict__ A, const float* __restrict__ B, float* __restrict__ P) {
    __shared__ float Bs[64][65];
    __shared__ float As[32][65];
    int tid = threadIdx.x;
    int bm = blockIdx.x * 32;
    int ks = blockIdx.y;
    int kbeg = ks * (H_ / 8), kend = kbeg + H_ / 8;
    float acc0[4] = {0.f, 0.f, 0.f, 0.f};
    float acc1[4] = {0.f, 0.f, 0.f, 0.f};
    int tn = tid & 15;
    int tr = tid >> 4;
    for (int k0 = kbeg; k0 < kend; k0 += 64) {
        for (int i = tid; i < 64 * 64; i += 256) {
            int n = i >> 6, kk = i & 63;
            Bs[n][kk] = B[(size_t)n * H_ + k0 + kk];
        }
        for (int i = tid; i < 32 * 64; i += 256) {
            int r = i >> 6, kk = i & 63;
            As[r][kk] = A[(size_t)(bm + r) * H_ + k0 + kk];
        }
        __syncthreads();
#pragma unroll 8
        for (int kk = 0; kk < 64; kk++) {
            float a0 = As[tr][kk], a1 = As[tr + 16][kk];
#pragma unroll
            for (int j = 0; j < 4; j++) {
                float bv = Bs[tn * 4 + j][kk];
                acc0[j] = fmaf(a0, bv, acc0[j]);
                acc1[j] = fmaf(a1, bv, acc1[j]);
            }
        }
        __syncthreads();
    }
#pragma unroll
    for (int j = 0; j < 4; j++) {
        P[((size_t)ks * BT_ + bm + tr) * LR_ + tn * 4 + j] = acc0[j];
        P[((size_t)ks * BT_ + bm + tr + 16) * LR_ + tn * 4 + j] = acc1[j];
    }
}

__global__ void laurel1_reduce(const float* __restrict__ P,
                               u16* __restrict__ oH, u16* __restrict__ oL) {
    int i = blockIdx.x * blockDim.x + threadIdx.x;
    if (i >= BT_ * LR_) return;
    float s = 0.f;
#pragma unroll
    for (int k = 0; k < 8; k++) s += P[(size_t)k * BT_ * LR_ + i];
    uint32_t h = f2bf(s);
    oH[i] = (u16)h;
    oL[i] = (u16)f2bf(s - bf2f(h));
}

extern "C" void kernel_launch(void* const* d_in, const int* in_sizes, int n_in,
                              void* d_out, int out_size) {
    const float* hs    = (const float*)d_in[0];
    const float* cosb  = (const float*)d_in[1];
    const float* sinb  = (const float*)d_in[2];
    const float* wq    = (const float*)d_in[3];
    const float* wk    = (const float*)d_in[4];
    const float* wv    = (const float*)d_in[5];
    const float* wo    = (const float*)d_in[6];
    const float* qnw   = (const float*)d_in[7];
    const float* knw   = (const float*)d_in[8];
    const float* in_ln = (const float*)d_in[9];
    const float* pa_ln = (const float*)d_in[10];
    const float* pf_ln = (const float*)d_in[11];
    const float* pw_ln = (const float*)d_in[12];
    const float* gatew = (const float*)d_in[13];
    const float* upw   = (const float*)d_in[14];
    const float* downw = (const float*)d_in[15];
    const float* llw   = (const float*)d_in[16];
    const float* lrw   = (const float*)d_in[17];
    const float* lnw   = (const float*)d_in[18];
    const float* rnw   = (const float*)d_in[19];
    const float* rw    = (const float*)d_in[20];
    const float* pcw   = (const float*)d_in[21];
    const float* ccw   = (const float*)d_in[22];
    const float* cscal = (const float*)d_in[23];
    float* out = (float*)d_out;

    Scratch* S = 0;
    cudaGetSymbolAddress((void**)&S, g_scratch);

    // weight splits (independent of activations)
    {
        struct { const float* w; u16* h; u16* l; size_t n; } ws[8] = {
            { wq,    S->wqH, S->wqL, (size_t)NH_ * HD_ * H_ },
            { wk,    S->wkH, S->wkL, (size_t)NKV_ * HD_ * H_ },
            { wv,    S->wvH, S->wvL, (size_t)NKV_ * HD_ * H_ },
            { wo,    S->woH, S->woL, (size_t)H_ * NH_ * HD_ },
            { gatew, S->gwH, S->gwL, (size_t)FF_ * H_ },
            { upw,   S->uwH, S->uwL, (size_t)FF_ * H_ },
            { downw, S->dwH, S->dwL, (size_t)H_ * FF_ },
            { lrw,   S->lwH, S->lwL, (size_t)H_ * LR_ },
        };
        for (int i = 0; i < 8; i++) {
            int n4 = (int)(ws[i].n / 4);
            split_kernel<<<(n4 + 255) / 256, 256>>>(ws[i].w, ws[i].h, ws[i].l, n4);
        }
    }

    router_kernel<<<BT_, 256>>>(hs, rnw, rw, S->m);
    predict_kernel<<<BT_, 256>>>(hs, S->m, pcw, S->pred);
    ln_kernel<<<BT_, 256>>>(S->pred, in_ln, (const float*)0, (const float*)0, 1.f,
                            S->xnorm, S->xnH, S->xnL);

    // laurel
    laurel1_kernel<<<dim3(BT_ / 32, 8), 256>>>(S->xnorm, llw, S->lrpart);
    laurel1_reduce<<<(BT_ * LR_ + 255) / 256, 256>>>(S->lrpart, S->lrbH, S->lrbL);
    mma_nt<<<dim3(16, 16), 256>>>(S->lrbH, S->lrbL, S->lwH, S->lwL,
                                  S->laurel, (u16*)0, (u16*)0, LR_, LR_, LR_, H_);
    ln_kernel<<<BT_, 256>>>(S->laurel, lnw, S->xnorm, (const float*)0, 1.f,
                            S->laurel, (u16*)0, (u16*)0);

    // QKV projections
    mma_nt<<<dim3(16, 16), 256>>>(S->xnH, S->xnL, S->wqH, S->wqL,
                                  S->qraw, (u16*)0, (u16*)0, H_, H_, H_, NH_ * HD_);
    mma_nt<<<dim3(16, 4), 256>>>(S->xnH, S->xnL, S->wkH, S->wkL,
                                 S->kraw, (u16*)0, (u16*)0, H_, H_, H_, NKV_ * HD_);
    mma_nt<<<dim3(16, 4), 256>>>(S->xnH, S->xnL, S->wvH, S->wvL,
                                 S->vraw, (u16*)0, (u16*)0, H_, H_, H_, NKV_ * HD_);
    qkvpost_kernel<<<BT_ * NH_, 256>>>(S->qraw, qnw, cosb, sinb, S->qH, S->qL, NH_, 1, 0);
    qkvpost_kernel<<<BT_ * NKV_, 256>>>(S->kraw, knw, cosb, sinb, S->kH, S->kL, NKV_, 1, 0);
    qkvpost_kernel<<<BT_ * NKV_, 256>>>(S->vraw, (const float*)0, cosb, sinb,
                                        S->vTH, S->vTL, NKV_, 0, 1);

    // attention
    mma_scores<<<dim3(8, 8, B_ * NH_), 256>>>(S->qH, S->qL, S->kH, S->kL, S->scores);
    softmax_kernel<<<B_ * NH_ * T_, 256>>>(S->scores, S->pbH, S->pbL);
    mma_attnv<<<dim3(8, 2, B_ * NH_), 256>>>(S->pbH, S->pbL, S->vTH, S->vTL, S->aoH, S->aoL);
    mma_nt<<<dim3(16, 16), 256>>>(S->aoH, S->aoL, S->woH, S->woL,
                                  S->attnproj, (u16*)0, (u16*)0,
                                  NH_ * HD_, NH_ * HD_, NH_ * HD_, H_);

    ln_kernel<<<BT_, 256>>>(S->attnproj, pa_ln, S->pred, S->laurel,
                            0.7071067811865476f, S->attnlaurel, (u16*)0, (u16*)0);
    ln_kernel<<<BT_, 256>>>(S->attnlaurel, pf_ln, (const float*)0, (const float*)0, 1.f,
                            (float*)0, S->hnH, S->hnL);

    // MLP
    mma_nt<<<dim3(16, 64), 256>>>(S->hnH, S->hnL, S->gwH, S->gwL,
                                  S->gate, (u16*)0, (u16*)0, H_, H_, H_, FF_);
    mma_nt<<<dim3(16, 64), 256>>>(S->hnH, S->hnL, S->uwH, S->uwL,
                                  S->up, (u16*)0, (u16*)0, H_, H_, H_, FF_);
    {
        int n4 = (int)(FFSZ_ / 4);
        gelumul_kernel<<<(n4 + 255) / 256, 256>>>(S->gate, S->up, S->gpH, S->gpL, n4);
    }
    mma_nt<<<dim3(16, 16), 256>>>(S->gpH, S->gpL, S->dwH, S->dwL,
                                  S->ffw, (u16*)0, (u16*)0, FF_, FF_, FF_, H_);
    ln_kernel<<<BT_, 256>>>(S->ffw, pw_ln, S->attnlaurel, (const float*)0, 1.f,
                            S->act, (u16*)0, (u16*)0);

    // AltUp correct
    router_kernel<<<BT_, 256>>>(S->act, rnw, rw, S->mc);
    correct_kernel<<<BT_, 256>>>(S->act, S->pred, S->mc, ccw, cscal, out);

    (void)in_sizes; (void)n_in; (void)out_size;
}

// round 7
// speedup vs baseline: 1.2547x; 1.2547x over previous
#include <cuda_runtime.h>
#include <cstdint>
#include <cstddef>
#include <math.h>

typedef unsigned short u16;

constexpr int B_ = 2, T_ = 1024, H_ = 2048, NH_ = 8, NKV_ = 2, HD_ = 256;
constexpr int FF_ = 8192, LR_ = 64;
constexpr int BT_ = B_ * T_;
constexpr size_t BTH_ = (size_t)BT_ * H_;
constexpr float EPS_ = 1e-6f;

struct Scratch {
    float pred[4 * BTH_];
    float xnorm[BTH_];
    float lrpart[4 * BT_ * LR_];
    float lrbuf[BT_ * LR_];
    float laurel[BTH_];
    float qraw[BTH_];
    float kraw[(size_t)BT_ * NKV_ * HD_];
    float vraw[(size_t)BT_ * NKV_ * HD_];
    float q[BTH_];
    float k[(size_t)BT_ * NKV_ * HD_];
    float vT[(size_t)BT_ * NKV_ * HD_];
    float scores[(size_t)B_ * NH_ * T_ * T_];
    float attnout[BTH_];
    float attnproj[BTH_];
    float attnlaurel[BTH_];
    float hn[BTH_];
    float gate[(size_t)BT_ * FF_];
    float up[(size_t)BT_ * FF_];
    float ffw[BTH_];
    float act[BTH_];
    float m[BT_ * 4];
    float mc[BT_ * 4];
};
__device__ Scratch g_scratch;

// ---------- bf16 / fp16 bit helpers ----------
__device__ __forceinline__ uint32_t f2bf(float x) {
    uint32_t u = __float_as_uint(x);
    return (u + 0x7FFFu + ((u >> 16) & 1u)) >> 16;
}
__device__ __forceinline__ float bf2f(uint32_t b) {
    return __uint_as_float(b << 16);
}
__device__ __forceinline__ u16 f2h(float x) {
    u16 h;
    asm("cvt.rn.f16.f32 %0, %1;" : "=h"(h) : "f"(x));
    return h;
}
__device__ __forceinline__ float h2f(u16 h) {
    float f;
    asm("cvt.f32.f16 %0, %1;" : "=f"(f) : "h"(h));
    return f;
}

// ---------- reductions ----------
__device__ __forceinline__ float warpSum(float v) {
#pragma unroll
    for (int o = 16; o > 0; o >>= 1) v += __shfl_xor_sync(0xffffffffu, v, o);
    return v;
}
__device__ __forceinline__ float warpMax(float v) {
#pragma unroll
    for (int o = 16; o > 0; o >>= 1) v = fmaxf(v, __shfl_xor_sync(0xffffffffu, v, o));
    return v;
}
__device__ __forceinline__ float blockSum(float v, float* red) {
    v = warpSum(v);
    int lane = threadIdx.x & 31, w = threadIdx.x >> 5;
    if (lane == 0) red[w] = v;
    __syncthreads();
    int nw = (blockDim.x + 31) >> 5;
    float r = (lane < nw) ? red[lane] : 0.f;
    if (w == 0) {
        r = warpSum(r);
        if (lane == 0) red[0] = r;
    }
    __syncthreads();
    r = red[0];
    __syncthreads();
    return r;
}
__device__ __forceinline__ float blockMax(float v, float* red) {
    v = warpMax(v);
    int lane = threadIdx.x & 31, w = threadIdx.x >> 5;
    if (lane == 0) red[w] = v;
    __syncthreads();
    int nw = (blockDim.x + 31) >> 5;
    float r = (lane < nw) ? red[lane] : -INFINITY;
    if (w == 0) {
        r = warpMax(r);
        if (lane == 0) red[0] = r;
    }
    __syncthreads();
    r = red[0];
    __syncthreads();
    return r;
}

// ---------- elementwise kernels (R4-proven) ----------
__global__ void ln_kernel(const float* __restrict__ a, const float* __restrict__ w,
                          const float* __restrict__ add1, const float* __restrict__ add2,
                          float scale, float* __restrict__ dst) {
    __shared__ float sx[H_];
    __shared__ float red[32];
    size_t off = (size_t)blockIdx.x * H_;
    int tid = threadIdx.x;
    float ls = 0.f;
    for (int i = tid; i < H_; i += blockDim.x) {
        float v = a[off + i];
        sx[i] = v;
        ls += v;
    }
    float mean = blockSum(ls, red) * (1.f / H_);
    float lv = 0.f;
    for (int i = tid; i < H_; i += blockDim.x) {
        float d = sx[i] - mean;
        lv += d * d;
    }
    float var = blockSum(lv, red) * (1.f / H_);
    float rs = rsqrtf(var + EPS_);
    for (int i = tid; i < H_; i += blockDim.x) {
        float v = (sx[i] - mean) * rs * w[i];
        if (add1) v += add1[off + i];
        if (add2) v += add2[off + i];
        dst[off + i] = v * scale;
    }
}

__global__ void router_kernel(const float* __restrict__ x, const float* __restrict__ nw,
                              const float* __restrict__ rw, float* __restrict__ m) {
    __shared__ float sx[H_];
    __shared__ float red[32];
    size_t off = (size_t)blockIdx.x * H_;
    int tid = threadIdx.x;
    float ls = 0.f;
    for (int i = tid; i < H_; i += blockDim.x) {
        float v = x[off + i];
        sx[i] = v;
        ls += v;
    }
    float mean = blockSum(ls, red) * (1.f / H_);
    float lv = 0.f;
    for (int i = tid; i < H_; i += blockDim.x) {
        float d = sx[i] - mean;
        lv += d * d;
    }
    float rs = rsqrtf(blockSum(lv, red) * (1.f / H_) + EPS_);
    float a0 = 0.f, a1 = 0.f, a2 = 0.f, a3 = 0.f;
    for (int i = tid; i < H_; i += blockDim.x) {
        float r = (sx[i] - mean) * rs * nw[i] * (1.f / H_);
        a0 += r * rw[i];
        a1 += r * rw[H_ + i];
        a2 += r * rw[2 * H_ + i];
        a3 += r * rw[3 * H_ + i];
    }
    float t0 = blockSum(a0, red);
    float t1 = blockSum(a1, red);
    float t2 = blockSum(a2, red);
    float t3 = blockSum(a3, red);
    if (tid == 0) {
        m[blockIdx.x * 4 + 0] = tanhf(t0);
        m[blockIdx.x * 4 + 1] = tanhf(t1);
        m[blockIdx.x * 4 + 2] = tanhf(t2);
        m[blockIdx.x * 4 + 3] = tanhf(t3);
    }
}

__global__ void predict_kernel(const float* __restrict__ hs, const float* __restrict__ m,
                               const float* __restrict__ pcw, float* __restrict__ pred) {
    __shared__ float cf[16];
    int token = blockIdx.x, tid = threadIdx.x;
    if (tid < 16) {
        float s = 0.f;
#pragma unroll
        for (int i = 0; i < 4; i++) s += m[token * 4 + i] * pcw[tid * 4 + i];
        cf[tid] = s;
    }
    __syncthreads();
    size_t off = (size_t)token * H_;
    for (int f = tid; f < H_; f += blockDim.x) {
        float h0 = hs[off + f];
        float h1 = hs[BTH_ + off + f];
        float h2 = hs[2 * BTH_ + off + f];
        float h3 = hs[3 * BTH_ + off + f];
        pred[off + f]            = h0 + h0 * cf[0]  + h1 * cf[1]  + h2 * cf[2]  + h3 * cf[3];
        pred[BTH_ + off + f]     = h1 + h0 * cf[4]  + h1 * cf[5]  + h2 * cf[6]  + h3 * cf[7];
        pred[2 * BTH_ + off + f] = h2 + h0 * cf[8]  + h1 * cf[9]  + h2 * cf[10] + h3 * cf[11];
        pred[3 * BTH_ + off + f] = h3 + h0 * cf[12] + h1 * cf[13] + h2 * cf[14] + h3 * cf[15];
    }
}

__global__ void correct_kernel(const float* __restrict__ act, const float* __restrict__ pred,
                               const float* __restrict__ mc, const float* __restrict__ ccw,
                               const float* __restrict__ cscale, float* __restrict__ out) {
    __shared__ float cc[4];
    int token = blockIdx.x, tid = threadIdx.x;
    if (tid < 4) {
        float s = 1.f;
#pragma unroll
        for (int i = 0; i < 4; i++) s += mc[token * 4 + i] * ccw[tid * 4 + i];
        cc[tid] = s;
    }
    __syncthreads();
    size_t off = (size_t)token * H_;
    for (int f = tid; f < H_; f += blockDim.x) {
        float p0 = pred[off + f];
        float inno = act[off + f] - p0;
        out[off + f]            = (inno * cc[0] + p0) * cscale[f];
        out[BTH_ + off + f]     = inno * cc[1] + pred[BTH_ + off + f];
        out[2 * BTH_ + off + f] = inno * cc[2] + pred[2 * BTH_ + off + f];
        out[3 * BTH_ + off + f] = inno * cc[3] + pred[3 * BTH_ + off + f];
    }
}

__global__ void qkvpost_kernel(const float* __restrict__ raw, const float* __restrict__ nw,
                               const float* __restrict__ cosb, const float* __restrict__ sinb,
                               float* __restrict__ out, int nheads, int do_rope, int trans) {
    __shared__ float sx[HD_];
    __shared__ float red[32];
    int idx = blockIdx.x;
    int h = idx % nheads;
    int bt = idx / nheads;
    int t = bt % T_, b = bt / T_;
    int d = threadIdx.x;
    float v = raw[(size_t)bt * nheads * HD_ + h * HD_ + d];
    float mean = blockSum(v, red) * (1.f / HD_);
    float c = v - mean;
    float var = blockSum(c * c, red) * (1.f / HD_);
    float ln = c * rsqrtf(var + EPS_) * (nw ? nw[d] : 1.f);
    sx[d] = ln;
    __syncthreads();
    float o = ln;
    if (do_rope) {
        float cs = cosb[(size_t)bt * HD_ + d];
        float sn = sinb[(size_t)bt * HD_ + d];
        float rot = (d < 128) ? -sx[d + 128] : sx[d - 128];
        o = ln * cs + rot * sn;
    }
    if (trans) {
        out[((size_t)(b * nheads + h) * HD_ + d) * T_ + t] = o;
    } else {
        out[((size_t)(b * nheads + h) * T_ + t) * HD_ + d] = o;
    }
}

__global__ void softmax_kernel(float* __restrict__ scores) {
    __shared__ float sx[T_];
    __shared__ float red[32];
    int q = blockIdx.x % T_;
    size_t off = (size_t)blockIdx.x * T_;
    int tid = threadIdx.x;
    int n = q + 1;
    float lm = -INFINITY;
    for (int i = tid; i < n; i += blockDim.x) {
        float v = scores[off + i];
        sx[i] = v;
        lm = fmaxf(lm, v);
    }
    float gm = blockMax(lm, red);
    float lsum = 0.f;
    for (int i = tid; i < n; i += blockDim.x) {
        float e = __expf(sx[i] - gm);
        sx[i] = e;
        lsum += e;
    }
    float inv = 1.f / blockSum(lsum, red);
    for (int i = tid; i < T_; i += blockDim.x) {
        scores[off + i] = (i < n) ? sx[i] * inv : 0.f;
    }
}

__device__ __forceinline__ float gelu_tanh(float x) {
    return 0.5f * x * (1.f + tanhf(0.7978845608028654f * (x + 0.044715f * x * x * x)));
}

__global__ void gelumul_kernel(float* __restrict__ g, const float* __restrict__ u, int n4) {
    int i = blockIdx.x * blockDim.x + threadIdx.x;
    if (i >= n4) return;
    float4 a = reinterpret_cast<float4*>(g)[i];
    float4 b = reinterpret_cast<const float4*>(u)[i];
    a.x = gelu_tanh(a.x) * b.x;
    a.y = gelu_tanh(a.y) * b.y;
    a.z = gelu_tanh(a.z) * b.z;
    a.w = gelu_tanh(a.w) * b.w;
    reinterpret_cast<float4*>(g)[i] = a;
}

// ===== shared MMA plumbing =====
__device__ __forceinline__ void ldsm4(uint32_t* r, uint32_t addr) {
    asm volatile("ldmatrix.sync.aligned.m8n8.x4.shared.b16 {%0,%1,%2,%3}, [%4];"
                 : "=r"(r[0]), "=r"(r[1]), "=r"(r[2]), "=r"(r[3]) : "r"(addr));
}
__device__ __forceinline__ void mma_bf(float* d, const uint32_t* a, uint32_t b0, uint32_t b1) {
    asm volatile("mma.sync.aligned.m16n8k16.row.col.f32.bf16.bf16.f32 "
                 "{%0,%1,%2,%3}, {%4,%5,%6,%7}, {%8,%9}, {%0,%1,%2,%3};"
                 : "+f"(d[0]), "+f"(d[1]), "+f"(d[2]), "+f"(d[3])
                 : "r"(a[0]), "r"(a[1]), "r"(a[2]), "r"(a[3]), "r"(b0), "r"(b1));
}
__device__ __forceinline__ void mma_fp(float* d, const uint32_t* a, uint32_t b0, uint32_t b1) {
    asm volatile("mma.sync.aligned.m16n8k16.row.col.f32.f16.f16.f32 "
                 "{%0,%1,%2,%3}, {%4,%5,%6,%7}, {%8,%9}, {%0,%1,%2,%3};"
                 : "+f"(d[0]), "+f"(d[1]), "+f"(d[2]), "+f"(d[3])
                 : "r"(a[0]), "r"(a[1]), "r"(a[2]), "r"(a[3]), "r"(b0), "r"(b1));
}
__device__ __forceinline__ void splitStoreBF(float4 v, uint32_t* hi, uint32_t* lo) {
    uint32_t hx = f2bf(v.x), hy = f2bf(v.y), hz = f2bf(v.z), hw = f2bf(v.w);
    uint32_t lx = f2bf(v.x - bf2f(hx));
    uint32_t ly = f2bf(v.y - bf2f(hy));
    uint32_t lz = f2bf(v.z - bf2f(hz));
    uint32_t lw = f2bf(v.w - bf2f(hw));
    hi[0] = hx | (hy << 16);
    hi[1] = hz | (hw << 16);
    lo[0] = lx | (ly << 16);
    lo[1] = lz | (lw << 16);
}
__device__ __forceinline__ void splitStoreH(float4 v, uint32_t* hi, uint32_t* lo) {
    u16 hx = f2h(v.x), hy = f2h(v.y), hz = f2h(v.z), hw = f2h(v.w);
    u16 lx = f2h(v.x - h2f(hx));
    u16 ly = f2h(v.y - h2f(hy));
    u16 lz = f2h(v.z - h2f(hz));
    u16 lw = f2h(v.w - h2f(hw));
    hi[0] = (uint32_t)hx | ((uint32_t)hy << 16);
    hi[1] = (uint32_t)hz | ((uint32_t)hw << 16);
    lo[0] = (uint32_t)lx | ((uint32_t)ly << 16);
    lo[1] = (uint32_t)lz | ((uint32_t)lw << 16);
}
__device__ __forceinline__ void convStoreH(float4 v, uint32_t* hi) {
    u16 hx = f2h(v.x), hy = f2h(v.y), hz = f2h(v.z), hw = f2h(v.w);
    hi[0] = (uint32_t)hx | ((uint32_t)hy << 16);
    hi[1] = (uint32_t)hz | ((uint32_t)hw << 16);
}

constexpr int MBM = 128, MBN = 128, MBK = 32;
constexpr int MLDW = 20;   // words per smem row = 40 halves = 80 B (conflict-free)

// ===== 3-pass bf16 core (Round-4 proven) — for q/k projections + scores =====
struct MSmem3 {
    uint32_t Ah[MBM][MLDW];
    uint32_t Al[MBM][MLDW];
    uint32_t Bh[MBN][MLDW];
    uint32_t Bl[MBN][MLDW];
};

__device__ __forceinline__ void mma_core3(
    const float* __restrict__ A, const float* __restrict__ B, float* __restrict__ C,
    int K, int lda, int ldb, int ldc, int bm, int bn, MSmem3& s)
{
    const int tid = threadIdx.x;
    const int lane = tid & 31, wid = tid >> 5;
    const int wm = wid & 3, wn = wid >> 2;

    float acc[2][8][4];
#pragma unroll
    for (int i = 0; i < 2; i++)
#pragma unroll
        for (int j = 0; j < 8; j++)
#pragma unroll
            for (int e = 0; e < 4; e++) acc[i][j][e] = 0.f;

    const int lr = tid >> 3;
    const int lc = (tid & 7) * 4;
    const int wc = (tid & 7) * 2;

    const uint32_t sb = (uint32_t)__cvta_generic_to_shared(&s);
    const uint32_t offAl = MBM * MLDW * 4;
    const uint32_t offBh = 2 * MBM * MLDW * 4;
    const uint32_t offBl = 3 * MBM * MLDW * 4;
    const int arow = wm * 32 + (lane & 15);
    const int acol = (lane >> 4) * 8;
    const int brow = wn * 64 + (lane & 7) + ((lane >> 4) << 3);
    const int bcol = ((lane >> 3) & 1) << 3;

    for (int k0 = 0; k0 < K; k0 += MBK) {
#pragma unroll
        for (int p = 0; p < 4; p++) {
            int r = lr + p * 32;
            float4 av = *reinterpret_cast<const float4*>(&A[(size_t)(bm + r) * lda + k0 + lc]);
            splitStoreBF(av, &s.Ah[r][wc], &s.Al[r][wc]);
            float4 bv = *reinterpret_cast<const float4*>(&B[(size_t)(bn + r) * ldb + k0 + lc]);
            splitStoreBF(bv, &s.Bh[r][wc], &s.Bl[r][wc]);
        }
        __syncthreads();

#pragma unroll
        for (int kk = 0; kk < 2; kk++) {
            uint32_t ah[2][4], al[2][4], bh[4][4], bl[4][4];
#pragma unroll
            for (int mf = 0; mf < 2; mf++) {
                uint32_t ao = (uint32_t)(((arow + mf * 16) * MLDW * 4) + (kk * 16 + acol) * 2);
                ldsm4(ah[mf], sb + ao);
                ldsm4(al[mf], sb + offAl + ao);
            }
#pragma unroll
            for (int np = 0; np < 4; np++) {
                uint32_t bo = (uint32_t)(((brow + np * 16) * MLDW * 4) + (kk * 16 + bcol) * 2);
                ldsm4(bh[np], sb + offBh + bo);
                ldsm4(bl[np], sb + offBl + bo);
            }
#pragma unroll
            for (int mf = 0; mf < 2; mf++) {
#pragma unroll
                for (int nf = 0; nf < 8; nf++) {
                    int np = nf >> 1;
                    int hf = (nf & 1) * 2;
                    mma_bf(acc[mf][nf], ah[mf], bh[np][hf], bh[np][hf + 1]);
                    mma_bf(acc[mf][nf], al[mf], bh[np][hf], bh[np][hf + 1]);
                    mma_bf(acc[mf][nf], ah[mf], bl[np][hf], bl[np][hf + 1]);
                }
            }
        }
        __syncthreads();
    }

#pragma unroll
    for (int mf = 0; mf < 2; mf++) {
        int row = bm + wm * 32 + mf * 16 + (lane >> 2);
#pragma unroll
        for (int nf = 0; nf < 8; nf++) {
            int col = bn + wn * 64 + nf * 8 + (lane & 3) * 2;
            *reinterpret_cast<float2*>(&C[(size_t)row * ldc + col]) =
                make_float2(acc[mf][nf][0], acc[mf][nf][1]);
            *reinterpret_cast<float2*>(&C[(size_t)(row + 8) * ldc + col]) =
                make_float2(acc[mf][nf][2], acc[mf][nf][3]);
        }
    }
}

__global__ void __launch_bounds__(256, 2)
mma_nt3(const float* __restrict__ A, const float* __restrict__ B, float* __restrict__ C,
        int K, int lda, int ldb, int ldc) {
    __shared__ MSmem3 s;
    mma_core3(A, B, C, K, lda, ldb, ldc, blockIdx.x * MBM, blockIdx.y * MBN, s);
}

__global__ void __launch_bounds__(256, 2)
mma_scores(const float* __restrict__ q, const float* __restrict__ k, float* __restrict__ sc) {
    if (blockIdx.y > blockIdx.x) return;
    int z = blockIdx.z;
    int b = z >> 3, h = z & 7;
    const float* A = q + (size_t)z * T_ * HD_;
    const float* B = k + (size_t)(b * NKV_ + (h >> 2)) * T_ * HD_;
    float* C = sc + (size_t)z * T_ * T_;
    __shared__ MSmem3 s;
    mma_core3(A, B, C, HD_, HD_, HD_, T_, blockIdx.x * MBM, blockIdx.y * MBN, s);
}

// ===== 2-pass fp16 core (A split, B hi-only) — well-conditioned GEMMs =====
struct MSmem2 {
    uint32_t Ah[MBM][MLDW];
    uint32_t Al[MBM][MLDW];
    uint32_t Bh[MBN][MLDW];
};

__device__ __forceinline__ void mma_core2(
    const float* __restrict__ A, const float* __restrict__ B, float* __restrict__ C,
    int K, int lda, int ldb, int ldc, int bm, int bn, MSmem2& s)
{
    const int tid = threadIdx.x;
    const int lane = tid & 31, wid = tid >> 5;
    const int wm = wid & 3, wn = wid >> 2;

    float acc[2][8][4];
#pragma unroll
    for (int i = 0; i < 2; i++)
#pragma unroll
        for (int j = 0; j < 8; j++)
#pragma unroll
            for (int e = 0; e < 4; e++) acc[i][j][e] = 0.f;

    const int lr = tid >> 3;
    const int lc = (tid & 7) * 4;
    const int wc = (tid & 7) * 2;

    const uint32_t sb = (uint32_t)__cvta_generic_to_shared(&s);
    const uint32_t offAl = MBM * MLDW * 4;
    const uint32_t offBh = 2 * MBM * MLDW * 4;
    const int arow = wm * 32 + (lane & 15);
    const int acol = (lane >> 4) * 8;
    const int brow = wn * 64 + (lane & 7) + ((lane >> 4) << 3);
    const int bcol = ((lane >> 3) & 1) << 3;

    for (int k0 = 0; k0 < K; k0 += MBK) {
#pragma unroll
        for (int p = 0; p < 4; p++) {
            int r = lr + p * 32;
            float4 av = *reinterpret_cast<const float4*>(&A[(size_t)(bm + r) * lda + k0 + lc]);
            splitStoreH(av, &s.Ah[r][wc], &s.Al[r][wc]);
            float4 bv = *reinterpret_cast<const float4*>(&B[(size_t)(bn + r) * ldb + k0 + lc]);
            convStoreH(bv, &s.Bh[r][wc]);
        }
        __syncthreads();

#pragma unroll
        for (int kk = 0; kk < 2; kk++) {
            uint32_t ah[2][4], al[2][4], bh[4][4];
#pragma unroll
            for (int mf = 0; mf < 2; mf++) {
                uint32_t ao = (uint32_t)(((arow + mf * 16) * MLDW * 4) + (kk * 16 + acol) * 2);
                ldsm4(ah[mf], sb + ao);
                ldsm4(al[mf], sb + offAl + ao);
            }
#pragma unroll
            for (int np = 0; np < 4; np++) {
                uint32_t bo = (uint32_t)(((brow + np * 16) * MLDW * 4) + (kk * 16 + bcol) * 2);
                ldsm4(bh[np], sb + offBh + bo);
            }
#pragma unroll
            for (int mf = 0; mf < 2; mf++) {
#pragma unroll
                for (int nf = 0; nf < 8; nf++) {
                    int np = nf >> 1;
                    int hf = (nf & 1) * 2;
                    mma_fp(acc[mf][nf], ah[mf], bh[np][hf], bh[np][hf + 1]);
                    mma_fp(acc[mf][nf], al[mf], bh[np][hf], bh[np][hf + 1]);
                }
            }
        }
        __syncthreads();
    }

#pragma unroll
    for (int mf = 0; mf < 2; mf++) {
        int row = bm + wm * 32 + mf * 16 + (lane >> 2);
#pragma unroll
        for (int nf = 0; nf < 8; nf++) {
            int col = bn + wn * 64 + nf * 8 + (lane & 3) * 2;
            *reinterpret_cast<float2*>(&C[(size_t)row * ldc + col]) =
                make_float2(acc[mf][nf][0], acc[mf][nf][1]);
            *reinterpret_cast<float2*>(&C[(size_t)(row + 8) * ldc + col]) =
                make_float2(acc[mf][nf][2], acc[mf][nf][3]);
        }
    }
}

__global__ void __launch_bounds__(256, 2)
mma_nt2(const float* __restrict__ A, const float* __restrict__ B, float* __restrict__ C,
        int K, int lda, int ldb, int ldc) {
    __shared__ MSmem2 s;
    mma_core2(A, B, C, K, lda, ldb, ldc, blockIdx.x * MBM, blockIdx.y * MBN, s);
}

__global__ void __launch_bounds__(256, 2)
mma_attnv(const float* __restrict__ p, const float* __restrict__ vT, float* __restrict__ o) {
    int z = blockIdx.z;
    int b = z >> 3, h = z & 7;
    const float* A = p + (size_t)z * T_ * T_;
    const float* B = vT + (size_t)(b * NKV_ + (h >> 2)) * HD_ * T_;
    float* C = o + (size_t)b * T_ * H_ + (size_t)h * HD_;
    int bm = blockIdx.x * MBM;
    __shared__ MSmem2 s;
    mma_core2(A, B, C, bm + MBM, T_, T_, H_, bm, blockIdx.y * MBN, s);
}

// laurel1: C[2048,64] = A[2048,2048] @ B[64,2048]^T, split-K x4
__global__ void __launch_bounds__(256)
laurel1_kernel(const float* __restrict__ A, const float* __restrict__ B, float* __restrict__ P) {
    __shared__ float Bs[64][65];
    __shared__ float As[32][65];
    int tid = threadIdx.x;
    int bm = blockIdx.x * 32;
    int ks = blockIdx.y;
    int kbeg = ks * (H_ / 4), kend = kbeg + H_ / 4;
    float acc0[4] = {0.f, 0.f, 0.f, 0.f};
    float acc1[4] = {0.f, 0.f, 0.f, 0.f};
    int tn = tid & 15;
    int tr = tid >> 4;
    for (int k0 = kbeg; k0 < kend; k0 += 64) {
        for (int i = tid; i < 64 * 64; i += 256) {
            int n = i >> 6, kk = i & 63;
            Bs[n][kk] = B[(size_t)n * H_ + k0 + kk];
        }
        for (int i = tid; i < 32 * 64; i += 256) {
            int r = i >> 6, kk = i & 63;
            As[r][kk] = A[(size_t)(bm + r) * H_ + k0 + kk];
        }
        __syncthreads();
#pragma unroll 8
        for (int kk = 0; kk < 64; kk++) {
            float a0 = As[tr][kk], a1 = As[tr + 16][kk];
#pragma unroll
            for (int j = 0; j < 4; j++) {
                float bv = Bs[tn * 4 + j][kk];
                acc0[j] = fmaf(a0, bv, acc0[j]);
                acc1[j] = fmaf(a1, bv, acc1[j]);
            }
        }
        __syncthreads();
    }
#pragma unroll
    for (int j = 0; j < 4; j++) {
        P[((size_t)ks * BT_ + bm + tr) * LR_ + tn * 4 + j] = acc0[j];
        P[((size_t)ks * BT_ + bm + tr + 16) * LR_ + tn * 4 + j] = acc1[j];
    }
}

__global__ void laurel1_reduce(const float* __restrict__ P, float* __restrict__ out) {
    int i = blockIdx.x * blockDim.x + threadIdx.x;
    if (i >= BT_ * LR_) return;
    out[i] = P[i] + P[BT_ * LR_ + i] + P[2 * BT_ * LR_ + i] + P[3 * BT_ * LR_ + i];
}

extern "C" void kernel_launch(void* const* d_in, const int* in_sizes, int n_in,
                              void* d_out, int out_size) {
    const float* hs    = (const float*)d_in[0];
    const float* cosb  = (const float*)d_in[1];
    const float* sinb  = (const float*)d_in[2];
    const float* wq    = (const float*)d_in[3];
    const float* wk    = (const float*)d_in[4];
    const float* wv    = (const float*)d_in[5];
    const float* wo    = (const float*)d_in[6];
    const float* qnw   = (const float*)d_in[7];
    const float* knw   = (const float*)d_in[8];
    const float* in_ln = (const float*)d_in[9];
    const float* pa_ln = (const float*)d_in[10];
    const float* pf_ln = (const float*)d_in[11];
    const float* pw_ln = (const float*)d_in[12];
    const float* gatew = (const float*)d_in[13];
    const float* upw   = (const float*)d_in[14];
    const float* downw = (const float*)d_in[15];
    const float* llw   = (const float*)d_in[16];
    const float* lrw   = (const float*)d_in[17];
    const float* lnw   = (const float*)d_in[18];
    const float* rnw   = (const float*)d_in[19];
    const float* rw    = (const float*)d_in[20];
    const float* pcw   = (const float*)d_in[21];
    const float* ccw   = (const float*)d_in[22];
    const float* cscal = (const float*)d_in[23];
    float* out = (float*)d_out;

    Scratch* S = 0;
    cudaGetSymbolAddress((void**)&S, g_scratch);

    router_kernel<<<BT_, 256>>>(hs, rnw, rw, S->m);
    predict_kernel<<<BT_, 256>>>(hs, S->m, pcw, S->pred);
    ln_kernel<<<BT_, 256>>>(S->pred, in_ln, (const float*)0, (const float*)0, 1.f, S->xnorm);

    laurel1_kernel<<<dim3(BT_ / 32, 4), 256>>>(S->xnorm, llw, S->lrpart);
    laurel1_reduce<<<(BT_ * LR_ + 255) / 256, 256>>>(S->lrpart, S->lrbuf);
    mma_nt2<<<dim3(16, 16), 256>>>(S->lrbuf, lrw, S->laurel, LR_, LR_, LR_, H_);
    ln_kernel<<<BT_, 256>>>(S->laurel, lnw, S->xnorm, (const float*)0, 1.f, S->laurel);

    // q,k: 3-pass bf16 (feed softmax logits); v: 2-pass fp16
    mma_nt3<<<dim3(16, 16), 256>>>(S->xnorm, wq, S->qraw, H_, H_, H_, NH_ * HD_);
    mma_nt3<<<dim3(16, 4), 256>>>(S->xnorm, wk, S->kraw, H_, H_, H_, NKV_ * HD_);
    mma_nt2<<<dim3(16, 4), 256>>>(S->xnorm, wv, S->vraw, H_, H_, H_, NKV_ * HD_);
    qkvpost_kernel<<<BT_ * NH_, 256>>>(S->qraw, qnw, cosb, sinb, S->q, NH_, 1, 0);
    qkvpost_kernel<<<BT_ * NKV_, 256>>>(S->kraw, knw, cosb, sinb, S->k, NKV_, 1, 0);
    qkvpost_kernel<<<BT_ * NKV_, 256>>>(S->vraw, (const float*)0, cosb, sinb, S->vT, NKV_, 0, 1);

    mma_scores<<<dim3(8, 8, B_ * NH_), 256>>>(S->q, S->k, S->scores);
    softmax_kernel<<<B_ * NH_ * T_, 256>>>(S->scores);
    mma_attnv<<<dim3(8, 2, B_ * NH_), 256>>>(S->scores, S->vT, S->attnout);
    mma_nt2<<<dim3(16, 16), 256>>>(S->attnout, wo, S->attnproj,
                                   NH_ * HD_, NH_ * HD_, NH_ * HD_, H_);

    ln_kernel<<<BT_, 256>>>(S->attnproj, pa_ln, S->pred, S->laurel,
                            0.7071067811865476f, S->attnlaurel);
    ln_kernel<<<BT_, 256>>>(S->attnlaurel, pf_ln, (const float*)0, (const float*)0, 1.f, S->hn);

    mma_nt2<<<dim3(16, 64), 256>>>(S->hn, gatew, S->gate, H_, H_, H_, FF_);
    mma_nt2<<<dim3(16, 64), 256>>>(S->hn, upw, S->up, H_, H_, H_, FF_);

    int n4 = (int)(((size_t)BT_ * FF_) / 4);
    gelumul_kernel<<<(n4 + 255) / 256, 256>>>(S->gate, S->up, n4);

    mma_nt2<<<dim3(16, 16), 256>>>(S->gate, downw, S->ffw, FF_, FF_, FF_, H_);
    ln_kernel<<<BT_, 256>>>(S->ffw, pw_ln, S->attnlaurel, (const float*)0, 1.f, S->act);

    router_kernel<<<BT_, 256>>>(S->act, rnw, rw, S->mc);
    correct_kernel<<<BT_, 256>>>(S->act, S->pred, S->mc, ccw, cscal, out);

    (void)in_sizes; (void)n_in; (void)out_size;
}

// round 8
// speedup vs baseline: 1.4621x; 1.1653x over previous
#include <cuda_runtime.h>
#include <cstdint>
#include <cstddef>
#include <math.h>

typedef unsigned short u16;

constexpr int B_ = 2, T_ = 1024, H_ = 2048, NH_ = 8, NKV_ = 2, HD_ = 256;
constexpr int FF_ = 8192, LR_ = 64;
constexpr int BT_ = B_ * T_;
constexpr size_t BTH_ = (size_t)BT_ * H_;
constexpr float EPS_ = 1e-6f;

struct Scratch {
    float pred[4 * BTH_];
    float xnorm[BTH_];
    float lrpart[8 * BT_ * LR_];
    float lrbuf[BT_ * LR_];
    float laurel[BTH_];
    float qraw[BTH_];
    float kraw[(size_t)BT_ * NKV_ * HD_];
    float vraw[(size_t)BT_ * NKV_ * HD_];
    float q[BTH_];
    float k[(size_t)BT_ * NKV_ * HD_];
    float vT[(size_t)BT_ * NKV_ * HD_];
    float scores[(size_t)B_ * NH_ * T_ * T_];
    float attnout[BTH_];
    float attnproj[BTH_];
    float attnlaurel[BTH_];
    float hn[BTH_];
    float gate[(size_t)BT_ * FF_];
    float up[(size_t)BT_ * FF_];
    float ffw[BTH_];
    float act[BTH_];
    float m[BT_ * 4];
    float mc[BT_ * 4];
};
__device__ Scratch g_scratch;

// ---------- bf16 / fp16 bit helpers ----------
__device__ __forceinline__ uint32_t f2bf(float x) {
    uint32_t u = __float_as_uint(x);
    return (u + 0x7FFFu + ((u >> 16) & 1u)) >> 16;
}
__device__ __forceinline__ float bf2f(uint32_t b) {
    return __uint_as_float(b << 16);
}
__device__ __forceinline__ u16 f2h(float x) {
    u16 h;
    asm("cvt.rn.f16.f32 %0, %1;" : "=h"(h) : "f"(x));
    return h;
}
__device__ __forceinline__ float h2f(u16 h) {
    float f;
    asm("cvt.f32.f16 %0, %1;" : "=f"(f) : "h"(h));
    return f;
}

// ---------- reductions ----------
__device__ __forceinline__ float warpSum(float v) {
#pragma unroll
    for (int o = 16; o > 0; o >>= 1) v += __shfl_xor_sync(0xffffffffu, v, o);
    return v;
}
__device__ __forceinline__ float warpMax(float v) {
#pragma unroll
    for (int o = 16; o > 0; o >>= 1) v = fmaxf(v, __shfl_xor_sync(0xffffffffu, v, o));
    return v;
}
__device__ __forceinline__ float blockSum(float v, float* red) {
    v = warpSum(v);
    int lane = threadIdx.x & 31, w = threadIdx.x >> 5;
    if (lane == 0) red[w] = v;
    __syncthreads();
    int nw = (blockDim.x + 31) >> 5;
    float r = (lane < nw) ? red[lane] : 0.f;
    if (w == 0) {
        r = warpSum(r);
        if (lane == 0) red[0] = r;
    }
    __syncthreads();
    r = red[0];
    __syncthreads();
    return r;
}
__device__ __forceinline__ float blockMax(float v, float* red) {
    v = warpMax(v);
    int lane = threadIdx.x & 31, w = threadIdx.x >> 5;
    if (lane == 0) red[w] = v;
    __syncthreads();
    int nw = (blockDim.x + 31) >> 5;
    float r = (lane < nw) ? red[lane] : -INFINITY;
    if (w == 0) {
        r = warpMax(r);
        if (lane == 0) red[0] = r;
    }
    __syncthreads();
    r = red[0];
    __syncthreads();
    return r;
}

// ---------- elementwise kernels ----------
__global__ void ln_kernel(const float* __restrict__ a, const float* __restrict__ w,
                          const float* __restrict__ add1, const float* __restrict__ add2,
                          float scale, float* __restrict__ dst) {
    __shared__ float sx[H_];
    __shared__ float red[32];
    size_t off = (size_t)blockIdx.x * H_;
    int tid = threadIdx.x;
    float ls = 0.f;
    for (int i = tid; i < H_; i += blockDim.x) {
        float v = a[off + i];
        sx[i] = v;
        ls += v;
    }
    float mean = blockSum(ls, red) * (1.f / H_);
    float lv = 0.f;
    for (int i = tid; i < H_; i += blockDim.x) {
        float d = sx[i] - mean;
        lv += d * d;
    }
    float var = blockSum(lv, red) * (1.f / H_);
    float rs = rsqrtf(var + EPS_);
    for (int i = tid; i < H_; i += blockDim.x) {
        float v = (sx[i] - mean) * rs * w[i];
        if (add1) v += add1[off + i];
        if (add2) v += add2[off + i];
        dst[off + i] = v * scale;
    }
}

__global__ void router_kernel(const float* __restrict__ x, const float* __restrict__ nw,
                              const float* __restrict__ rw, float* __restrict__ m) {
    __shared__ float sx[H_];
    __shared__ float red[32];
    size_t off = (size_t)blockIdx.x * H_;
    int tid = threadIdx.x;
    float ls = 0.f;
    for (int i = tid; i < H_; i += blockDim.x) {
        float v = x[off + i];
        sx[i] = v;
        ls += v;
    }
    float mean = blockSum(ls, red) * (1.f / H_);
    float lv = 0.f;
    for (int i = tid; i < H_; i += blockDim.x) {
        float d = sx[i] - mean;
        lv += d * d;
    }
    float rs = rsqrtf(blockSum(lv, red) * (1.f / H_) + EPS_);
    float a0 = 0.f, a1 = 0.f, a2 = 0.f, a3 = 0.f;
    for (int i = tid; i < H_; i += blockDim.x) {
        float r = (sx[i] - mean) * rs * nw[i] * (1.f / H_);
        a0 += r * rw[i];
        a1 += r * rw[H_ + i];
        a2 += r * rw[2 * H_ + i];
        a3 += r * rw[3 * H_ + i];
    }
    float t0 = blockSum(a0, red);
    float t1 = blockSum(a1, red);
    float t2 = blockSum(a2, red);
    float t3 = blockSum(a3, red);
    if (tid == 0) {
        m[blockIdx.x * 4 + 0] = tanhf(t0);
        m[blockIdx.x * 4 + 1] = tanhf(t1);
        m[blockIdx.x * 4 + 2] = tanhf(t2);
        m[blockIdx.x * 4 + 3] = tanhf(t3);
    }
}

__global__ void predict_kernel(const float* __restrict__ hs, const float* __restrict__ m,
                               const float* __restrict__ pcw, float* __restrict__ pred) {
    __shared__ float cf[16];
    int token = blockIdx.x, tid = threadIdx.x;
    if (tid < 16) {
        float s = 0.f;
#pragma unroll
        for (int i = 0; i < 4; i++) s += m[token * 4 + i] * pcw[tid * 4 + i];
        cf[tid] = s;
    }
    __syncthreads();
    size_t off = (size_t)token * H_;
    for (int f = tid; f < H_; f += blockDim.x) {
        float h0 = hs[off + f];
        float h1 = hs[BTH_ + off + f];
        float h2 = hs[2 * BTH_ + off + f];
        float h3 = hs[3 * BTH_ + off + f];
        pred[off + f]            = h0 + h0 * cf[0]  + h1 * cf[1]  + h2 * cf[2]  + h3 * cf[3];
        pred[BTH_ + off + f]     = h1 + h0 * cf[4]  + h1 * cf[5]  + h2 * cf[6]  + h3 * cf[7];
        pred[2 * BTH_ + off + f] = h2 + h0 * cf[8]  + h1 * cf[9]  + h2 * cf[10] + h3 * cf[11];
        pred[3 * BTH_ + off + f] = h3 + h0 * cf[12] + h1 * cf[13] + h2 * cf[14] + h3 * cf[15];
    }
}

__global__ void correct_kernel(const float* __restrict__ act, const float* __restrict__ pred,
                               const float* __restrict__ mc, const float* __restrict__ ccw,
                               const float* __restrict__ cscale, float* __restrict__ out) {
    __shared__ float cc[4];
    int token = blockIdx.x, tid = threadIdx.x;
    if (tid < 4) {
        float s = 1.f;
#pragma unroll
        for (int i = 0; i < 4; i++) s += mc[token * 4 + i] * ccw[tid * 4 + i];
        cc[tid] = s;
    }
    __syncthreads();
    size_t off = (size_t)token * H_;
    for (int f = tid; f < H_; f += blockDim.x) {
        float p0 = pred[off + f];
        float inno = act[off + f] - p0;
        out[off + f]            = (inno * cc[0] + p0) * cscale[f];
        out[BTH_ + off + f]     = inno * cc[1] + pred[BTH_ + off + f];
        out[2 * BTH_ + off + f] = inno * cc[2] + pred[2 * BTH_ + off + f];
        out[3 * BTH_ + off + f] = inno * cc[3] + pred[3 * BTH_ + off + f];
    }
}

__global__ void qkvpost_kernel(const float* __restrict__ raw, const float* __restrict__ nw,
                               const float* __restrict__ cosb, const float* __restrict__ sinb,
                               float* __restrict__ out, int nheads, int do_rope, int trans) {
    __shared__ float sx[HD_];
    __shared__ float red[32];
    int idx = blockIdx.x;
    int h = idx % nheads;
    int bt = idx / nheads;
    int t = bt % T_, b = bt / T_;
    int d = threadIdx.x;
    float v = raw[(size_t)bt * nheads * HD_ + h * HD_ + d];
    float mean = blockSum(v, red) * (1.f / HD_);
    float c = v - mean;
    float var = blockSum(c * c, red) * (1.f / HD_);
    float ln = c * rsqrtf(var + EPS_) * (nw ? nw[d] : 1.f);
    sx[d] = ln;
    __syncthreads();
    float o = ln;
    if (do_rope) {
        float cs = cosb[(size_t)bt * HD_ + d];
        float sn = sinb[(size_t)bt * HD_ + d];
        float rot = (d < 128) ? -sx[d + 128] : sx[d - 128];
        o = ln * cs + rot * sn;
    }
    if (trans) {
        out[((size_t)(b * nheads + h) * HD_ + d) * T_ + t] = o;
    } else {
        out[((size_t)(b * nheads + h) * T_ + t) * HD_ + d] = o;
    }
}

__global__ void softmax_kernel(float* __restrict__ scores) {
    __shared__ float sx[T_];
    __shared__ float red[32];
    int q = blockIdx.x % T_;
    size_t off = (size_t)blockIdx.x * T_;
    int tid = threadIdx.x;
    int n = q + 1;
    float lm = -INFINITY;
    for (int i = tid; i < n; i += blockDim.x) {
        float v = scores[off + i];
        sx[i] = v;
        lm = fmaxf(lm, v);
    }
    float gm = blockMax(lm, red);
    float lsum = 0.f;
    for (int i = tid; i < n; i += blockDim.x) {
        float e = __expf(sx[i] - gm);
        sx[i] = e;
        lsum += e;
    }
    float inv = 1.f / blockSum(lsum, red);
    for (int i = tid; i < T_; i += blockDim.x) {
        scores[off + i] = (i < n) ? sx[i] * inv : 0.f;
    }
}

__device__ __forceinline__ float gelu_tanh(float x) {
    return 0.5f * x * (1.f + tanhf(0.7978845608028654f * (x + 0.044715f * x * x * x)));
}

__global__ void gelumul_kernel(float* __restrict__ g, const float* __restrict__ u, int n4) {
    int i = blockIdx.x * blockDim.x + threadIdx.x;
    if (i >= n4) return;
    float4 a = reinterpret_cast<float4*>(g)[i];
    float4 b = reinterpret_cast<const float4*>(u)[i];
    a.x = gelu_tanh(a.x) * b.x;
    a.y = gelu_tanh(a.y) * b.y;
    a.z = gelu_tanh(a.z) * b.z;
    a.w = gelu_tanh(a.w) * b.w;
    reinterpret_cast<float4*>(g)[i] = a;
}

// ===== shared MMA plumbing =====
__device__ __forceinline__ void ldsm4(uint32_t* r, uint32_t addr) {
    asm volatile("ldmatrix.sync.aligned.m8n8.x4.shared.b16 {%0,%1,%2,%3}, [%4];"
                 : "=r"(r[0]), "=r"(r[1]), "=r"(r[2]), "=r"(r[3]) : "r"(addr));
}
__device__ __forceinline__ void mma_bf(float* d, const uint32_t* a, uint32_t b0, uint32_t b1) {
    asm volatile("mma.sync.aligned.m16n8k16.row.col.f32.bf16.bf16.f32 "
                 "{%0,%1,%2,%3}, {%4,%5,%6,%7}, {%8,%9}, {%0,%1,%2,%3};"
                 : "+f"(d[0]), "+f"(d[1]), "+f"(d[2]), "+f"(d[3])
                 : "r"(a[0]), "r"(a[1]), "r"(a[2]), "r"(a[3]), "r"(b0), "r"(b1));
}
__device__ __forceinline__ void mma_fp(float* d, const uint32_t* a, uint32_t b0, uint32_t b1) {
    asm volatile("mma.sync.aligned.m16n8k16.row.col.f32.f16.f16.f32 "
                 "{%0,%1,%2,%3}, {%4,%5,%6,%7}, {%8,%9}, {%0,%1,%2,%3};"
                 : "+f"(d[0]), "+f"(d[1]), "+f"(d[2]), "+f"(d[3])
                 : "r"(a[0]), "r"(a[1]), "r"(a[2]), "r"(a[3]), "r"(b0), "r"(b1));
}
__device__ __forceinline__ void splitStoreBF(float4 v, uint32_t* hi, uint32_t* lo) {
    uint32_t hx = f2bf(v.x), hy = f2bf(v.y), hz = f2bf(v.z), hw = f2bf(v.w);
    uint32_t lx = f2bf(v.x - bf2f(hx));
    uint32_t ly = f2bf(v.y - bf2f(hy));
    uint32_t lz = f2bf(v.z - bf2f(hz));
    uint32_t lw = f2bf(v.w - bf2f(hw));
    hi[0] = hx | (hy << 16);
    hi[1] = hz | (hw << 16);
    lo[0] = lx | (ly << 16);
    lo[1] = lz | (lw << 16);
}
__device__ __forceinline__ void splitStoreH(float4 v, uint32_t* hi, uint32_t* lo) {
    u16 hx = f2h(v.x), hy = f2h(v.y), hz = f2h(v.z), hw = f2h(v.w);
    u16 lx = f2h(v.x - h2f(hx));
    u16 ly = f2h(v.y - h2f(hy));
    u16 lz = f2h(v.z - h2f(hz));
    u16 lw = f2h(v.w - h2f(hw));
    hi[0] = (uint32_t)hx | ((uint32_t)hy << 16);
    hi[1] = (uint32_t)hz | ((uint32_t)hw << 16);
    lo[0] = (uint32_t)lx | ((uint32_t)ly << 16);
    lo[1] = (uint32_t)lz | ((uint32_t)lw << 16);
}
__device__ __forceinline__ void convStoreH(float4 v, uint32_t* hi) {
    u16 hx = f2h(v.x), hy = f2h(v.y), hz = f2h(v.z), hw = f2h(v.w);
    hi[0] = (uint32_t)hx | ((uint32_t)hy << 16);
    hi[1] = (uint32_t)hz | ((uint32_t)hw << 16);
}

constexpr int MBM = 128, MBN = 128, MBK = 32;
constexpr int MLDW = 20;   // words per smem row = 40 halves = 80 B (conflict-free)

// ===== 3-pass bf16 core — q/k projections + scores =====
struct MSmem3 {
    uint32_t Ah[MBM][MLDW];
    uint32_t Al[MBM][MLDW];
    uint32_t Bh[MBN][MLDW];
    uint32_t Bl[MBN][MLDW];
};

__device__ __forceinline__ void mma_core3(
    const float* __restrict__ A, const float* __restrict__ B, float* __restrict__ C,
    int K, int lda, int ldb, int ldc, int bm, int bn, MSmem3& s)
{
    const int tid = threadIdx.x;
    const int lane = tid & 31, wid = tid >> 5;
    const int wm = wid & 3, wn = wid >> 2;

    float acc[2][8][4];
#pragma unroll
    for (int i = 0; i < 2; i++)
#pragma unroll
        for (int j = 0; j < 8; j++)
#pragma unroll
            for (int e = 0; e < 4; e++) acc[i][j][e] = 0.f;

    const int lr = tid >> 3;
    const int lc = (tid & 7) * 4;
    const int wc = (tid & 7) * 2;

    const uint32_t sb = (uint32_t)__cvta_generic_to_shared(&s);
    const uint32_t offAl = MBM * MLDW * 4;
    const uint32_t offBh = 2 * MBM * MLDW * 4;
    const uint32_t offBl = 3 * MBM * MLDW * 4;
    const int arow = wm * 32 + (lane & 15);
    const int acol = (lane >> 4) * 8;
    const int brow = wn * 64 + (lane & 7) + ((lane >> 4) << 3);
    const int bcol = ((lane >> 3) & 1) << 3;

    for (int k0 = 0; k0 < K; k0 += MBK) {
#pragma unroll
        for (int p = 0; p < 4; p++) {
            int r = lr + p * 32;
            float4 av = *reinterpret_cast<const float4*>(&A[(size_t)(bm + r) * lda + k0 + lc]);
            splitStoreBF(av, &s.Ah[r][wc], &s.Al[r][wc]);
            float4 bv = *reinterpret_cast<const float4*>(&B[(size_t)(bn + r) * ldb + k0 + lc]);
            splitStoreBF(bv, &s.Bh[r][wc], &s.Bl[r][wc]);
        }
        __syncthreads();

#pragma unroll
        for (int kk = 0; kk < 2; kk++) {
            uint32_t ah[2][4], al[2][4], bh[4][4], bl[4][4];
#pragma unroll
            for (int mf = 0; mf < 2; mf++) {
                uint32_t ao = (uint32_t)(((arow + mf * 16) * MLDW * 4) + (kk * 16 + acol) * 2);
                ldsm4(ah[mf], sb + ao);
                ldsm4(al[mf], sb + offAl + ao);
            }
#pragma unroll
            for (int np = 0; np < 4; np++) {
                uint32_t bo = (uint32_t)(((brow + np * 16) * MLDW * 4) + (kk * 16 + bcol) * 2);
                ldsm4(bh[np], sb + offBh + bo);
                ldsm4(bl[np], sb + offBl + bo);
            }
#pragma unroll
            for (int mf = 0; mf < 2; mf++) {
#pragma unroll
                for (int nf = 0; nf < 8; nf++) {
                    int np = nf >> 1;
                    int hf = (nf & 1) * 2;
                    mma_bf(acc[mf][nf], ah[mf], bh[np][hf], bh[np][hf + 1]);
                    mma_bf(acc[mf][nf], al[mf], bh[np][hf], bh[np][hf + 1]);
                    mma_bf(acc[mf][nf], ah[mf], bl[np][hf], bl[np][hf + 1]);
                }
            }
        }
        __syncthreads();
    }

#pragma unroll
    for (int mf = 0; mf < 2; mf++) {
        int row = bm + wm * 32 + mf * 16 + (lane >> 2);
#pragma unroll
        for (int nf = 0; nf < 8; nf++) {
            int col = bn + wn * 64 + nf * 8 + (lane & 3) * 2;
            *reinterpret_cast<float2*>(&C[(size_t)row * ldc + col]) =
                make_float2(acc[mf][nf][0], acc[mf][nf][1]);
            *reinterpret_cast<float2*>(&C[(size_t)(row + 8) * ldc + col]) =
                make_float2(acc[mf][nf][2], acc[mf][nf][3]);
        }
    }
}

__global__ void __launch_bounds__(256, 2)
mma_nt3(const float* __restrict__ A, const float* __restrict__ B, float* __restrict__ C,
        int K, int lda, int ldb, int ldc) {
    __shared__ MSmem3 s;
    mma_core3(A, B, C, K, lda, ldb, ldc, blockIdx.x * MBM, blockIdx.y * MBN, s);
}

__global__ void __launch_bounds__(256, 2)
mma_scores(const float* __restrict__ q, const float* __restrict__ k, float* __restrict__ sc) {
    if (blockIdx.y > blockIdx.x) return;
    int z = blockIdx.z;
    int b = z >> 3, h = z & 7;
    const float* A = q + (size_t)z * T_ * HD_;
    const float* B = k + (size_t)(b * NKV_ + (h >> 2)) * T_ * HD_;
    float* C = sc + (size_t)z * T_ * T_;
    __shared__ MSmem3 s;
    mma_core3(A, B, C, HD_, HD_, HD_, T_, blockIdx.x * MBM, blockIdx.y * MBN, s);
}

// ===== 2-pass fp16 core (A split, B hi-only) =====
struct MSmem2 {
    uint32_t Ah[MBM][MLDW];
    uint32_t Al[MBM][MLDW];
    uint32_t Bh[MBN][MLDW];
};

__device__ __forceinline__ void mma_core2(
    const float* __restrict__ A, const float* __restrict__ B, float* __restrict__ C,
    int K, int lda, int ldb, int ldc, int bm, int bn, MSmem2& s)
{
    const int tid = threadIdx.x;
    const int lane = tid & 31, wid = tid >> 5;
    const int wm = wid & 3, wn = wid >> 2;

    float acc[2][8][4];
#pragma unroll
    for (int i = 0; i < 2; i++)
#pragma unroll
        for (int j = 0; j < 8; j++)
#pragma unroll
            for (int e = 0; e < 4; e++) acc[i][j][e] = 0.f;

    const int lr = tid >> 3;
    const int lc = (tid & 7) * 4;
    const int wc = (tid & 7) * 2;

    const uint32_t sb = (uint32_t)__cvta_generic_to_shared(&s);
    const uint32_t offAl = MBM * MLDW * 4;
    const uint32_t offBh = 2 * MBM * MLDW * 4;
    const int arow = wm * 32 + (lane & 15);
    const int acol = (lane >> 4) * 8;
    const int brow = wn * 64 + (lane & 7) + ((lane >> 4) << 3);
    const int bcol = ((lane >> 3) & 1) << 3;

    for (int k0 = 0; k0 < K; k0 += MBK) {
#pragma unroll
        for (int p = 0; p < 4; p++) {
            int r = lr + p * 32;
            float4 av = *reinterpret_cast<const float4*>(&A[(size_t)(bm + r) * lda + k0 + lc]);
            splitStoreH(av, &s.Ah[r][wc], &s.Al[r][wc]);
            float4 bv = *reinterpret_cast<const float4*>(&B[(size_t)(bn + r) * ldb + k0 + lc]);
            convStoreH(bv, &s.Bh[r][wc]);
        }
        __syncthreads();

#pragma unroll
        for (int kk = 0; kk < 2; kk++) {
            uint32_t ah[2][4], al[2][4], bh[4][4];
#pragma unroll
            for (int mf = 0; mf < 2; mf++) {
                uint32_t ao = (uint32_t)(((arow + mf * 16) * MLDW * 4) + (kk * 16 + acol) * 2);
                ldsm4(ah[mf], sb + ao);
                ldsm4(al[mf], sb + offAl + ao);
            }
#pragma unroll
            for (int np = 0; np < 4; np++) {
                uint32_t bo = (uint32_t)(((brow + np * 16) * MLDW * 4) + (kk * 16 + bcol) * 2);
                ldsm4(bh[np], sb + offBh + bo);
            }
#pragma unroll
            for (int mf = 0; mf < 2; mf++) {
#pragma unroll
                for (int nf = 0; nf < 8; nf++) {
                    int np = nf >> 1;
                    int hf = (nf & 1) * 2;
                    mma_fp(acc[mf][nf], ah[mf], bh[np][hf], bh[np][hf + 1]);
                    mma_fp(acc[mf][nf], al[mf], bh[np][hf], bh[np][hf + 1]);
                }
            }
        }
        __syncthreads();
    }

#pragma unroll
    for (int mf = 0; mf < 2; mf++) {
        int row = bm + wm * 32 + mf * 16 + (lane >> 2);
#pragma unroll
        for (int nf = 0; nf < 8; nf++) {
            int col = bn + wn * 64 + nf * 8 + (lane & 3) * 2;
            *reinterpret_cast<float2*>(&C[(size_t)row * ldc + col]) =
                make_float2(acc[mf][nf][0], acc[mf][nf][1]);
            *reinterpret_cast<float2*>(&C[(size_t)(row + 8) * ldc + col]) =
                make_float2(acc[mf][nf][2], acc[mf][nf][3]);
        }
    }
}

__global__ void __launch_bounds__(256, 2)
mma_nt2(const float* __restrict__ A, const float* __restrict__ B, float* __restrict__ C,
        int K, int lda, int ldb, int ldc) {
    __shared__ MSmem2 s;
    mma_core2(A, B, C, K, lda, ldb, ldc, blockIdx.x * MBM, blockIdx.y * MBN, s);
}

__global__ void __launch_bounds__(256, 2)
mma_attnv(const float* __restrict__ p, const float* __restrict__ vT, float* __restrict__ o) {
    int z = blockIdx.z;
    int b = z >> 3, h = z & 7;
    const float* A = p + (size_t)z * T_ * T_;
    const float* B = vT + (size_t)(b * NKV_ + (h >> 2)) * HD_ * T_;
    float* C = o + (size_t)b * T_ * H_ + (size_t)h * HD_;
    int bm = blockIdx.x * MBM;
    __shared__ MSmem2 s;
    mma_core2(A, B, C, bm + MBM, T_, T_, H_, bm, blockIdx.y * MBN, s);
}

// ===== 1-pass fp16 core (A, B single) — gate/up GEMMs =====
struct MSmem1 {
    uint32_t Ah[MBM][MLDW];
    uint32_t Bh[MBN][MLDW];
};

__device__ __forceinline__ void mma_core1(
    const float* __restrict__ A, const float* __restrict__ B, float* __restrict__ C,
    int K, int lda, int ldb, int ldc, int bm, int bn, MSmem1& s)
{
    const int tid = threadIdx.x;
    const int lane = tid & 31, wid = tid >> 5;
    const int wm = wid & 3, wn = wid >> 2;

    float acc[2][8][4];
#pragma unroll
    for (int i = 0; i < 2; i++)
#pragma unroll
        for (int j = 0; j < 8; j++)
#pragma unroll
            for (int e = 0; e < 4; e++) acc[i][j][e] = 0.f;

    const int lr = tid >> 3;
    const int lc = (tid & 7) * 4;
    const int wc = (tid & 7) * 2;

    const uint32_t sb = (uint32_t)__cvta_generic_to_shared(&s);
    const uint32_t offBh = MBM * MLDW * 4;
    const int arow = wm * 32 + (lane & 15);
    const int acol = (lane >> 4) * 8;
    const int brow = wn * 64 + (lane & 7) + ((lane >> 4) << 3);
    const int bcol = ((lane >> 3) & 1) << 3;

    for (int k0 = 0; k0 < K; k0 += MBK) {
#pragma unroll
        for (int p = 0; p < 4; p++) {
            int r = lr + p * 32;
            float4 av = *reinterpret_cast<const float4*>(&A[(size_t)(bm + r) * lda + k0 + lc]);
            convStoreH(av, &s.Ah[r][wc]);
            float4 bv = *reinterpret_cast<const float4*>(&B[(size_t)(bn + r) * ldb + k0 + lc]);
            convStoreH(bv, &s.Bh[r][wc]);
        }
        __syncthreads();

#pragma unroll
        for (int kk = 0; kk < 2; kk++) {
            uint32_t ah[2][4], bh[4][4];
#pragma unroll
            for (int mf = 0; mf < 2; mf++) {
                uint32_t ao = (uint32_t)(((arow + mf * 16) * MLDW * 4) + (kk * 16 + acol) * 2);
                ldsm4(ah[mf], sb + ao);
            }
#pragma unroll
            for (int np = 0; np < 4; np++) {
                uint32_t bo = (uint32_t)(((brow + np * 16) * MLDW * 4) + (kk * 16 + bcol) * 2);
                ldsm4(bh[np], sb + offBh + bo);
            }
#pragma unroll
            for (int mf = 0; mf < 2; mf++) {
#pragma unroll
                for (int nf = 0; nf < 8; nf++) {
                    int np = nf >> 1;
                    int hf = (nf & 1) * 2;
                    mma_fp(acc[mf][nf], ah[mf], bh[np][hf], bh[np][hf + 1]);
                }
            }
        }
        __syncthreads();
    }

#pragma unroll
    for (int mf = 0; mf < 2; mf++) {
        int row = bm + wm * 32 + mf * 16 + (lane >> 2);
#pragma unroll
        for (int nf = 0; nf < 8; nf++) {
            int col = bn + wn * 64 + nf * 8 + (lane & 3) * 2;
            *reinterpret_cast<float2*>(&C[(size_t)row * ldc + col]) =
                make_float2(acc[mf][nf][0], acc[mf][nf][1]);
            *reinterpret_cast<float2*>(&C[(size_t)(row + 8) * ldc + col]) =
                make_float2(acc[mf][nf][2], acc[mf][nf][3]);
        }
    }
}

__global__ void __launch_bounds__(256, 2)
mma_nt1(const float* __restrict__ A, const float* __restrict__ B, float* __restrict__ C,
        int K, int lda, int ldb, int ldc) {
    __shared__ MSmem1 s;
    mma_core1(A, B, C, K, lda, ldb, ldc, blockIdx.x * MBM, blockIdx.y * MBN, s);
}

// laurel1: split-K x8
__global__ void __launch_bounds__(256)
laurel1_kernel(const float* __restrict__ A, const float* __restrict__ B, float* __restrict__ P) {
    __shared__ float Bs[64][65];
    __shared__ float As[32][65];
    int tid = threadIdx.x;
    int bm = blockIdx.x * 32;
    int ks = blockIdx.y;
    int kbeg = ks * (H_ / 8), kend = kbeg + H_ / 8;
    float acc0[4] = {0.f, 0.f, 0.f, 0.f};
    float acc1[4] = {0.f, 0.f, 0.f, 0.f};
    int tn = tid & 15;
    int tr = tid >> 4;
    for (int k0 = kbeg; k0 < kend; k0 += 64) {
        for (int i = tid; i < 64 * 64; i += 256) {
            int n = i >> 6, kk = i & 63;
            Bs[n][kk] = B[(size_t)n * H_ + k0 + kk];
        }
        for (int i = tid; i < 32 * 64; i += 256) {
            int r = i >> 6, kk = i & 63;
            As[r][kk] = A[(size_t)(bm + r) * H_ + k0 + kk];
        }
        __syncthreads();
#pragma unroll 8
        for (int kk = 0; kk < 64; kk++) {
            float a0 = As[tr][kk], a1 = As[tr + 16][kk];
#pragma unroll
            for (int j = 0; j < 4; j++) {
                float bv = Bs[tn * 4 + j][kk];
                acc0[j] = fmaf(a0, bv, acc0[j]);
                acc1[j] = fmaf(a1, bv, acc1[j]);
            }
        }
        __syncthreads();
    }
#pragma unroll
    for (int j = 0; j < 4; j++) {
        P[((size_t)ks * BT_ + bm + tr) * LR_ + tn * 4 + j] = acc0[j];
        P[((size_t)ks * BT_ + bm + tr + 16) * LR_ + tn * 4 + j] = acc1[j];
    }
}

__global__ void laurel1_reduce(const float* __restrict__ P, float* __restrict__ out) {
    int i = blockIdx.x * blockDim.x + threadIdx.x;
    if (i >= BT_ * LR_) return;
    float s = 0.f;
#pragma unroll
    for (int k = 0; k < 8; k++) s += P[(size_t)k * BT_ * LR_ + i];
    out[i] = s;
}

extern "C" void kernel_launch(void* const* d_in, const int* in_sizes, int n_in,
                              void* d_out, int out_size) {
    const float* hs    = (const float*)d_in[0];
    const float* cosb  = (const float*)d_in[1];
    const float* sinb  = (const float*)d_in[2];
    const float* wq    = (const float*)d_in[3];
    const float* wk    = (const float*)d_in[4];
    const float* wv    = (const float*)d_in[5];
    const float* wo    = (const float*)d_in[6];
    const float* qnw   = (const float*)d_in[7];
    const float* knw   = (const float*)d_in[8];
    const float* in_ln = (const float*)d_in[9];
    const float* pa_ln = (const float*)d_in[10];
    const float* pf_ln = (const float*)d_in[11];
    const float* pw_ln = (const float*)d_in[12];
    const float* gatew = (const float*)d_in[13];
    const float* upw   = (const float*)d_in[14];
    const float* downw = (const float*)d_in[15];
    const float* llw   = (const float*)d_in[16];
    const float* lrw   = (const float*)d_in[17];
    const float* lnw   = (const float*)d_in[18];
    const float* rnw   = (const float*)d_in[19];
    const float* rw    = (const float*)d_in[20];
    const float* pcw   = (const float*)d_in[21];
    const float* ccw   = (const float*)d_in[22];
    const float* cscal = (const float*)d_in[23];
    float* out = (float*)d_out;

    Scratch* S = 0;
    cudaGetSymbolAddress((void**)&S, g_scratch);

    router_kernel<<<BT_, 256>>>(hs, rnw, rw, S->m);
    predict_kernel<<<BT_, 256>>>(hs, S->m, pcw, S->pred);
    ln_kernel<<<BT_, 256>>>(S->pred, in_ln, (const float*)0, (const float*)0, 1.f, S->xnorm);

    laurel1_kernel<<<dim3(BT_ / 32, 8), 256>>>(S->xnorm, llw, S->lrpart);
    laurel1_reduce<<<(BT_ * LR_ + 255) / 256, 256>>>(S->lrpart, S->lrbuf);
    mma_nt2<<<dim3(16, 16), 256>>>(S->lrbuf, lrw, S->laurel, LR_, LR_, LR_, H_);
    ln_kernel<<<BT_, 256>>>(S->laurel, lnw, S->xnorm, (const float*)0, 1.f, S->laurel);

    // q,k: 3-pass bf16 (softmax-feeding); v: 2-pass fp16
    mma_nt3<<<dim3(16, 16), 256>>>(S->xnorm, wq, S->qraw, H_, H_, H_, NH_ * HD_);
    mma_nt3<<<dim3(16, 4), 256>>>(S->xnorm, wk, S->kraw, H_, H_, H_, NKV_ * HD_);
    mma_nt2<<<dim3(16, 4), 256>>>(S->xnorm, wv, S->vraw, H_, H_, H_, NKV_ * HD_);
    qkvpost_kernel<<<BT_ * NH_, 256>>>(S->qraw, qnw, cosb, sinb, S->q, NH_, 1, 0);
    qkvpost_kernel<<<BT_ * NKV_, 256>>>(S->kraw, knw, cosb, sinb, S->k, NKV_, 1, 0);
    qkvpost_kernel<<<BT_ * NKV_, 256>>>(S->vraw, (const float*)0, cosb, sinb, S->vT, NKV_, 0, 1);

    mma_scores<<<dim3(8, 8, B_ * NH_), 256>>>(S->q, S->k, S->scores);
    softmax_kernel<<<B_ * NH_ * T_, 256>>>(S->scores);
    mma_attnv<<<dim3(8, 2, B_ * NH_), 256>>>(S->scores, S->vT, S->attnout);
    mma_nt2<<<dim3(16, 16), 256>>>(S->attnout, wo, S->attnproj,
                                   NH_ * HD_, NH_ * HD_, NH_ * HD_, H_);

    ln_kernel<<<BT_, 256>>>(S->attnproj, pa_ln, S->pred, S->laurel,
                            0.7071067811865476f, S->attnlaurel);
    ln_kernel<<<BT_, 256>>>(S->attnlaurel, pf_ln, (const float*)0, (const float*)0, 1.f, S->hn);

    // gate/up: 1-pass fp16; down: 2-pass fp16
    mma_nt1<<<dim3(16, 64), 256>>>(S->hn, gatew, S->gate, H_, H_, H_, FF_);
    mma_nt1<<<dim3(16, 64), 256>>>(S->hn, upw, S->up, H_, H_, H_, FF_);

    int n4 = (int)(((size_t)BT_ * FF_) / 4);
    gelumul_kernel<<<(n4 + 255) / 256, 256>>>(S->gate, S->up, n4);

    mma_nt2<<<dim3(16, 16), 256>>>(S->gate, downw, S->ffw, FF_, FF_, FF_, H_);
    ln_kernel<<<BT_, 256>>>(S->ffw, pw_ln, S->attnlaurel, (const float*)0, 1.f, S->act);

    router_kernel<<<BT_, 256>>>(S->act, rnw, rw, S->mc);
    correct_kernel<<<BT_, 256>>>(S->act, S->pred, S->mc, ccw, cscal, out);

    (void)in_sizes; (void)n_in; (void)out_size;
}

// round 9
// speedup vs baseline: 1.6890x; 1.1553x over previous
#include <cuda_runtime.h>
#include <cstdint>
#include <cstddef>
#include <math.h>

typedef unsigned short u16;

constexpr int B_ = 2, T_ = 1024, H_ = 2048, NH_ = 8, NKV_ = 2, HD_ = 256;
constexpr int FF_ = 8192, LR_ = 64;
constexpr int BT_ = B_ * T_;
constexpr size_t BTH_ = (size_t)BT_ * H_;
constexpr float EPS_ = 1e-6f;

struct Scratch {
    float pred[4 * BTH_];
    float xnorm[BTH_];
    float lrpart[8 * BT_ * LR_];
    float lrbuf[BT_ * LR_];
    float laurel[BTH_];
    float qraw[BTH_];
    float kraw[(size_t)BT_ * NKV_ * HD_];
    float vraw[(size_t)BT_ * NKV_ * HD_];
    float q[BTH_];
    float k[(size_t)BT_ * NKV_ * HD_];
    float vT[(size_t)BT_ * NKV_ * HD_];
    float scores[(size_t)B_ * NH_ * T_ * T_];
    float attnout[BTH_];
    float attnproj[BTH_];
    float attnlaurel[BTH_];
    float hn[BTH_];
    float gate[(size_t)BT_ * FF_];
    float up[(size_t)BT_ * FF_];
    float ffw[BTH_];
    float act[BTH_];
    float m[BT_ * 4];
    float mc[BT_ * 4];
};
__device__ Scratch g_scratch;

// ---------- bf16 / fp16 bit helpers ----------
__device__ __forceinline__ uint32_t f2bf(float x) {
    uint32_t u = __float_as_uint(x);
    return (u + 0x7FFFu + ((u >> 16) & 1u)) >> 16;
}
__device__ __forceinline__ float bf2f(uint32_t b) {
    return __uint_as_float(b << 16);
}
__device__ __forceinline__ u16 f2h(float x) {
    u16 h;
    asm("cvt.rn.f16.f32 %0, %1;" : "=h"(h) : "f"(x));
    return h;
}

// ---------- reductions ----------
__device__ __forceinline__ float warpSum(float v) {
#pragma unroll
    for (int o = 16; o > 0; o >>= 1) v += __shfl_xor_sync(0xffffffffu, v, o);
    return v;
}
__device__ __forceinline__ float warpMax(float v) {
#pragma unroll
    for (int o = 16; o > 0; o >>= 1) v = fmaxf(v, __shfl_xor_sync(0xffffffffu, v, o));
    return v;
}
__device__ __forceinline__ float blockSum(float v, float* red) {
    v = warpSum(v);
    int lane = threadIdx.x & 31, w = threadIdx.x >> 5;
    if (lane == 0) red[w] = v;
    __syncthreads();
    int nw = (blockDim.x + 31) >> 5;
    float r = (lane < nw) ? red[lane] : 0.f;
    if (w == 0) {
        r = warpSum(r);
        if (lane == 0) red[0] = r;
    }
    __syncthreads();
    r = red[0];
    __syncthreads();
    return r;
}
__device__ __forceinline__ float blockMax(float v, float* red) {
    v = warpMax(v);
    int lane = threadIdx.x & 31, w = threadIdx.x >> 5;
    if (lane == 0) red[w] = v;
    __syncthreads();
    int nw = (blockDim.x + 31) >> 5;
    float r = (lane < nw) ? red[lane] : -INFINITY;
    if (w == 0) {
        r = warpMax(r);
        if (lane == 0) red[0] = r;
    }
    __syncthreads();
    r = red[0];
    __syncthreads();
    return r;
}

// ---------- elementwise kernels ----------
__global__ void ln_kernel(const float* __restrict__ a, const float* __restrict__ w,
                          const float* __restrict__ add1, const float* __restrict__ add2,
                          float scale, float* __restrict__ dst) {
    __shared__ float sx[H_];
    __shared__ float red[32];
    size_t off = (size_t)blockIdx.x * H_;
    int tid = threadIdx.x;
    float ls = 0.f;
    for (int i = tid; i < H_; i += blockDim.x) {
        float v = a[off + i];
        sx[i] = v;
        ls += v;
    }
    float mean = blockSum(ls, red) * (1.f / H_);
    float lv = 0.f;
    for (int i = tid; i < H_; i += blockDim.x) {
        float d = sx[i] - mean;
        lv += d * d;
    }
    float var = blockSum(lv, red) * (1.f / H_);
    float rs = rsqrtf(var + EPS_);
    for (int i = tid; i < H_; i += blockDim.x) {
        float v = (sx[i] - mean) * rs * w[i];
        if (add1) v += add1[off + i];
        if (add2) v += add2[off + i];
        dst[off + i] = v * scale;
    }
}

__global__ void router_kernel(const float* __restrict__ x, const float* __restrict__ nw,
                              const float* __restrict__ rw, float* __restrict__ m) {
    __shared__ float sx[H_];
    __shared__ float red[32];
    size_t off = (size_t)blockIdx.x * H_;
    int tid = threadIdx.x;
    float ls = 0.f;
    for (int i = tid; i < H_; i += blockDim.x) {
        float v = x[off + i];
        sx[i] = v;
        ls += v;
    }
    float mean = blockSum(ls, red) * (1.f / H_);
    float lv = 0.f;
    for (int i = tid; i < H_; i += blockDim.x) {
        float d = sx[i] - mean;
        lv += d * d;
    }
    float rs = rsqrtf(blockSum(lv, red) * (1.f / H_) + EPS_);
    float a0 = 0.f, a1 = 0.f, a2 = 0.f, a3 = 0.f;
    for (int i = tid; i < H_; i += blockDim.x) {
        float r = (sx[i] - mean) * rs * nw[i] * (1.f / H_);
        a0 += r * rw[i];
        a1 += r * rw[H_ + i];
        a2 += r * rw[2 * H_ + i];
        a3 += r * rw[3 * H_ + i];
    }
    float t0 = blockSum(a0, red);
    float t1 = blockSum(a1, red);
    float t2 = blockSum(a2, red);
    float t3 = blockSum(a3, red);
    if (tid == 0) {
        m[blockIdx.x * 4 + 0] = tanhf(t0);
        m[blockIdx.x * 4 + 1] = tanhf(t1);
        m[blockIdx.x * 4 + 2] = tanhf(t2);
        m[blockIdx.x * 4 + 3] = tanhf(t3);
    }
}

__global__ void predict_kernel(const float* __restrict__ hs, const float* __restrict__ m,
                               const float* __restrict__ pcw, float* __restrict__ pred) {
    __shared__ float cf[16];
    int token = blockIdx.x, tid = threadIdx.x;
    if (tid < 16) {
        float s = 0.f;
#pragma unroll
        for (int i = 0; i < 4; i++) s += m[token * 4 + i] * pcw[tid * 4 + i];
        cf[tid] = s;
    }
    __syncthreads();
    size_t off = (size_t)token * H_;
    for (int f = tid; f < H_; f += blockDim.x) {
        float h0 = hs[off + f];
        float h1 = hs[BTH_ + off + f];
        float h2 = hs[2 * BTH_ + off + f];
        float h3 = hs[3 * BTH_ + off + f];
        pred[off + f]            = h0 + h0 * cf[0]  + h1 * cf[1]  + h2 * cf[2]  + h3 * cf[3];
        pred[BTH_ + off + f]     = h1 + h0 * cf[4]  + h1 * cf[5]  + h2 * cf[6]  + h3 * cf[7];
        pred[2 * BTH_ + off + f] = h2 + h0 * cf[8]  + h1 * cf[9]  + h2 * cf[10] + h3 * cf[11];
        pred[3 * BTH_ + off + f] = h3 + h0 * cf[12] + h1 * cf[13] + h2 * cf[14] + h3 * cf[15];
    }
}

__global__ void correct_kernel(const float* __restrict__ act, const float* __restrict__ pred,
                               const float* __restrict__ mc, const float* __restrict__ ccw,
                               const float* __restrict__ cscale, float* __restrict__ out) {
    __shared__ float cc[4];
    int token = blockIdx.x, tid = threadIdx.x;
    if (tid < 4) {
        float s = 1.f;
#pragma unroll
        for (int i = 0; i < 4; i++) s += mc[token * 4 + i] * ccw[tid * 4 + i];
        cc[tid] = s;
    }
    __syncthreads();
    size_t off = (size_t)token * H_;
    for (int f = tid; f < H_; f += blockDim.x) {
        float p0 = pred[off + f];
        float inno = act[off + f] - p0;
        out[off + f]            = (inno * cc[0] + p0) * cscale[f];
        out[BTH_ + off + f]     = inno * cc[1] + pred[BTH_ + off + f];
        out[2 * BTH_ + off + f] = inno * cc[2] + pred[2 * BTH_ + off + f];
        out[3 * BTH_ + off + f] = inno * cc[3] + pred[3 * BTH_ + off + f];
    }
}

__global__ void qkvpost_kernel(const float* __restrict__ raw, const float* __restrict__ nw,
                               const float* __restrict__ cosb, const float* __restrict__ sinb,
                               float* __restrict__ out, int nheads, int do_rope, int trans) {
    __shared__ float sx[HD_];
    __shared__ float red[32];
    int idx = blockIdx.x;
    int h = idx % nheads;
    int bt = idx / nheads;
    int t = bt % T_, b = bt / T_;
    int d = threadIdx.x;
    float v = raw[(size_t)bt * nheads * HD_ + h * HD_ + d];
    float mean = blockSum(v, red) * (1.f / HD_);
    float c = v - mean;
    float var = blockSum(c * c, red) * (1.f / HD_);
    float ln = c * rsqrtf(var + EPS_) * (nw ? nw[d] : 1.f);
    sx[d] = ln;
    __syncthreads();
    float o = ln;
    if (do_rope) {
        float cs = cosb[(size_t)bt * HD_ + d];
        float sn = sinb[(size_t)bt * HD_ + d];
        float rot = (d < 128) ? -sx[d + 128] : sx[d - 128];
        o = ln * cs + rot * sn;
    }
    if (trans) {
        out[((size_t)(b * nheads + h) * HD_ + d) * T_ + t] = o;
    } else {
        out[((size_t)(b * nheads + h) * T_ + t) * HD_ + d] = o;
    }
}

__global__ void softmax_kernel(float* __restrict__ scores) {
    __shared__ float sx[T_];
    __shared__ float red[32];
    int q = blockIdx.x % T_;
    size_t off = (size_t)blockIdx.x * T_;
    int tid = threadIdx.x;
    int n = q + 1;
    float lm = -INFINITY;
    for (int i = tid; i < n; i += blockDim.x) {
        float v = scores[off + i];
        sx[i] = v;
        lm = fmaxf(lm, v);
    }
    float gm = blockMax(lm, red);
    float lsum = 0.f;
    for (int i = tid; i < n; i += blockDim.x) {
        float e = __expf(sx[i] - gm);
        sx[i] = e;
        lsum += e;
    }
    float inv = 1.f / blockSum(lsum, red);
    for (int i = tid; i < T_; i += blockDim.x) {
        scores[off + i] = (i < n) ? sx[i] * inv : 0.f;
    }
}

__device__ __forceinline__ float gelu_tanh(float x) {
    return 0.5f * x * (1.f + tanhf(0.7978845608028654f * (x + 0.044715f * x * x * x)));
}

__global__ void gelumul_kernel(float* __restrict__ g, const float* __restrict__ u, int n4) {
    int i = blockIdx.x * blockDim.x + threadIdx.x;
    if (i >= n4) return;
    float4 a = reinterpret_cast<float4*>(g)[i];
    float4 b = reinterpret_cast<const float4*>(u)[i];
    a.x = gelu_tanh(a.x) * b.x;
    a.y = gelu_tanh(a.y) * b.y;
    a.z = gelu_tanh(a.z) * b.z;
    a.w = gelu_tanh(a.w) * b.w;
    reinterpret_cast<float4*>(g)[i] = a;
}

// ===== shared MMA plumbing =====
__device__ __forceinline__ void ldsm4(uint32_t* r, uint32_t addr) {
    asm volatile("ldmatrix.sync.aligned.m8n8.x4.shared.b16 {%0,%1,%2,%3}, [%4];"
                 : "=r"(r[0]), "=r"(r[1]), "=r"(r[2]), "=r"(r[3]) : "r"(addr));
}
__device__ __forceinline__ void mma_bf(float* d, const uint32_t* a, uint32_t b0, uint32_t b1) {
    asm volatile("mma.sync.aligned.m16n8k16.row.col.f32.bf16.bf16.f32 "
                 "{%0,%1,%2,%3}, {%4,%5,%6,%7}, {%8,%9}, {%0,%1,%2,%3};"
                 : "+f"(d[0]), "+f"(d[1]), "+f"(d[2]), "+f"(d[3])
                 : "r"(a[0]), "r"(a[1]), "r"(a[2]), "r"(a[3]), "r"(b0), "r"(b1));
}
__device__ __forceinline__ void mma_fp(float* d, const uint32_t* a, uint32_t b0, uint32_t b1) {
    asm volatile("mma.sync.aligned.m16n8k16.row.col.f32.f16.f16.f32 "
                 "{%0,%1,%2,%3}, {%4,%5,%6,%7}, {%8,%9}, {%0,%1,%2,%3};"
                 : "+f"(d[0]), "+f"(d[1]), "+f"(d[2]), "+f"(d[3])
                 : "r"(a[0]), "r"(a[1]), "r"(a[2]), "r"(a[3]), "r"(b0), "r"(b1));
}
__device__ __forceinline__ void splitStoreBF(float4 v, uint32_t* hi, uint32_t* lo) {
    uint32_t hx = f2bf(v.x), hy = f2bf(v.y), hz = f2bf(v.z), hw = f2bf(v.w);
    uint32_t lx = f2bf(v.x - bf2f(hx));
    uint32_t ly = f2bf(v.y - bf2f(hy));
    uint32_t lz = f2bf(v.z - bf2f(hz));
    uint32_t lw = f2bf(v.w - bf2f(hw));
    hi[0] = hx | (hy << 16);
    hi[1] = hz | (hw << 16);
    lo[0] = lx | (ly << 16);
    lo[1] = lz | (lw << 16);
}
__device__ __forceinline__ void convStoreH(float4 v, uint32_t* hi) {
    u16 hx = f2h(v.x), hy = f2h(v.y), hz = f2h(v.z), hw = f2h(v.w);
    hi[0] = (uint32_t)hx | ((uint32_t)hy << 16);
    hi[1] = (uint32_t)hz | ((uint32_t)hw << 16);
}

constexpr int MBM = 128, MBN = 128, MBK = 32;
constexpr int MLDW = 20;   // words per smem row = 40 halves = 80 B (conflict-free)

// ===== 3-pass bf16 core — q/k projections + scores =====
struct MSmem3 {
    uint32_t Ah[MBM][MLDW];
    uint32_t Al[MBM][MLDW];
    uint32_t Bh[MBN][MLDW];
    uint32_t Bl[MBN][MLDW];
};

__device__ __forceinline__ void mma_core3(
    const float* __restrict__ A, const float* __restrict__ B, float* __restrict__ C,
    int K, int lda, int ldb, int ldc, int bm, int bn, MSmem3& s)
{
    const int tid = threadIdx.x;
    const int lane = tid & 31, wid = tid >> 5;
    const int wm = wid & 3, wn = wid >> 2;

    float acc[2][8][4];
#pragma unroll
    for (int i = 0; i < 2; i++)
#pragma unroll
        for (int j = 0; j < 8; j++)
#pragma unroll
            for (int e = 0; e < 4; e++) acc[i][j][e] = 0.f;

    const int lr = tid >> 3;
    const int lc = (tid & 7) * 4;
    const int wc = (tid & 7) * 2;

    const uint32_t sb = (uint32_t)__cvta_generic_to_shared(&s);
    const uint32_t offAl = MBM * MLDW * 4;
    const uint32_t offBh = 2 * MBM * MLDW * 4;
    const uint32_t offBl = 3 * MBM * MLDW * 4;
    const int arow = wm * 32 + (lane & 15);
    const int acol = (lane >> 4) * 8;
    const int brow = wn * 64 + (lane & 7) + ((lane >> 4) << 3);
    const int bcol = ((lane >> 3) & 1) << 3;

    for (int k0 = 0; k0 < K; k0 += MBK) {
#pragma unroll
        for (int p = 0; p < 4; p++) {
            int r = lr + p * 32;
            float4 av = *reinterpret_cast<const float4*>(&A[(size_t)(bm + r) * lda + k0 + lc]);
            splitStoreBF(av, &s.Ah[r][wc], &s.Al[r][wc]);
            float4 bv = *reinterpret_cast<const float4*>(&B[(size_t)(bn + r) * ldb + k0 + lc]);
            splitStoreBF(bv, &s.Bh[r][wc], &s.Bl[r][wc]);
        }
        __syncthreads();

#pragma unroll
        for (int kk = 0; kk < 2; kk++) {
            uint32_t ah[2][4], al[2][4], bh[4][4], bl[4][4];
#pragma unroll
            for (int mf = 0; mf < 2; mf++) {
                uint32_t ao = (uint32_t)(((arow + mf * 16) * MLDW * 4) + (kk * 16 + acol) * 2);
                ldsm4(ah[mf], sb + ao);
                ldsm4(al[mf], sb + offAl + ao);
            }
#pragma unroll
            for (int np = 0; np < 4; np++) {
                uint32_t bo = (uint32_t)(((brow + np * 16) * MLDW * 4) + (kk * 16 + bcol) * 2);
                ldsm4(bh[np], sb + offBh + bo);
                ldsm4(bl[np], sb + offBl + bo);
            }
#pragma unroll
            for (int mf = 0; mf < 2; mf++) {
#pragma unroll
                for (int nf = 0; nf < 8; nf++) {
                    int np = nf >> 1;
                    int hf = (nf & 1) * 2;
                    mma_bf(acc[mf][nf], ah[mf], bh[np][hf], bh[np][hf + 1]);
                    mma_bf(acc[mf][nf], al[mf], bh[np][hf], bh[np][hf + 1]);
                    mma_bf(acc[mf][nf], ah[mf], bl[np][hf], bl[np][hf + 1]);
                }
            }
        }
        __syncthreads();
    }

#pragma unroll
    for (int mf = 0; mf < 2; mf++) {
        int row = bm + wm * 32 + mf * 16 + (lane >> 2);
#pragma unroll
        for (int nf = 0; nf < 8; nf++) {
            int col = bn + wn * 64 + nf * 8 + (lane & 3) * 2;
            *reinterpret_cast<float2*>(&C[(size_t)row * ldc + col]) =
                make_float2(acc[mf][nf][0], acc[mf][nf][1]);
            *reinterpret_cast<float2*>(&C[(size_t)(row + 8) * ldc + col]) =
                make_float2(acc[mf][nf][2], acc[mf][nf][3]);
        }
    }
}

__global__ void __launch_bounds__(256, 2)
mma_nt3(const float* __restrict__ A, const float* __restrict__ B, float* __restrict__ C,
        int K, int lda, int ldb, int ldc) {
    __shared__ MSmem3 s;
    mma_core3(A, B, C, K, lda, ldb, ldc, blockIdx.x * MBM, blockIdx.y * MBN, s);
}

__global__ void __launch_bounds__(256, 2)
mma_scores(const float* __restrict__ q, const float* __restrict__ k, float* __restrict__ sc) {
    if (blockIdx.y > blockIdx.x) return;
    int z = blockIdx.z;
    int b = z >> 3, h = z & 7;
    const float* A = q + (size_t)z * T_ * HD_;
    const float* B = k + (size_t)(b * NKV_ + (h >> 2)) * T_ * HD_;
    float* C = sc + (size_t)z * T_ * T_;
    __shared__ MSmem3 s;
    mma_core3(A, B, C, HD_, HD_, HD_, T_, blockIdx.x * MBM, blockIdx.y * MBN, s);
}

// ===== 1-pass fp16 core — all non-softmax-feeding GEMMs =====
struct MSmem1 {
    uint32_t Ah[MBM][MLDW];
    uint32_t Bh[MBN][MLDW];
};

__device__ __forceinline__ void mma_core1(
    const float* __restrict__ A, const float* __restrict__ B, float* __restrict__ C,
    int K, int lda, int ldb, int ldc, int bm, int bn, MSmem1& s)
{
    const int tid = threadIdx.x;
    const int lane = tid & 31, wid = tid >> 5;
    const int wm = wid & 3, wn = wid >> 2;

    float acc[2][8][4];
#pragma unroll
    for (int i = 0; i < 2; i++)
#pragma unroll
        for (int j = 0; j < 8; j++)
#pragma unroll
            for (int e = 0; e < 4; e++) acc[i][j][e] = 0.f;

    const int lr = tid >> 3;
    const int lc = (tid & 7) * 4;
    const int wc = (tid & 7) * 2;

    const uint32_t sb = (uint32_t)__cvta_generic_to_shared(&s);
    const uint32_t offBh = MBM * MLDW * 4;
    const int arow = wm * 32 + (lane & 15);
    const int acol = (lane >> 4) * 8;
    const int brow = wn * 64 + (lane & 7) + ((lane >> 4) << 3);
    const int bcol = ((lane >> 3) & 1) << 3;

    for (int k0 = 0; k0 < K; k0 += MBK) {
#pragma unroll
        for (int p = 0; p < 4; p++) {
            int r = lr + p * 32;
            float4 av = *reinterpret_cast<const float4*>(&A[(size_t)(bm + r) * lda + k0 + lc]);
            convStoreH(av, &s.Ah[r][wc]);
            float4 bv = *reinterpret_cast<const float4*>(&B[(size_t)(bn + r) * ldb + k0 + lc]);
            convStoreH(bv, &s.Bh[r][wc]);
        }
        __syncthreads();

#pragma unroll
        for (int kk = 0; kk < 2; kk++) {
            uint32_t ah[2][4], bh[4][4];
#pragma unroll
            for (int mf = 0; mf < 2; mf++) {
                uint32_t ao = (uint32_t)(((arow + mf * 16) * MLDW * 4) + (kk * 16 + acol) * 2);
                ldsm4(ah[mf], sb + ao);
            }
#pragma unroll
            for (int np = 0; np < 4; np++) {
                uint32_t bo = (uint32_t)(((brow + np * 16) * MLDW * 4) + (kk * 16 + bcol) * 2);
                ldsm4(bh[np], sb + offBh + bo);
            }
#pragma unroll
            for (int mf = 0; mf < 2; mf++) {
#pragma unroll
                for (int nf = 0; nf < 8; nf++) {
                    int np = nf >> 1;
                    int hf = (nf & 1) * 2;
                    mma_fp(acc[mf][nf], ah[mf], bh[np][hf], bh[np][hf + 1]);
                }
            }
        }
        __syncthreads();
    }

#pragma unroll
    for (int mf = 0; mf < 2; mf++) {
        int row = bm + wm * 32 + mf * 16 + (lane >> 2);
#pragma unroll
        for (int nf = 0; nf < 8; nf++) {
            int col = bn + wn * 64 + nf * 8 + (lane & 3) * 2;
            *reinterpret_cast<float2*>(&C[(size_t)row * ldc + col]) =
                make_float2(acc[mf][nf][0], acc[mf][nf][1]);
            *reinterpret_cast<float2*>(&C[(size_t)(row + 8) * ldc + col]) =
                make_float2(acc[mf][nf][2], acc[mf][nf][3]);
        }
    }
}

__global__ void __launch_bounds__(256, 2)
mma_nt1(const float* __restrict__ A, const float* __restrict__ B, float* __restrict__ C,
        int K, int lda, int ldb, int ldc) {
    __shared__ MSmem1 s;
    mma_core1(A, B, C, K, lda, ldb, ldc, blockIdx.x * MBM, blockIdx.y * MBN, s);
}

__global__ void __launch_bounds__(256, 2)
mma_attnv(const float* __restrict__ p, const float* __restrict__ vT, float* __restrict__ o) {
    int z = blockIdx.z;
    int b = z >> 3, h = z & 7;
    const float* A = p + (size_t)z * T_ * T_;
    const float* B = vT + (size_t)(b * NKV_ + (h >> 2)) * HD_ * T_;
    float* C = o + (size_t)b * T_ * H_ + (size_t)h * HD_;
    int bm = blockIdx.x * MBM;
    __shared__ MSmem1 s;
    mma_core1(A, B, C, bm + MBM, T_, T_, H_, bm, blockIdx.y * MBN, s);
}

// laurel1: split-K x8
__global__ void __launch_bounds__(256)
laurel1_kernel(const float* __restrict__ A, const float* __restrict__ B, float* __restrict__ P) {
    __shared__ float Bs[64][65];
    __shared__ float As[32][65];
    int tid = threadIdx.x;
    int bm = blockIdx.x * 32;
    int ks = blockIdx.y;
    int kbeg = ks * (H_ / 8), kend = kbeg + H_ / 8;
    float acc0[4] = {0.f, 0.f, 0.f, 0.f};
    float acc1[4] = {0.f, 0.f, 0.f, 0.f};
    int tn = tid & 15;
    int tr = tid >> 4;
    for (int k0 = kbeg; k0 < kend; k0 += 64) {
        for (int i = tid; i < 64 * 64; i += 256) {
            int n = i >> 6, kk = i & 63;
            Bs[n][kk] = B[(size_t)n * H_ + k0 + kk];
        }
        for (int i = tid; i < 32 * 64; i += 256) {
            int r = i >> 6, kk = i & 63;
            As[r][kk] = A[(size_t)(bm + r) * H_ + k0 + kk];
        }
        __syncthreads();
#pragma unroll 8
        for (int kk = 0; kk < 64; kk++) {
            float a0 = As[tr][kk], a1 = As[tr + 16][kk];
#pragma unroll
            for (int j = 0; j < 4; j++) {
                float bv = Bs[tn * 4 + j][kk];
                acc0[j] = fmaf(a0, bv, acc0[j]);
                acc1[j] = fmaf(a1, bv, acc1[j]);
            }
        }
        __syncthreads();
    }
#pragma unroll
    for (int j = 0; j < 4; j++) {
        P[((size_t)ks * BT_ + bm + tr) * LR_ + tn * 4 + j] = acc0[j];
        P[((size_t)ks * BT_ + bm + tr + 16) * LR_ + tn * 4 + j] = acc1[j];
    }
}

__global__ void laurel1_reduce(const float* __restrict__ P, float* __restrict__ out) {
    int i = blockIdx.x * blockDim.x + threadIdx.x;
    if (i >= BT_ * LR_) return;
    float s = 0.f;
#pragma unroll
    for (int k = 0; k < 8; k++) s += P[(size_t)k * BT_ * LR_ + i];
    out[i] = s;
}

extern "C" void kernel_launch(void* const* d_in, const int* in_sizes, int n_in,
                              void* d_out, int out_size) {
    const float* hs    = (const float*)d_in[0];
    const float* cosb  = (const float*)d_in[1];
    const float* sinb  = (const float*)d_in[2];
    const float* wq    = (const float*)d_in[3];
    const float* wk    = (const float*)d_in[4];
    const float* wv    = (const float*)d_in[5];
    const float* wo    = (const float*)d_in[6];
    const float* qnw   = (const float*)d_in[7];
    const float* knw   = (const float*)d_in[8];
    const float* in_ln = (const float*)d_in[9];
    const float* pa_ln = (const float*)d_in[10];
    const float* pf_ln = (const float*)d_in[11];
    const float* pw_ln = (const float*)d_in[12];
    const float* gatew = (const float*)d_in[13];
    const float* upw   = (const float*)d_in[14];
    const float* downw = (const float*)d_in[15];
    const float* llw   = (const float*)d_in[16];
    const float* lrw   = (const float*)d_in[17];
    const float* lnw   = (const float*)d_in[18];
    const float* rnw   = (const float*)d_in[19];
    const float* rw    = (const float*)d_in[20];
    const float* pcw   = (const float*)d_in[21];
    const float* ccw   = (const float*)d_in[22];
    const float* cscal = (const float*)d_in[23];
    float* out = (float*)d_out;

    Scratch* S = 0;
    cudaGetSymbolAddress((void**)&S, g_scratch);

    router_kernel<<<BT_, 256>>>(hs, rnw, rw, S->m);
    predict_kernel<<<BT_, 256>>>(hs, S->m, pcw, S->pred);
    ln_kernel<<<BT_, 256>>>(S->pred, in_ln, (const float*)0, (const float*)0, 1.f, S->xnorm);

    laurel1_kernel<<<dim3(BT_ / 32, 8), 256>>>(S->xnorm, llw, S->lrpart);
    laurel1_reduce<<<(BT_ * LR_ + 255) / 256, 256>>>(S->lrpart, S->lrbuf);
    mma_nt1<<<dim3(16, 16), 256>>>(S->lrbuf, lrw, S->laurel, LR_, LR_, LR_, H_);
    ln_kernel<<<BT_, 256>>>(S->laurel, lnw, S->xnorm, (const float*)0, 1.f, S->laurel);

    // q,k: 3-pass bf16 (softmax-feeding); v: 1-pass fp16
    mma_nt3<<<dim3(16, 16), 256>>>(S->xnorm, wq, S->qraw, H_, H_, H_, NH_ * HD_);
    mma_nt3<<<dim3(16, 4), 256>>>(S->xnorm, wk, S->kraw, H_, H_, H_, NKV_ * HD_);
    mma_nt1<<<dim3(16, 4), 256>>>(S->xnorm, wv, S->vraw, H_, H_, H_, NKV_ * HD_);
    qkvpost_kernel<<<BT_ * NH_, 256>>>(S->qraw, qnw, cosb, sinb, S->q, NH_, 1, 0);
    qkvpost_kernel<<<BT_ * NKV_, 256>>>(S->kraw, knw, cosb, sinb, S->k, NKV_, 1, 0);
    qkvpost_kernel<<<BT_ * NKV_, 256>>>(S->vraw, (const float*)0, cosb, sinb, S->vT, NKV_, 0, 1);

    mma_scores<<<dim3(8, 8, B_ * NH_), 256>>>(S->q, S->k, S->scores);
    softmax_kernel<<<B_ * NH_ * T_, 256>>>(S->scores);
    mma_attnv<<<dim3(8, 2, B_ * NH_), 256>>>(S->scores, S->vT, S->attnout);
    mma_nt1<<<dim3(16, 16), 256>>>(S->attnout, wo, S->attnproj,
                                   NH_ * HD_, NH_ * HD_, NH_ * HD_, H_);

    ln_kernel<<<BT_, 256>>>(S->attnproj, pa_ln, S->pred, S->laurel,
                            0.7071067811865476f, S->attnlaurel);
    ln_kernel<<<BT_, 256>>>(S->attnlaurel, pf_ln, (const float*)0, (const float*)0, 1.f, S->hn);

    mma_nt1<<<dim3(16, 64), 256>>>(S->hn, gatew, S->gate, H_, H_, H_, FF_);
    mma_nt1<<<dim3(16, 64), 256>>>(S->hn, upw, S->up, H_, H_, H_, FF_);

    int n4 = (int)(((size_t)BT_ * FF_) / 4);
    gelumul_kernel<<<(n4 + 255) / 256, 256>>>(S->gate, S->up, n4);

    mma_nt1<<<dim3(16, 16), 256>>>(S->gate, downw, S->ffw, FF_, FF_, FF_, H_);
    ln_kernel<<<BT_, 256>>>(S->ffw, pw_ln, S->attnlaurel, (const float*)0, 1.f, S->act);

    router_kernel<<<BT_, 256>>>(S->act, rnw, rw, S->mc);
    correct_kernel<<<BT_, 256>>>(S->act, S->pred, S->mc, ccw, cscal, out);

    (void)in_sizes; (void)n_in; (void)out_size;
}

// round 10
// speedup vs baseline: 1.7043x; 1.0090x over previous
#include <cuda_runtime.h>
#include <cstdint>
#include <cstddef>
#include <math.h>

typedef unsigned short u16;

constexpr int B_ = 2, T_ = 1024, H_ = 2048, NH_ = 8, NKV_ = 2, HD_ = 256;
constexpr int FF_ = 8192, LR_ = 64;
constexpr int BT_ = B_ * T_;
constexpr size_t BTH_ = (size_t)BT_ * H_;
constexpr float EPS_ = 1e-6f;

struct Scratch {
    float pred[4 * BTH_];
    float xnorm[BTH_];
    float lrpart[8 * BT_ * LR_];
    float lrbuf[BT_ * LR_];
    float laurel[BTH_];
    float qraw[BTH_];
    float kraw[(size_t)BT_ * NKV_ * HD_];
    float vraw[(size_t)BT_ * NKV_ * HD_];
    float q[BTH_];
    float k[(size_t)BT_ * NKV_ * HD_];
    float vT[(size_t)BT_ * NKV_ * HD_];
    float scores[(size_t)B_ * NH_ * T_ * T_];
    float attnout[BTH_];
    float attnproj[BTH_];
    float attnlaurel[BTH_];
    float hn[BTH_];
    float gate[(size_t)BT_ * FF_];
    float up[(size_t)BT_ * FF_];
    float ffw[BTH_];
};
__device__ Scratch g_scratch;

// ---------- bf16 / fp16 bit helpers ----------
__device__ __forceinline__ uint32_t f2bf(float x) {
    uint32_t u = __float_as_uint(x);
    return (u + 0x7FFFu + ((u >> 16) & 1u)) >> 16;
}
__device__ __forceinline__ float bf2f(uint32_t b) {
    return __uint_as_float(b << 16);
}
__device__ __forceinline__ u16 f2h(float x) {
    u16 h;
    asm("cvt.rn.f16.f32 %0, %1;" : "=h"(h) : "f"(x));
    return h;
}

// ---------- reductions ----------
__device__ __forceinline__ float warpSum(float v) {
#pragma unroll
    for (int o = 16; o > 0; o >>= 1) v += __shfl_xor_sync(0xffffffffu, v, o);
    return v;
}
__device__ __forceinline__ float warpMax(float v) {
#pragma unroll
    for (int o = 16; o > 0; o >>= 1) v = fmaxf(v, __shfl_xor_sync(0xffffffffu, v, o));
    return v;
}
__device__ __forceinline__ float blockSum(float v, float* red) {
    v = warpSum(v);
    int lane = threadIdx.x & 31, w = threadIdx.x >> 5;
    if (lane == 0) red[w] = v;
    __syncthreads();
    int nw = (blockDim.x + 31) >> 5;
    float r = (lane < nw) ? red[lane] : 0.f;
    if (w == 0) {
        r = warpSum(r);
        if (lane == 0) red[0] = r;
    }
    __syncthreads();
    r = red[0];
    __syncthreads();
    return r;
}
__device__ __forceinline__ float blockMax(float v, float* red) {
    v = warpMax(v);
    int lane = threadIdx.x & 31, w = threadIdx.x >> 5;
    if (lane == 0) red[w] = v;
    __syncthreads();
    int nw = (blockDim.x + 31) >> 5;
    float r = (lane < nw) ? red[lane] : -INFINITY;
    if (w == 0) {
        r = warpMax(r);
        if (lane == 0) red[0] = r;
    }
    __syncthreads();
    r = red[0];
    __syncthreads();
    return r;
}

// ===== fused per-token kernels =====

// router(hs0) + AltUp predict + input LN -> pred[4], xnorm
__global__ void fused_pre(const float* __restrict__ hs, const float* __restrict__ rnw,
                          const float* __restrict__ rw, const float* __restrict__ pcw,
                          const float* __restrict__ inw,
                          float* __restrict__ pred, float* __restrict__ xnorm) {
    __shared__ float sx[H_];
    __shared__ float px[H_];
    __shared__ float red[32];
    __shared__ float cf[16];
    size_t off = (size_t)blockIdx.x * H_;
    int tid = threadIdx.x;

    float ls = 0.f;
    for (int i = tid; i < H_; i += blockDim.x) {
        float v = hs[off + i];
        sx[i] = v;
        ls += v;
    }
    float mean = blockSum(ls, red) * (1.f / H_);
    float lv = 0.f;
    for (int i = tid; i < H_; i += blockDim.x) {
        float d = sx[i] - mean;
        lv += d * d;
    }
    float rs = rsqrtf(blockSum(lv, red) * (1.f / H_) + EPS_);

    float a0 = 0.f, a1 = 0.f, a2 = 0.f, a3 = 0.f;
    for (int i = tid; i < H_; i += blockDim.x) {
        float r = (sx[i] - mean) * rs * rnw[i] * (1.f / H_);
        a0 += r * rw[i];
        a1 += r * rw[H_ + i];
        a2 += r * rw[2 * H_ + i];
        a3 += r * rw[3 * H_ + i];
    }
    float t0 = blockSum(a0, red);
    float t1 = blockSum(a1, red);
    float t2 = blockSum(a2, red);
    float t3 = blockSum(a3, red);
    if (tid < 16) {
        float m0 = tanhf(t0), m1 = tanhf(t1), m2 = tanhf(t2), m3 = tanhf(t3);
        cf[tid] = m0 * pcw[tid * 4] + m1 * pcw[tid * 4 + 1]
                + m2 * pcw[tid * 4 + 2] + m3 * pcw[tid * 4 + 3];
    }
    __syncthreads();

    float ps = 0.f;
    for (int i = tid; i < H_; i += blockDim.x) {
        float h0 = sx[i];
        float h1 = hs[BTH_ + off + i];
        float h2 = hs[2 * BTH_ + off + i];
        float h3 = hs[3 * BTH_ + off + i];
        float p0 = h0 + h0 * cf[0] + h1 * cf[1] + h2 * cf[2] + h3 * cf[3];
        pred[off + i] = p0;
        px[i] = p0;
        ps += p0;
        pred[BTH_ + off + i]     = h1 + h0 * cf[4]  + h1 * cf[5]  + h2 * cf[6]  + h3 * cf[7];
        pred[2 * BTH_ + off + i] = h2 + h0 * cf[8]  + h1 * cf[9]  + h2 * cf[10] + h3 * cf[11];
        pred[3 * BTH_ + off + i] = h3 + h0 * cf[12] + h1 * cf[13] + h2 * cf[14] + h3 * cf[15];
    }
    float mean2 = blockSum(ps, red) * (1.f / H_);
    float lv2 = 0.f;
    for (int i = tid; i < H_; i += blockDim.x) {
        float d = px[i] - mean2;
        lv2 += d * d;
    }
    float rs2 = rsqrtf(blockSum(lv2, red) * (1.f / H_) + EPS_);
    for (int i = tid; i < H_; i += blockDim.x) {
        xnorm[off + i] = (px[i] - mean2) * rs2 * inw[i];
    }
}

// post-attn LN (+pred0+laurel, /sqrt2) + pre-ffw LN -> attnlaurel, hn
__global__ void fused_mid(const float* __restrict__ ap, const float* __restrict__ paw,
                          const float* __restrict__ pred, const float* __restrict__ laurel,
                          const float* __restrict__ pfw,
                          float* __restrict__ attnlaurel, float* __restrict__ hn) {
    __shared__ float sx[H_];
    __shared__ float ax[H_];
    __shared__ float red[32];
    size_t off = (size_t)blockIdx.x * H_;
    int tid = threadIdx.x;

    float ls = 0.f;
    for (int i = tid; i < H_; i += blockDim.x) {
        float v = ap[off + i];
        sx[i] = v;
        ls += v;
    }
    float mean = blockSum(ls, red) * (1.f / H_);
    float lv = 0.f;
    for (int i = tid; i < H_; i += blockDim.x) {
        float d = sx[i] - mean;
        lv += d * d;
    }
    float rs = rsqrtf(blockSum(lv, red) * (1.f / H_) + EPS_);

    float ls2 = 0.f;
    for (int i = tid; i < H_; i += blockDim.x) {
        float v = (sx[i] - mean) * rs * paw[i] + pred[off + i] + laurel[off + i];
        v *= 0.7071067811865476f;
        ax[i] = v;
        attnlaurel[off + i] = v;
        ls2 += v;
    }
    float mean2 = blockSum(ls2, red) * (1.f / H_);
    float lv2 = 0.f;
    for (int i = tid; i < H_; i += blockDim.x) {
        float d = ax[i] - mean2;
        lv2 += d * d;
    }
    float rs2 = rsqrtf(blockSum(lv2, red) * (1.f / H_) + EPS_);
    for (int i = tid; i < H_; i += blockDim.x) {
        hn[off + i] = (ax[i] - mean2) * rs2 * pfw[i];
    }
}

// post-ffw LN (+attnlaurel) + router + AltUp correct -> out (act stays in smem)
__global__ void fused_post(const float* __restrict__ ffw, const float* __restrict__ pww,
                           const float* __restrict__ attnlaurel,
                           const float* __restrict__ rnw, const float* __restrict__ rw,
                           const float* __restrict__ ccw, const float* __restrict__ cscale,
                           const float* __restrict__ pred, float* __restrict__ out) {
    __shared__ float sx[H_];
    __shared__ float ax[H_];
    __shared__ float red[32];
    size_t off = (size_t)blockIdx.x * H_;
    int tid = threadIdx.x;

    float ls = 0.f;
    for (int i = tid; i < H_; i += blockDim.x) {
        float v = ffw[off + i];
        sx[i] = v;
        ls += v;
    }
    float mean = blockSum(ls, red) * (1.f / H_);
    float lv = 0.f;
    for (int i = tid; i < H_; i += blockDim.x) {
        float d = sx[i] - mean;
        lv += d * d;
    }
    float rs = rsqrtf(blockSum(lv, red) * (1.f / H_) + EPS_);

    float as = 0.f;
    for (int i = tid; i < H_; i += blockDim.x) {
        float v = (sx[i] - mean) * rs * pww[i] + attnlaurel[off + i];
        ax[i] = v;
        as += v;
    }
    // router on act
    float mean2 = blockSum(as, red) * (1.f / H_);
    float lv2 = 0.f;
    for (int i = tid; i < H_; i += blockDim.x) {
        float d = ax[i] - mean2;
        lv2 += d * d;
    }
    float rs2 = rsqrtf(blockSum(lv2, red) * (1.f / H_) + EPS_);
    float a0 = 0.f, a1 = 0.f, a2 = 0.f, a3 = 0.f;
    for (int i = tid; i < H_; i += blockDim.x) {
        float r = (ax[i] - mean2) * rs2 * rnw[i] * (1.f / H_);
        a0 += r * rw[i];
        a1 += r * rw[H_ + i];
        a2 += r * rw[2 * H_ + i];
        a3 += r * rw[3 * H_ + i];
    }
    float m0 = tanhf(blockSum(a0, red));
    float m1 = tanhf(blockSum(a1, red));
    float m2 = tanhf(blockSum(a2, red));
    float m3 = tanhf(blockSum(a3, red));
    float cc0 = 1.f + m0 * ccw[0]  + m1 * ccw[1]  + m2 * ccw[2]  + m3 * ccw[3];
    float cc1 = 1.f + m0 * ccw[4]  + m1 * ccw[5]  + m2 * ccw[6]  + m3 * ccw[7];
    float cc2 = 1.f + m0 * ccw[8]  + m1 * ccw[9]  + m2 * ccw[10] + m3 * ccw[11];
    float cc3 = 1.f + m0 * ccw[12] + m1 * ccw[13] + m2 * ccw[14] + m3 * ccw[15];

    for (int f = tid; f < H_; f += blockDim.x) {
        float p0 = pred[off + f];
        float inno = ax[f] - p0;
        out[off + f]            = (inno * cc0 + p0) * cscale[f];
        out[BTH_ + off + f]     = inno * cc1 + pred[BTH_ + off + f];
        out[2 * BTH_ + off + f] = inno * cc2 + pred[2 * BTH_ + off + f];
        out[3 * BTH_ + off + f] = inno * cc3 + pred[3 * BTH_ + off + f];
    }
}

// ---------- remaining elementwise ----------
__global__ void ln_kernel(const float* __restrict__ a, const float* __restrict__ w,
                          const float* __restrict__ add1, const float* __restrict__ add2,
                          float scale, float* __restrict__ dst) {
    __shared__ float sx[H_];
    __shared__ float red[32];
    size_t off = (size_t)blockIdx.x * H_;
    int tid = threadIdx.x;
    float ls = 0.f;
    for (int i = tid; i < H_; i += blockDim.x) {
        float v = a[off + i];
        sx[i] = v;
        ls += v;
    }
    float mean = blockSum(ls, red) * (1.f / H_);
    float lv = 0.f;
    for (int i = tid; i < H_; i += blockDim.x) {
        float d = sx[i] - mean;
        lv += d * d;
    }
    float var = blockSum(lv, red) * (1.f / H_);
    float rs = rsqrtf(var + EPS_);
    for (int i = tid; i < H_; i += blockDim.x) {
        float v = (sx[i] - mean) * rs * w[i];
        if (add1) v += add1[off + i];
        if (add2) v += add2[off + i];
        dst[off + i] = v * scale;
    }
}

__global__ void qkvpost_kernel(const float* __restrict__ raw, const float* __restrict__ nw,
                               const float* __restrict__ cosb, const float* __restrict__ sinb,
                               float* __restrict__ out, int nheads, int do_rope, int trans) {
    __shared__ float sx[HD_];
    __shared__ float red[32];
    int idx = blockIdx.x;
    int h = idx % nheads;
    int bt = idx / nheads;
    int t = bt % T_, b = bt / T_;
    int d = threadIdx.x;
    float v = raw[(size_t)bt * nheads * HD_ + h * HD_ + d];
    float mean = blockSum(v, red) * (1.f / HD_);
    float c = v - mean;
    float var = blockSum(c * c, red) * (1.f / HD_);
    float ln = c * rsqrtf(var + EPS_) * (nw ? nw[d] : 1.f);
    sx[d] = ln;
    __syncthreads();
    float o = ln;
    if (do_rope) {
        float cs = cosb[(size_t)bt * HD_ + d];
        float sn = sinb[(size_t)bt * HD_ + d];
        float rot = (d < 128) ? -sx[d + 128] : sx[d - 128];
        o = ln * cs + rot * sn;
    }
    if (trans) {
        out[((size_t)(b * nheads + h) * HD_ + d) * T_ + t] = o;
    } else {
        out[((size_t)(b * nheads + h) * T_ + t) * HD_ + d] = o;
    }
}

__global__ void softmax_kernel(float* __restrict__ scores) {
    __shared__ float sx[T_];
    __shared__ float red[32];
    int q = blockIdx.x % T_;
    size_t off = (size_t)blockIdx.x * T_;
    int tid = threadIdx.x;
    int n = q + 1;
    float lm = -INFINITY;
    for (int i = tid; i < n; i += blockDim.x) {
        float v = scores[off + i];
        sx[i] = v;
        lm = fmaxf(lm, v);
    }
    float gm = blockMax(lm, red);
    float lsum = 0.f;
    for (int i = tid; i < n; i += blockDim.x) {
        float e = __expf(sx[i] - gm);
        sx[i] = e;
        lsum += e;
    }
    float inv = 1.f / blockSum(lsum, red);
    for (int i = tid; i < T_; i += blockDim.x) {
        scores[off + i] = (i < n) ? sx[i] * inv : 0.f;
    }
}

__device__ __forceinline__ float gelu_tanh(float x) {
    return 0.5f * x * (1.f + tanhf(0.7978845608028654f * (x + 0.044715f * x * x * x)));
}

__global__ void gelumul_kernel(float* __restrict__ g, const float* __restrict__ u, int n4) {
    int i = blockIdx.x * blockDim.x + threadIdx.x;
    if (i >= n4) return;
    float4 a = reinterpret_cast<float4*>(g)[i];
    float4 b = reinterpret_cast<const float4*>(u)[i];
    a.x = gelu_tanh(a.x) * b.x;
    a.y = gelu_tanh(a.y) * b.y;
    a.z = gelu_tanh(a.z) * b.z;
    a.w = gelu_tanh(a.w) * b.w;
    reinterpret_cast<float4*>(g)[i] = a;
}

// ===== shared MMA plumbing =====
__device__ __forceinline__ void ldsm4(uint32_t* r, uint32_t addr) {
    asm volatile("ldmatrix.sync.aligned.m8n8.x4.shared.b16 {%0,%1,%2,%3}, [%4];"
                 : "=r"(r[0]), "=r"(r[1]), "=r"(r[2]), "=r"(r[3]) : "r"(addr));
}
__device__ __forceinline__ void mma_bf(float* d, const uint32_t* a, uint32_t b0, uint32_t b1) {
    asm volatile("mma.sync.aligned.m16n8k16.row.col.f32.bf16.bf16.f32 "
                 "{%0,%1,%2,%3}, {%4,%5,%6,%7}, {%8,%9}, {%0,%1,%2,%3};"
                 : "+f"(d[0]), "+f"(d[1]), "+f"(d[2]), "+f"(d[3])
                 : "r"(a[0]), "r"(a[1]), "r"(a[2]), "r"(a[3]), "r"(b0), "r"(b1));
}
__device__ __forceinline__ void mma_fp(float* d, const uint32_t* a, uint32_t b0, uint32_t b1) {
    asm volatile("mma.sync.aligned.m16n8k16.row.col.f32.f16.f16.f32 "
                 "{%0,%1,%2,%3}, {%4,%5,%6,%7}, {%8,%9}, {%0,%1,%2,%3};"
                 : "+f"(d[0]), "+f"(d[1]), "+f"(d[2]), "+f"(d[3])
                 : "r"(a[0]), "r"(a[1]), "r"(a[2]), "r"(a[3]), "r"(b0), "r"(b1));
}
__device__ __forceinline__ void splitStoreBF(float4 v, uint32_t* hi, uint32_t* lo) {
    uint32_t hx = f2bf(v.x), hy = f2bf(v.y), hz = f2bf(v.z), hw = f2bf(v.w);
    uint32_t lx = f2bf(v.x - bf2f(hx));
    uint32_t ly = f2bf(v.y - bf2f(hy));
    uint32_t lz = f2bf(v.z - bf2f(hz));
    uint32_t lw = f2bf(v.w - bf2f(hw));
    hi[0] = hx | (hy << 16);
    hi[1] = hz | (hw << 16);
    lo[0] = lx | (ly << 16);
    lo[1] = lz | (lw << 16);
}
__device__ __forceinline__ void convStoreH(float4 v, uint32_t* hi) {
    u16 hx = f2h(v.x), hy = f2h(v.y), hz = f2h(v.z), hw = f2h(v.w);
    hi[0] = (uint32_t)hx | ((uint32_t)hy << 16);
    hi[1] = (uint32_t)hz | ((uint32_t)hw << 16);
}

constexpr int MBM = 128, MBN = 128, MBK = 32;
constexpr int MLDW = 20;

// ===== 3-pass bf16 core — q/k projections + scores =====
struct MSmem3 {
    uint32_t Ah[MBM][MLDW];
    uint32_t Al[MBM][MLDW];
    uint32_t Bh[MBN][MLDW];
    uint32_t Bl[MBN][MLDW];
};

__device__ __forceinline__ void mma_core3(
    const float* __restrict__ A, const float* __restrict__ B, float* __restrict__ C,
    int K, int lda, int ldb, int ldc, int bm, int bn, MSmem3& s)
{
    const int tid = threadIdx.x;
    const int lane = tid & 31, wid = tid >> 5;
    const int wm = wid & 3, wn = wid >> 2;

    float acc[2][8][4];
#pragma unroll
    for (int i = 0; i < 2; i++)
#pragma unroll
        for (int j = 0; j < 8; j++)
#pragma unroll
            for (int e = 0; e < 4; e++) acc[i][j][e] = 0.f;

    const int lr = tid >> 3;
    const int lc = (tid & 7) * 4;
    const int wc = (tid & 7) * 2;

    const uint32_t sb = (uint32_t)__cvta_generic_to_shared(&s);
    const uint32_t offAl = MBM * MLDW * 4;
    const uint32_t offBh = 2 * MBM * MLDW * 4;
    const uint32_t offBl = 3 * MBM * MLDW * 4;
    const int arow = wm * 32 + (lane & 15);
    const int acol = (lane >> 4) * 8;
    const int brow = wn * 64 + (lane & 7) + ((lane >> 4) << 3);
    const int bcol = ((lane >> 3) & 1) << 3;

    for (int k0 = 0; k0 < K; k0 += MBK) {
#pragma unroll
        for (int p = 0; p < 4; p++) {
            int r = lr + p * 32;
            float4 av = *reinterpret_cast<const float4*>(&A[(size_t)(bm + r) * lda + k0 + lc]);
            splitStoreBF(av, &s.Ah[r][wc], &s.Al[r][wc]);
            float4 bv = *reinterpret_cast<const float4*>(&B[(size_t)(bn + r) * ldb + k0 + lc]);
            splitStoreBF(bv, &s.Bh[r][wc], &s.Bl[r][wc]);
        }
        __syncthreads();

#pragma unroll
        for (int kk = 0; kk < 2; kk++) {
            uint32_t ah[2][4], al[2][4], bh[4][4], bl[4][4];
#pragma unroll
            for (int mf = 0; mf < 2; mf++) {
                uint32_t ao = (uint32_t)(((arow + mf * 16) * MLDW * 4) + (kk * 16 + acol) * 2);
                ldsm4(ah[mf], sb + ao);
                ldsm4(al[mf], sb + offAl + ao);
            }
#pragma unroll
            for (int np = 0; np < 4; np++) {
                uint32_t bo = (uint32_t)(((brow + np * 16) * MLDW * 4) + (kk * 16 + bcol) * 2);
                ldsm4(bh[np], sb + offBh + bo);
                ldsm4(bl[np], sb + offBl + bo);
            }
#pragma unroll
            for (int mf = 0; mf < 2; mf++) {
#pragma unroll
                for (int nf = 0; nf < 8; nf++) {
                    int np = nf >> 1;
                    int hf = (nf & 1) * 2;
                    mma_bf(acc[mf][nf], ah[mf], bh[np][hf], bh[np][hf + 1]);
                    mma_bf(acc[mf][nf], al[mf], bh[np][hf], bh[np][hf + 1]);
                    mma_bf(acc[mf][nf], ah[mf], bl[np][hf], bl[np][hf + 1]);
                }
            }
        }
        __syncthreads();
    }

#pragma unroll
    for (int mf = 0; mf < 2; mf++) {
        int row = bm + wm * 32 + mf * 16 + (lane >> 2);
#pragma unroll
        for (int nf = 0; nf < 8; nf++) {
            int col = bn + wn * 64 + nf * 8 + (lane & 3) * 2;
            *reinterpret_cast<float2*>(&C[(size_t)row * ldc + col]) =
                make_float2(acc[mf][nf][0], acc[mf][nf][1]);
            *reinterpret_cast<float2*>(&C[(size_t)(row + 8) * ldc + col]) =
                make_float2(acc[mf][nf][2], acc[mf][nf][3]);
        }
    }
}

__global__ void __launch_bounds__(256, 2)
mma_nt3(const float* __restrict__ A, const float* __restrict__ B, float* __restrict__ C,
        int K, int lda, int ldb, int ldc) {
    __shared__ MSmem3 s;
    mma_core3(A, B, C, K, lda, ldb, ldc, blockIdx.x * MBM, blockIdx.y * MBN, s);
}

__global__ void __launch_bounds__(256, 2)
mma_scores(const float* __restrict__ q, const float* __restrict__ k, float* __restrict__ sc) {
    if (blockIdx.y > blockIdx.x) return;
    int z = blockIdx.z;
    int b = z >> 3, h = z & 7;
    const float* A = q + (size_t)z * T_ * HD_;
    const float* B = k + (size_t)(b * NKV_ + (h >> 2)) * T_ * HD_;
    float* C = sc + (size_t)z * T_ * T_;
    __shared__ MSmem3 s;
    mma_core3(A, B, C, HD_, HD_, HD_, T_, blockIdx.x * MBM, blockIdx.y * MBN, s);
}

// ===== 1-pass fp16 core =====
struct MSmem1 {
    uint32_t Ah[MBM][MLDW];
    uint32_t Bh[MBN][MLDW];
};

__device__ __forceinline__ void mma_core1(
    const float* __restrict__ A, const float* __restrict__ B, float* __restrict__ C,
    int K, int lda, int ldb, int ldc, int bm, int bn, MSmem1& s)
{
    const int tid = threadIdx.x;
    const int lane = tid & 31, wid = tid >> 5;
    const int wm = wid & 3, wn = wid >> 2;

    float acc[2][8][4];
#pragma unroll
    for (int i = 0; i < 2; i++)
#pragma unroll
        for (int j = 0; j < 8; j++)
#pragma unroll
            for (int e = 0; e < 4; e++) acc[i][j][e] = 0.f;

    const int lr = tid >> 3;
    const int lc = (tid & 7) * 4;
    const int wc = (tid & 7) * 2;

    const uint32_t sb = (uint32_t)__cvta_generic_to_shared(&s);
    const uint32_t offBh = MBM * MLDW * 4;
    const int arow = wm * 32 + (lane & 15);
    const int acol = (lane >> 4) * 8;
    const int brow = wn * 64 + (lane & 7) + ((lane >> 4) << 3);
    const int bcol = ((lane >> 3) & 1) << 3;

    for (int k0 = 0; k0 < K; k0 += MBK) {
#pragma unroll
        for (int p = 0; p < 4; p++) {
            int r = lr + p * 32;
            float4 av = *reinterpret_cast<const float4*>(&A[(size_t)(bm + r) * lda + k0 + lc]);
            convStoreH(av, &s.Ah[r][wc]);
            float4 bv = *reinterpret_cast<const float4*>(&B[(size_t)(bn + r) * ldb + k0 + lc]);
            convStoreH(bv, &s.Bh[r][wc]);
        }
        __syncthreads();

#pragma unroll
        for (int kk = 0; kk < 2; kk++) {
            uint32_t ah[2][4], bh[4][4];
#pragma unroll
            for (int mf = 0; mf < 2; mf++) {
                uint32_t ao = (uint32_t)(((arow + mf * 16) * MLDW * 4) + (kk * 16 + acol) * 2);
                ldsm4(ah[mf], sb + ao);
            }
#pragma unroll
            for (int np = 0; np < 4; np++) {
                uint32_t bo = (uint32_t)(((brow + np * 16) * MLDW * 4) + (kk * 16 + bcol) * 2);
                ldsm4(bh[np], sb + offBh + bo);
            }
#pragma unroll
            for (int mf = 0; mf < 2; mf++) {
#pragma unroll
                for (int nf = 0; nf < 8; nf++) {
                    int np = nf >> 1;
                    int hf = (nf & 1) * 2;
                    mma_fp(acc[mf][nf], ah[mf], bh[np][hf], bh[np][hf + 1]);
                }
            }
        }
        __syncthreads();
    }

#pragma unroll
    for (int mf = 0; mf < 2; mf++) {
        int row = bm + wm * 32 + mf * 16 + (lane >> 2);
#pragma unroll
        for (int nf = 0; nf < 8; nf++) {
            int col = bn + wn * 64 + nf * 8 + (lane & 3) * 2;
            *reinterpret_cast<float2*>(&C[(size_t)row * ldc + col]) =
                make_float2(acc[mf][nf][0], acc[mf][nf][1]);
            *reinterpret_cast<float2*>(&C[(size_t)(row + 8) * ldc + col]) =
                make_float2(acc[mf][nf][2], acc[mf][nf][3]);
        }
    }
}

__global__ void __launch_bounds__(256, 2)
mma_nt1(const float* __restrict__ A, const float* __restrict__ B, float* __restrict__ C,
        int K, int lda, int ldb, int ldc) {
    __shared__ MSmem1 s;
    mma_core1(A, B, C, K, lda, ldb, ldc, blockIdx.x * MBM, blockIdx.y * MBN, s);
}

__global__ void __launch_bounds__(256, 2)
mma_attnv(const float* __restrict__ p, const float* __restrict__ vT, float* __restrict__ o) {
    int z = blockIdx.z;
    int b = z >> 3, h = z & 7;
    const float* A = p + (size_t)z * T_ * T_;
    const float* B = vT + (size_t)(b * NKV_ + (h >> 2)) * HD_ * T_;
    float* C = o + (size_t)b * T_ * H_ + (size_t)h * HD_;
    int bm = blockIdx.x * MBM;
    __shared__ MSmem1 s;
    mma_core1(A, B, C, bm + MBM, T_, T_, H_, bm, blockIdx.y * MBN, s);
}

// laurel1: split-K x8
__global__ void __launch_bounds__(256)
laurel1_kernel(const float* __restrict__ A, const float* __restrict__ B, float* __restrict__ P) {
    __shared__ float Bs[64][65];
    __shared__ float As[32][65];
    int tid = threadIdx.x;
    int bm = blockIdx.x * 32;
    int ks = blockIdx.y;
    int kbeg = ks * (H_ / 8), kend = kbeg + H_ / 8;
    float acc0[4] = {0.f, 0.f, 0.f, 0.f};
    float acc1[4] = {0.f, 0.f, 0.f, 0.f};
    int tn = tid & 15;
    int tr = tid >> 4;
    for (int k0 = kbeg; k0 < kend; k0 += 64) {
        for (int i = tid; i < 64 * 64; i += 256) {
            int n = i >> 6, kk = i & 63;
            Bs[n][kk] = B[(size_t)n * H_ + k0 + kk];
        }
        for (int i = tid; i < 32 * 64; i += 256) {
            int r = i >> 6, kk = i & 63;
            As[r][kk] = A[(size_t)(bm + r) * H_ + k0 + kk];
        }
        __syncthreads();
#pragma unroll 8
        for (int kk = 0; kk < 64; kk++) {
            float a0 = As[tr][kk], a1 = As[tr + 16][kk];
#pragma unroll
            for (int j = 0; j < 4; j++) {
                float bv = Bs[tn * 4 + j][kk];
                acc0[j] = fmaf(a0, bv, acc0[j]);
                acc1[j] = fmaf(a1, bv, acc1[j]);
            }
        }
        __syncthreads();
    }
#pragma unroll
    for (int j = 0; j < 4; j++) {
        P[((size_t)ks * BT_ + bm + tr) * LR_ + tn * 4 + j] = acc0[j];
        P[((size_t)ks * BT_ + bm + tr + 16) * LR_ + tn * 4 + j] = acc1[j];
    }
}

__global__ void laurel1_reduce(const float* __restrict__ P, float* __restrict__ out) {
    int i = blockIdx.x * blockDim.x + threadIdx.x;
    if (i >= BT_ * LR_) return;
    float s = 0.f;
#pragma unroll
    for (int k = 0; k < 8; k++) s += P[(size_t)k * BT_ * LR_ + i];
    out[i] = s;
}

extern "C" void kernel_launch(void* const* d_in, const int* in_sizes, int n_in,
                              void* d_out, int out_size) {
    const float* hs    = (const float*)d_in[0];
    const float* cosb  = (const float*)d_in[1];
    const float* sinb  = (const float*)d_in[2];
    const float* wq    = (const float*)d_in[3];
    const float* wk    = (const float*)d_in[4];
    const float* wv    = (const float*)d_in[5];
    const float* wo    = (const float*)d_in[6];
    const float* qnw   = (const float*)d_in[7];
    const float* knw   = (const float*)d_in[8];
    const float* in_ln = (const float*)d_in[9];
    const float* pa_ln = (const float*)d_in[10];
    const float* pf_ln = (const float*)d_in[11];
    const float* pw_ln = (const float*)d_in[12];
    const float* gatew = (const float*)d_in[13];
    const float* upw   = (const float*)d_in[14];
    const float* downw = (const float*)d_in[15];
    const float* llw   = (const float*)d_in[16];
    const float* lrw   = (const float*)d_in[17];
    const float* lnw   = (const float*)d_in[18];
    const float* rnw   = (const float*)d_in[19];
    const float* rw    = (const float*)d_in[20];
    const float* pcw   = (const float*)d_in[21];
    const float* ccw   = (const float*)d_in[22];
    const float* cscal = (const float*)d_in[23];
    float* out = (float*)d_out;

    Scratch* S = 0;
    cudaGetSymbolAddress((void**)&S, g_scratch);

    // fused: router + AltUp predict + input LN
    fused_pre<<<BT_, 256>>>(hs, rnw, rw, pcw, in_ln, S->pred, S->xnorm);

    laurel1_kernel<<<dim3(BT_ / 32, 8), 256>>>(S->xnorm, llw, S->lrpart);
    laurel1_reduce<<<(BT_ * LR_ + 255) / 256, 256>>>(S->lrpart, S->lrbuf);
    mma_nt1<<<dim3(16, 16), 256>>>(S->lrbuf, lrw, S->laurel, LR_, LR_, LR_, H_);
    ln_kernel<<<BT_, 256>>>(S->laurel, lnw, S->xnorm, (const float*)0, 1.f, S->laurel);

    // q,k: 3-pass bf16 (softmax-feeding); v: 1-pass fp16
    mma_nt3<<<dim3(16, 16), 256>>>(S->xnorm, wq, S->qraw, H_, H_, H_, NH_ * HD_);
    mma_nt3<<<dim3(16, 4), 256>>>(S->xnorm, wk, S->kraw, H_, H_, H_, NKV_ * HD_);
    mma_nt1<<<dim3(16, 4), 256>>>(S->xnorm, wv, S->vraw, H_, H_, H_, NKV_ * HD_);
    qkvpost_kernel<<<BT_ * NH_, 256>>>(S->qraw, qnw, cosb, sinb, S->q, NH_, 1, 0);
    qkvpost_kernel<<<BT_ * NKV_, 256>>>(S->kraw, knw, cosb, sinb, S->k, NKV_, 1, 0);
    qkvpost_kernel<<<BT_ * NKV_, 256>>>(S->vraw, (const float*)0, cosb, sinb, S->vT, NKV_, 0, 1);

    mma_scores<<<dim3(8, 8, B_ * NH_), 256>>>(S->q, S->k, S->scores);
    softmax_kernel<<<B_ * NH_ * T_, 256>>>(S->scores);
    mma_attnv<<<dim3(8, 2, B_ * NH_), 256>>>(S->scores, S->vT, S->attnout);
    mma_nt1<<<dim3(16, 16), 256>>>(S->attnout, wo, S->attnproj,
                                   NH_ * HD_, NH_ * HD_, NH_ * HD_, H_);

    // fused: post-attn LN + residuals + pre-ffw LN
    fused_mid<<<BT_, 256>>>(S->attnproj, pa_ln, S->pred, S->laurel, pf_ln,
                            S->attnlaurel, S->hn);

    mma_nt1<<<dim3(16, 64), 256>>>(S->hn, gatew, S->gate, H_, H_, H_, FF_);
    mma_nt1<<<dim3(16, 64), 256>>>(S->hn, upw, S->up, H_, H_, H_, FF_);

    int n4 = (int)(((size_t)BT_ * FF_) / 4);
    gelumul_kernel<<<(n4 + 255) / 256, 256>>>(S->gate, S->up, n4);

    mma_nt1<<<dim3(16, 16), 256>>>(S->gate, downw, S->ffw, FF_, FF_, FF_, H_);

    // fused: post-ffw LN + router + AltUp correct -> out
    fused_post<<<BT_, 256>>>(S->ffw, pw_ln, S->attnlaurel, rnw, rw, ccw, cscal,
                             S->pred, out);

    (void)in_sizes; (void)n_in; (void)out_size;
}

// round 11
// speedup vs baseline: 1.9252x; 1.1296x over previous
#include <cuda_runtime.h>
#include <cstdint>
#include <cstddef>
#include <math.h>

typedef unsigned short u16;

constexpr int B_ = 2, T_ = 1024, H_ = 2048, NH_ = 8, NKV_ = 2, HD_ = 256;
constexpr int FF_ = 8192, LR_ = 64;
constexpr int BT_ = B_ * T_;
constexpr size_t BTH_ = (size_t)BT_ * H_;
constexpr float EPS_ = 1e-6f;

struct Scratch {
    float pred[4 * BTH_];
    float xnorm[BTH_];
    float lrpart[8 * BT_ * LR_];
    float lrbuf[BT_ * LR_];
    float laurel[BTH_];
    float qraw[BTH_];
    float kraw[(size_t)BT_ * NKV_ * HD_];
    float vraw[(size_t)BT_ * NKV_ * HD_];
    float q[BTH_];
    float k[(size_t)BT_ * NKV_ * HD_];
    float vT[(size_t)BT_ * NKV_ * HD_];
    float scores[(size_t)B_ * NH_ * T_ * T_];
    float attnout[BTH_];
    float attnproj[BTH_];
    float attnlaurel[BTH_];
    float hn[BTH_];
    float gate[(size_t)BT_ * FF_];
    float up[(size_t)BT_ * FF_];
    float ffw[BTH_];
};
__device__ Scratch g_scratch;

// ---------- bf16 / fp16 bit helpers ----------
__device__ __forceinline__ uint32_t f2bf(float x) {
    uint32_t u = __float_as_uint(x);
    return (u + 0x7FFFu + ((u >> 16) & 1u)) >> 16;
}
__device__ __forceinline__ float bf2f(uint32_t b) {
    return __uint_as_float(b << 16);
}
__device__ __forceinline__ u16 f2h(float x) {
    u16 h;
    asm("cvt.rn.f16.f32 %0, %1;" : "=h"(h) : "f"(x));
    return h;
}

// ---------- reductions ----------
__device__ __forceinline__ float warpSum(float v) {
#pragma unroll
    for (int o = 16; o > 0; o >>= 1) v += __shfl_xor_sync(0xffffffffu, v, o);
    return v;
}
__device__ __forceinline__ float warpMax(float v) {
#pragma unroll
    for (int o = 16; o > 0; o >>= 1) v = fmaxf(v, __shfl_xor_sync(0xffffffffu, v, o));
    return v;
}
__device__ __forceinline__ float blockSum(float v, float* red) {
    v = warpSum(v);
    int lane = threadIdx.x & 31, w = threadIdx.x >> 5;
    if (lane == 0) red[w] = v;
    __syncthreads();
    int nw = (blockDim.x + 31) >> 5;
    float r = (lane < nw) ? red[lane] : 0.f;
    if (w == 0) {
        r = warpSum(r);
        if (lane == 0) red[0] = r;
    }
    __syncthreads();
    r = red[0];
    __syncthreads();
    return r;
}
__device__ __forceinline__ float blockMax(float v, float* red) {
    v = warpMax(v);
    int lane = threadIdx.x & 31, w = threadIdx.x >> 5;
    if (lane == 0) red[w] = v;
    __syncthreads();
    int nw = (blockDim.x + 31) >> 5;
    float r = (lane < nw) ? red[lane] : -INFINITY;
    if (w == 0) {
        r = warpMax(r);
        if (lane == 0) red[0] = r;
    }
    __syncthreads();
    r = red[0];
    __syncthreads();
    return r;
}

// ===== fused per-token kernels =====
__global__ void fused_pre(const float* __restrict__ hs, const float* __restrict__ rnw,
                          const float* __restrict__ rw, const float* __restrict__ pcw,
                          const float* __restrict__ inw,
                          float* __restrict__ pred, float* __restrict__ xnorm) {
    __shared__ float sx[H_];
    __shared__ float px[H_];
    __shared__ float red[32];
    __shared__ float cf[16];
    size_t off = (size_t)blockIdx.x * H_;
    int tid = threadIdx.x;

    float ls = 0.f;
    for (int i = tid; i < H_; i += blockDim.x) {
        float v = hs[off + i];
        sx[i] = v;
        ls += v;
    }
    float mean = blockSum(ls, red) * (1.f / H_);
    float lv = 0.f;
    for (int i = tid; i < H_; i += blockDim.x) {
        float d = sx[i] - mean;
        lv += d * d;
    }
    float rs = rsqrtf(blockSum(lv, red) * (1.f / H_) + EPS_);

    float a0 = 0.f, a1 = 0.f, a2 = 0.f, a3 = 0.f;
    for (int i = tid; i < H_; i += blockDim.x) {
        float r = (sx[i] - mean) * rs * rnw[i] * (1.f / H_);
        a0 += r * rw[i];
        a1 += r * rw[H_ + i];
        a2 += r * rw[2 * H_ + i];
        a3 += r * rw[3 * H_ + i];
    }
    float t0 = blockSum(a0, red);
    float t1 = blockSum(a1, red);
    float t2 = blockSum(a2, red);
    float t3 = blockSum(a3, red);
    if (tid < 16) {
        float m0 = tanhf(t0), m1 = tanhf(t1), m2 = tanhf(t2), m3 = tanhf(t3);
        cf[tid] = m0 * pcw[tid * 4] + m1 * pcw[tid * 4 + 1]
                + m2 * pcw[tid * 4 + 2] + m3 * pcw[tid * 4 + 3];
    }
    __syncthreads();

    float ps = 0.f;
    for (int i = tid; i < H_; i += blockDim.x) {
        float h0 = sx[i];
        float h1 = hs[BTH_ + off + i];
        float h2 = hs[2 * BTH_ + off + i];
        float h3 = hs[3 * BTH_ + off + i];
        float p0 = h0 + h0 * cf[0] + h1 * cf[1] + h2 * cf[2] + h3 * cf[3];
        pred[off + i] = p0;
        px[i] = p0;
        ps += p0;
        pred[BTH_ + off + i]     = h1 + h0 * cf[4]  + h1 * cf[5]  + h2 * cf[6]  + h3 * cf[7];
        pred[2 * BTH_ + off + i] = h2 + h0 * cf[8]  + h1 * cf[9]  + h2 * cf[10] + h3 * cf[11];
        pred[3 * BTH_ + off + i] = h3 + h0 * cf[12] + h1 * cf[13] + h2 * cf[14] + h3 * cf[15];
    }
    float mean2 = blockSum(ps, red) * (1.f / H_);
    float lv2 = 0.f;
    for (int i = tid; i < H_; i += blockDim.x) {
        float d = px[i] - mean2;
        lv2 += d * d;
    }
    float rs2 = rsqrtf(blockSum(lv2, red) * (1.f / H_) + EPS_);
    for (int i = tid; i < H_; i += blockDim.x) {
        xnorm[off + i] = (px[i] - mean2) * rs2 * inw[i];
    }
}

__global__ void fused_mid(const float* __restrict__ ap, const float* __restrict__ paw,
                          const float* __restrict__ pred, const float* __restrict__ laurel,
                          const float* __restrict__ pfw,
                          float* __restrict__ attnlaurel, float* __restrict__ hn) {
    __shared__ float sx[H_];
    __shared__ float ax[H_];
    __shared__ float red[32];
    size_t off = (size_t)blockIdx.x * H_;
    int tid = threadIdx.x;

    float ls = 0.f;
    for (int i = tid; i < H_; i += blockDim.x) {
        float v = ap[off + i];
        sx[i] = v;
        ls += v;
    }
    float mean = blockSum(ls, red) * (1.f / H_);
    float lv = 0.f;
    for (int i = tid; i < H_; i += blockDim.x) {
        float d = sx[i] - mean;
        lv += d * d;
    }
    float rs = rsqrtf(blockSum(lv, red) * (1.f / H_) + EPS_);

    float ls2 = 0.f;
    for (int i = tid; i < H_; i += blockDim.x) {
        float v = (sx[i] - mean) * rs * paw[i] + pred[off + i] + laurel[off + i];
        v *= 0.7071067811865476f;
        ax[i] = v;
        attnlaurel[off + i] = v;
        ls2 += v;
    }
    float mean2 = blockSum(ls2, red) * (1.f / H_);
    float lv2 = 0.f;
    for (int i = tid; i < H_; i += blockDim.x) {
        float d = ax[i] - mean2;
        lv2 += d * d;
    }
    float rs2 = rsqrtf(blockSum(lv2, red) * (1.f / H_) + EPS_);
    for (int i = tid; i < H_; i += blockDim.x) {
        hn[off + i] = (ax[i] - mean2) * rs2 * pfw[i];
    }
}

__global__ void fused_post(const float* __restrict__ ffw, const float* __restrict__ pww,
                           const float* __restrict__ attnlaurel,
                           const float* __restrict__ rnw, const float* __restrict__ rw,
                           const float* __restrict__ ccw, const float* __restrict__ cscale,
                           const float* __restrict__ pred, float* __restrict__ out) {
    __shared__ float sx[H_];
    __shared__ float ax[H_];
    __shared__ float red[32];
    size_t off = (size_t)blockIdx.x * H_;
    int tid = threadIdx.x;

    float ls = 0.f;
    for (int i = tid; i < H_; i += blockDim.x) {
        float v = ffw[off + i];
        sx[i] = v;
        ls += v;
    }
    float mean = blockSum(ls, red) * (1.f / H_);
    float lv = 0.f;
    for (int i = tid; i < H_; i += blockDim.x) {
        float d = sx[i] - mean;
        lv += d * d;
    }
    float rs = rsqrtf(blockSum(lv, red) * (1.f / H_) + EPS_);

    float as = 0.f;
    for (int i = tid; i < H_; i += blockDim.x) {
        float v = (sx[i] - mean) * rs * pww[i] + attnlaurel[off + i];
        ax[i] = v;
        as += v;
    }
    float mean2 = blockSum(as, red) * (1.f / H_);
    float lv2 = 0.f;
    for (int i = tid; i < H_; i += blockDim.x) {
        float d = ax[i] - mean2;
        lv2 += d * d;
    }
    float rs2 = rsqrtf(blockSum(lv2, red) * (1.f / H_) + EPS_);
    float a0 = 0.f, a1 = 0.f, a2 = 0.f, a3 = 0.f;
    for (int i = tid; i < H_; i += blockDim.x) {
        float r = (ax[i] - mean2) * rs2 * rnw[i] * (1.f / H_);
        a0 += r * rw[i];
        a1 += r * rw[H_ + i];
        a2 += r * rw[2 * H_ + i];
        a3 += r * rw[3 * H_ + i];
    }
    float m0 = tanhf(blockSum(a0, red));
    float m1 = tanhf(blockSum(a1, red));
    float m2 = tanhf(blockSum(a2, red));
    float m3 = tanhf(blockSum(a3, red));
    float cc0 = 1.f + m0 * ccw[0]  + m1 * ccw[1]  + m2 * ccw[2]  + m3 * ccw[3];
    float cc1 = 1.f + m0 * ccw[4]  + m1 * ccw[5]  + m2 * ccw[6]  + m3 * ccw[7];
    float cc2 = 1.f + m0 * ccw[8]  + m1 * ccw[9]  + m2 * ccw[10] + m3 * ccw[11];
    float cc3 = 1.f + m0 * ccw[12] + m1 * ccw[13] + m2 * ccw[14] + m3 * ccw[15];

    for (int f = tid; f < H_; f += blockDim.x) {
        float p0 = pred[off + f];
        float inno = ax[f] - p0;
        out[off + f]            = (inno * cc0 + p0) * cscale[f];
        out[BTH_ + off + f]     = inno * cc1 + pred[BTH_ + off + f];
        out[2 * BTH_ + off + f] = inno * cc2 + pred[2 * BTH_ + off + f];
        out[3 * BTH_ + off + f] = inno * cc3 + pred[3 * BTH_ + off + f];
    }
}

// ---------- remaining elementwise ----------
__global__ void ln_kernel(const float* __restrict__ a, const float* __restrict__ w,
                          const float* __restrict__ add1, const float* __restrict__ add2,
                          float scale, float* __restrict__ dst) {
    __shared__ float sx[H_];
    __shared__ float red[32];
    size_t off = (size_t)blockIdx.x * H_;
    int tid = threadIdx.x;
    float ls = 0.f;
    for (int i = tid; i < H_; i += blockDim.x) {
        float v = a[off + i];
        sx[i] = v;
        ls += v;
    }
    float mean = blockSum(ls, red) * (1.f / H_);
    float lv = 0.f;
    for (int i = tid; i < H_; i += blockDim.x) {
        float d = sx[i] - mean;
        lv += d * d;
    }
    float var = blockSum(lv, red) * (1.f / H_);
    float rs = rsqrtf(var + EPS_);
    for (int i = tid; i < H_; i += blockDim.x) {
        float v = (sx[i] - mean) * rs * w[i];
        if (add1) v += add1[off + i];
        if (add2) v += add2[off + i];
        dst[off + i] = v * scale;
    }
}

// common per-head LN(+rope) body
__device__ __forceinline__ void qkvpost_body(
    const float* __restrict__ raw, const float* __restrict__ nw,
    const float* __restrict__ cosb, const float* __restrict__ sinb,
    float* __restrict__ out, int nheads, int do_rope, int trans, int idx) {
    __shared__ float sx[HD_];
    __shared__ float red[32];
    int h = idx % nheads;
    int bt = idx / nheads;
    int t = bt % T_, b = bt / T_;
    int d = threadIdx.x;
    float v = raw[(size_t)bt * nheads * HD_ + h * HD_ + d];
    float mean = blockSum(v, red) * (1.f / HD_);
    float c = v - mean;
    float var = blockSum(c * c, red) * (1.f / HD_);
    float ln = c * rsqrtf(var + EPS_) * (nw ? nw[d] : 1.f);
    sx[d] = ln;
    __syncthreads();
    float o = ln;
    if (do_rope) {
        float cs = cosb[(size_t)bt * HD_ + d];
        float sn = sinb[(size_t)bt * HD_ + d];
        float rot = (d < 128) ? -sx[d + 128] : sx[d - 128];
        o = ln * cs + rot * sn;
    }
    if (trans) {
        out[((size_t)(b * nheads + h) * HD_ + d) * T_ + t] = o;
    } else {
        out[((size_t)(b * nheads + h) * T_ + t) * HD_ + d] = o;
    }
}

__global__ void qkvpost_kernel(const float* __restrict__ raw, const float* __restrict__ nw,
                               const float* __restrict__ cosb, const float* __restrict__ sinb,
                               float* __restrict__ out, int nheads, int do_rope, int trans) {
    qkvpost_body(raw, nw, cosb, sinb, out, nheads, do_rope, trans, blockIdx.x);
}

// combined q+k post (q: BT_*NH_ blocks, then k: BT_*NKV_)
__global__ void qkvpost_qk(const float* __restrict__ qraw, const float* __restrict__ kraw,
                           const float* __restrict__ qnw, const float* __restrict__ knw,
                           const float* __restrict__ cosb, const float* __restrict__ sinb,
                           float* __restrict__ q, float* __restrict__ k) {
    int idx = blockIdx.x;
    if (idx < BT_ * NH_) {
        qkvpost_body(qraw, qnw, cosb, sinb, q, NH_, 1, 0, idx);
    } else {
        qkvpost_body(kraw, knw, cosb, sinb, k, NKV_, 1, 0, idx - BT_ * NH_);
    }
}

__global__ void softmax_kernel(float* __restrict__ scores) {
    __shared__ float sx[T_];
    __shared__ float red[32];
    int q = blockIdx.x % T_;
    size_t off = (size_t)blockIdx.x * T_;
    int tid = threadIdx.x;
    int n = q + 1;
    float lm = -INFINITY;
    for (int i = tid; i < n; i += blockDim.x) {
        float v = scores[off + i];
        sx[i] = v;
        lm = fmaxf(lm, v);
    }
    float gm = blockMax(lm, red);
    float lsum = 0.f;
    for (int i = tid; i < n; i += blockDim.x) {
        float e = __expf(sx[i] - gm);
        sx[i] = e;
        lsum += e;
    }
    float inv = 1.f / blockSum(lsum, red);
    for (int i = tid; i < T_; i += blockDim.x) {
        scores[off + i] = (i < n) ? sx[i] * inv : 0.f;
    }
}

__device__ __forceinline__ float gelu_tanh(float x) {
    return 0.5f * x * (1.f + tanhf(0.7978845608028654f * (x + 0.044715f * x * x * x)));
}

__global__ void gelumul_kernel(float* __restrict__ g, const float* __restrict__ u, int n4) {
    int i = blockIdx.x * blockDim.x + threadIdx.x;
    if (i >= n4) return;
    float4 a = reinterpret_cast<float4*>(g)[i];
    float4 b = reinterpret_cast<const float4*>(u)[i];
    a.x = gelu_tanh(a.x) * b.x;
    a.y = gelu_tanh(a.y) * b.y;
    a.z = gelu_tanh(a.z) * b.z;
    a.w = gelu_tanh(a.w) * b.w;
    reinterpret_cast<float4*>(g)[i] = a;
}

// ===== shared MMA plumbing =====
__device__ __forceinline__ void ldsm4(uint32_t* r, uint32_t addr) {
    asm volatile("ldmatrix.sync.aligned.m8n8.x4.shared.b16 {%0,%1,%2,%3}, [%4];"
                 : "=r"(r[0]), "=r"(r[1]), "=r"(r[2]), "=r"(r[3]) : "r"(addr));
}
__device__ __forceinline__ void mma_bf(float* d, const uint32_t* a, uint32_t b0, uint32_t b1) {
    asm volatile("mma.sync.aligned.m16n8k16.row.col.f32.bf16.bf16.f32 "
                 "{%0,%1,%2,%3}, {%4,%5,%6,%7}, {%8,%9}, {%0,%1,%2,%3};"
                 : "+f"(d[0]), "+f"(d[1]), "+f"(d[2]), "+f"(d[3])
                 : "r"(a[0]), "r"(a[1]), "r"(a[2]), "r"(a[3]), "r"(b0), "r"(b1));
}
__device__ __forceinline__ void mma_fp(float* d, const uint32_t* a, uint32_t b0, uint32_t b1) {
    asm volatile("mma.sync.aligned.m16n8k16.row.col.f32.f16.f16.f32 "
                 "{%0,%1,%2,%3}, {%4,%5,%6,%7}, {%8,%9}, {%0,%1,%2,%3};"
                 : "+f"(d[0]), "+f"(d[1]), "+f"(d[2]), "+f"(d[3])
                 : "r"(a[0]), "r"(a[1]), "r"(a[2]), "r"(a[3]), "r"(b0), "r"(b1));
}
__device__ __forceinline__ void splitStoreBF(float4 v, uint32_t* hi, uint32_t* lo) {
    uint32_t hx = f2bf(v.x), hy = f2bf(v.y), hz = f2bf(v.z), hw = f2bf(v.w);
    uint32_t lx = f2bf(v.x - bf2f(hx));
    uint32_t ly = f2bf(v.y - bf2f(hy));
    uint32_t lz = f2bf(v.z - bf2f(hz));
    uint32_t lw = f2bf(v.w - bf2f(hw));
    hi[0] = hx | (hy << 16);
    hi[1] = hz | (hw << 16);
    lo[0] = lx | (ly << 16);
    lo[1] = lz | (lw << 16);
}
__device__ __forceinline__ void convStoreH(float4 v, uint32_t* hi) {
    u16 hx = f2h(v.x), hy = f2h(v.y), hz = f2h(v.z), hw = f2h(v.w);
    hi[0] = (uint32_t)hx | ((uint32_t)hy << 16);
    hi[1] = (uint32_t)hz | ((uint32_t)hw << 16);
}

constexpr int MBM = 128, MBN = 128, MBK = 32;
constexpr int MLDW = 20;

// ===== 3-pass bf16 core — q/k projections + scores =====
struct MSmem3 {
    uint32_t Ah[MBM][MLDW];
    uint32_t Al[MBM][MLDW];
    uint32_t Bh[MBN][MLDW];
    uint32_t Bl[MBN][MLDW];
};

__device__ __forceinline__ void mma_core3(
    const float* __restrict__ A, const float* __restrict__ B, float* __restrict__ C,
    int K, int lda, int ldb, int ldc, int bm, int bn, MSmem3& s)
{
    const int tid = threadIdx.x;
    const int lane = tid & 31, wid = tid >> 5;
    const int wm = wid & 3, wn = wid >> 2;

    float acc[2][8][4];
#pragma unroll
    for (int i = 0; i < 2; i++)
#pragma unroll
        for (int j = 0; j < 8; j++)
#pragma unroll
            for (int e = 0; e < 4; e++) acc[i][j][e] = 0.f;

    const int lr = tid >> 3;
    const int lc = (tid & 7) * 4;
    const int wc = (tid & 7) * 2;

    const uint32_t sb = (uint32_t)__cvta_generic_to_shared(&s);
    const uint32_t offAl = MBM * MLDW * 4;
    const uint32_t offBh = 2 * MBM * MLDW * 4;
    const uint32_t offBl = 3 * MBM * MLDW * 4;
    const int arow = wm * 32 + (lane & 15);
    const int acol = (lane >> 4) * 8;
    const int brow = wn * 64 + (lane & 7) + ((lane >> 4) << 3);
    const int bcol = ((lane >> 3) & 1) << 3;

    for (int k0 = 0; k0 < K; k0 += MBK) {
#pragma unroll
        for (int p = 0; p < 4; p++) {
            int r = lr + p * 32;
            float4 av = *reinterpret_cast<const float4*>(&A[(size_t)(bm + r) * lda + k0 + lc]);
            splitStoreBF(av, &s.Ah[r][wc], &s.Al[r][wc]);
            float4 bv = *reinterpret_cast<const float4*>(&B[(size_t)(bn + r) * ldb + k0 + lc]);
            splitStoreBF(bv, &s.Bh[r][wc], &s.Bl[r][wc]);
        }
        __syncthreads();

#pragma unroll
        for (int kk = 0; kk < 2; kk++) {
            uint32_t ah[2][4], al[2][4], bh[4][4], bl[4][4];
#pragma unroll
            for (int mf = 0; mf < 2; mf++) {
                uint32_t ao = (uint32_t)(((arow + mf * 16) * MLDW * 4) + (kk * 16 + acol) * 2);
                ldsm4(ah[mf], sb + ao);
                ldsm4(al[mf], sb + offAl + ao);
            }
#pragma unroll
            for (int np = 0; np < 4; np++) {
                uint32_t bo = (uint32_t)(((brow + np * 16) * MLDW * 4) + (kk * 16 + bcol) * 2);
                ldsm4(bh[np], sb + offBh + bo);
                ldsm4(bl[np], sb + offBl + bo);
            }
#pragma unroll
            for (int mf = 0; mf < 2; mf++) {
#pragma unroll
                for (int nf = 0; nf < 8; nf++) {
                    int np = nf >> 1;
                    int hf = (nf & 1) * 2;
                    mma_bf(acc[mf][nf], ah[mf], bh[np][hf], bh[np][hf + 1]);
                    mma_bf(acc[mf][nf], al[mf], bh[np][hf], bh[np][hf + 1]);
                    mma_bf(acc[mf][nf], ah[mf], bl[np][hf], bl[np][hf + 1]);
                }
            }
        }
        __syncthreads();
    }

#pragma unroll
    for (int mf = 0; mf < 2; mf++) {
        int row = bm + wm * 32 + mf * 16 + (lane >> 2);
#pragma unroll
        for (int nf = 0; nf < 8; nf++) {
            int col = bn + wn * 64 + nf * 8 + (lane & 3) * 2;
            *reinterpret_cast<float2*>(&C[(size_t)row * ldc + col]) =
                make_float2(acc[mf][nf][0], acc[mf][nf][1]);
            *reinterpret_cast<float2*>(&C[(size_t)(row + 8) * ldc + col]) =
                make_float2(acc[mf][nf][2], acc[mf][nf][3]);
        }
    }
}

// combined q+k projection (shared A = xnorm)
__global__ void __launch_bounds__(256, 2)
mma_qk(const float* __restrict__ A, const float* __restrict__ wq, const float* __restrict__ wk,
       float* __restrict__ qraw, float* __restrict__ kraw) {
    __shared__ MSmem3 s;
    if (blockIdx.y < 16) {
        mma_core3(A, wq, qraw, H_, H_, H_, NH_ * HD_, blockIdx.x * MBM, blockIdx.y * MBN, s);
    } else {
        mma_core3(A, wk, kraw, H_, H_, H_, NKV_ * HD_, blockIdx.x * MBM,
                  (blockIdx.y - 16) * MBN, s);
    }
}

__global__ void __launch_bounds__(256, 2)
mma_scores(const float* __restrict__ q, const float* __restrict__ k, float* __restrict__ sc) {
    if (blockIdx.y > blockIdx.x) return;
    int z = blockIdx.z;
    int b = z >> 3, h = z & 7;
    const float* A = q + (size_t)z * T_ * HD_;
    const float* B = k + (size_t)(b * NKV_ + (h >> 2)) * T_ * HD_;
    float* C = sc + (size_t)z * T_ * T_;
    __shared__ MSmem3 s;
    mma_core3(A, B, C, HD_, HD_, HD_, T_, blockIdx.x * MBM, blockIdx.y * MBN, s);
}

// ===== 1-pass fp16 core =====
struct MSmem1 {
    uint32_t Ah[MBM][MLDW];
    uint32_t Bh[MBN][MLDW];
};

__device__ __forceinline__ void mma_core1(
    const float* __restrict__ A, const float* __restrict__ B, float* __restrict__ C,
    int K, int lda, int ldb, int ldc, int bm, int bn, MSmem1& s)
{
    const int tid = threadIdx.x;
    const int lane = tid & 31, wid = tid >> 5;
    const int wm = wid & 3, wn = wid >> 2;

    float acc[2][8][4];
#pragma unroll
    for (int i = 0; i < 2; i++)
#pragma unroll
        for (int j = 0; j < 8; j++)
#pragma unroll
            for (int e = 0; e < 4; e++) acc[i][j][e] = 0.f;

    const int lr = tid >> 3;
    const int lc = (tid & 7) * 4;
    const int wc = (tid & 7) * 2;

    const uint32_t sb = (uint32_t)__cvta_generic_to_shared(&s);
    const uint32_t offBh = MBM * MLDW * 4;
    const int arow = wm * 32 + (lane & 15);
    const int acol = (lane >> 4) * 8;
    const int brow = wn * 64 + (lane & 7) + ((lane >> 4) << 3);
    const int bcol = ((lane >> 3) & 1) << 3;

    for (int k0 = 0; k0 < K; k0 += MBK) {
#pragma unroll
        for (int p = 0; p < 4; p++) {
            int r = lr + p * 32;
            float4 av = *reinterpret_cast<const float4*>(&A[(size_t)(bm + r) * lda + k0 + lc]);
            convStoreH(av, &s.Ah[r][wc]);
            float4 bv = *reinterpret_cast<const float4*>(&B[(size_t)(bn + r) * ldb + k0 + lc]);
            convStoreH(bv, &s.Bh[r][wc]);
        }
        __syncthreads();

#pragma unroll
        for (int kk = 0; kk < 2; kk++) {
            uint32_t ah[2][4], bh[4][4];
#pragma unroll
            for (int mf = 0; mf < 2; mf++) {
                uint32_t ao = (uint32_t)(((arow + mf * 16) * MLDW * 4) + (kk * 16 + acol) * 2);
                ldsm4(ah[mf], sb + ao);
            }
#pragma unroll
            for (int np = 0; np < 4; np++) {
                uint32_t bo = (uint32_t)(((brow + np * 16) * MLDW * 4) + (kk * 16 + bcol) * 2);
                ldsm4(bh[np], sb + offBh + bo);
            }
#pragma unroll
            for (int mf = 0; mf < 2; mf++) {
#pragma unroll
                for (int nf = 0; nf < 8; nf++) {
                    int np = nf >> 1;
                    int hf = (nf & 1) * 2;
                    mma_fp(acc[mf][nf], ah[mf], bh[np][hf], bh[np][hf + 1]);
                }
            }
        }
        __syncthreads();
    }

#pragma unroll
    for (int mf = 0; mf < 2; mf++) {
        int row = bm + wm * 32 + mf * 16 + (lane >> 2);
#pragma unroll
        for (int nf = 0; nf < 8; nf++) {
            int col = bn + wn * 64 + nf * 8 + (lane & 3) * 2;
            *reinterpret_cast<float2*>(&C[(size_t)row * ldc + col]) =
                make_float2(acc[mf][nf][0], acc[mf][nf][1]);
            *reinterpret_cast<float2*>(&C[(size_t)(row + 8) * ldc + col]) =
                make_float2(acc[mf][nf][2], acc[mf][nf][3]);
        }
    }
}

__global__ void __launch_bounds__(256, 2)
mma_nt1(const float* __restrict__ A, const float* __restrict__ B, float* __restrict__ C,
        int K, int lda, int ldb, int ldc) {
    __shared__ MSmem1 s;
    mma_core1(A, B, C, K, lda, ldb, ldc, blockIdx.x * MBM, blockIdx.y * MBN, s);
}

// combined gate+up GEMM (shared A = hn)
__global__ void __launch_bounds__(256, 2)
mma_gateup(const float* __restrict__ A, const float* __restrict__ gw,
           const float* __restrict__ uw, float* __restrict__ gate, float* __restrict__ up) {
    __shared__ MSmem1 s;
    if (blockIdx.y < 64) {
        mma_core1(A, gw, gate, H_, H_, H_, FF_, blockIdx.x * MBM, blockIdx.y * MBN, s);
    } else {
        mma_core1(A, uw, up, H_, H_, H_, FF_, blockIdx.x * MBM, (blockIdx.y - 64) * MBN, s);
    }
}

__global__ void __launch_bounds__(256, 2)
mma_attnv(const float* __restrict__ p, const float* __restrict__ vT, float* __restrict__ o) {
    int z = blockIdx.z;
    int b = z >> 3, h = z & 7;
    const float* A = p + (size_t)z * T_ * T_;
    const float* B = vT + (size_t)(b * NKV_ + (h >> 2)) * HD_ * T_;
    float* C = o + (size_t)b * T_ * H_ + (size_t)h * HD_;
    int bm = blockIdx.x * MBM;
    __shared__ MSmem1 s;
    mma_core1(A, B, C, bm + MBM, T_, T_, H_, bm, blockIdx.y * MBN, s);
}

// laurel1: split-K x8
__global__ void __launch_bounds__(256)
laurel1_kernel(const float* __restrict__ A, const float* __restrict__ B, float* __restrict__ P) {
    __shared__ float Bs[64][65];
    __shared__ float As[32][65];
    int tid = threadIdx.x;
    int bm = blockIdx.x * 32;
    int ks = blockIdx.y;
    int kbeg = ks * (H_ / 8), kend = kbeg + H_ / 8;
    float acc0[4] = {0.f, 0.f, 0.f, 0.f};
    float acc1[4] = {0.f, 0.f, 0.f, 0.f};
    int tn = tid & 15;
    int tr = tid >> 4;
    for (int k0 = kbeg; k0 < kend; k0 += 64) {
        for (int i = tid; i < 64 * 64; i += 256) {
            int n = i >> 6, kk = i & 63;
            Bs[n][kk] = B[(size_t)n * H_ + k0 + kk];
        }
        for (int i = tid; i < 32 * 64; i += 256) {
            int r = i >> 6, kk = i & 63;
            As[r][kk] = A[(size_t)(bm + r) * H_ + k0 + kk];
        }
        __syncthreads();
#pragma unroll 8
        for (int kk = 0; kk < 64; kk++) {
            float a0 = As[tr][kk], a1 = As[tr + 16][kk];
#pragma unroll
            for (int j = 0; j < 4; j++) {
                float bv = Bs[tn * 4 + j][kk];
                acc0[j] = fmaf(a0, bv, acc0[j]);
                acc1[j] = fmaf(a1, bv, acc1[j]);
            }
        }
        __syncthreads();
    }
#pragma unroll
    for (int j = 0; j < 4; j++) {
        P[((size_t)ks * BT_ + bm + tr) * LR_ + tn * 4 + j] = acc0[j];
        P[((size_t)ks * BT_ + bm + tr + 16) * LR_ + tn * 4 + j] = acc1[j];
    }
}

__global__ void laurel1_reduce(const float* __restrict__ P, float* __restrict__ out) {
    int i = blockIdx.x * blockDim.x + threadIdx.x;
    if (i >= BT_ * LR_) return;
    float s = 0.f;
#pragma unroll
    for (int k = 0; k < 8; k++) s += P[(size_t)k * BT_ * LR_ + i];
    out[i] = s;
}

// ---------- lazy-created side stream + events (host resources, created once
// on the first, uncaptured, correctness call; captured work identical every call)
static cudaStream_t g_s1 = 0;
static cudaEvent_t g_ev0 = 0, g_evL = 0;

extern "C" void kernel_launch(void* const* d_in, const int* in_sizes, int n_in,
                              void* d_out, int out_size) {
    const float* hs    = (const float*)d_in[0];
    const float* cosb  = (const float*)d_in[1];
    const float* sinb  = (const float*)d_in[2];
    const float* wq    = (const float*)d_in[3];
    const float* wk    = (const float*)d_in[4];
    const float* wv    = (const float*)d_in[5];
    const float* wo    = (const float*)d_in[6];
    const float* qnw   = (const float*)d_in[7];
    const float* knw   = (const float*)d_in[8];
    const float* in_ln = (const float*)d_in[9];
    const float* pa_ln = (const float*)d_in[10];
    const float* pf_ln = (const float*)d_in[11];
    const float* pw_ln = (const float*)d_in[12];
    const float* gatew = (const float*)d_in[13];
    const float* upw   = (const float*)d_in[14];
    const float* downw = (const float*)d_in[15];
    const float* llw   = (const float*)d_in[16];
    const float* lrw   = (const float*)d_in[17];
    const float* lnw   = (const float*)d_in[18];
    const float* rnw   = (const float*)d_in[19];
    const float* rw    = (const float*)d_in[20];
    const float* pcw   = (const float*)d_in[21];
    const float* ccw   = (const float*)d_in[22];
    const float* cscal = (const float*)d_in[23];
    float* out = (float*)d_out;

    Scratch* S = 0;
    cudaGetSymbolAddress((void**)&S, g_scratch);

    if (!g_s1) {
        cudaStreamCreateWithFlags(&g_s1, cudaStreamNonBlocking);
        cudaEventCreateWithFlags(&g_ev0, cudaEventDisableTiming);
        cudaEventCreateWithFlags(&g_evL, cudaEventDisableTiming);
    }

    // fused: router + AltUp predict + input LN
    fused_pre<<<BT_, 256>>>(hs, rnw, rw, pcw, in_ln, S->pred, S->xnorm);

    // fork: laurel chain + v chain on side stream
    cudaEventRecord(g_ev0, 0);
    cudaStreamWaitEvent(g_s1, g_ev0, 0);
    laurel1_kernel<<<dim3(BT_ / 32, 8), 256, 0, g_s1>>>(S->xnorm, llw, S->lrpart);
    laurel1_reduce<<<(BT_ * LR_ + 255) / 256, 256, 0, g_s1>>>(S->lrpart, S->lrbuf);
    mma_nt1<<<dim3(16, 16), 256, 0, g_s1>>>(S->lrbuf, lrw, S->laurel, LR_, LR_, LR_, H_);
    ln_kernel<<<BT_, 256, 0, g_s1>>>(S->laurel, lnw, S->xnorm, (const float*)0, 1.f, S->laurel);
    mma_nt1<<<dim3(16, 4), 256, 0, g_s1>>>(S->xnorm, wv, S->vraw, H_, H_, H_, NKV_ * HD_);
    qkvpost_kernel<<<BT_ * NKV_, 256, 0, g_s1>>>(S->vraw, (const float*)0, cosb, sinb,
                                                 S->vT, NKV_, 0, 1);
    cudaEventRecord(g_evL, g_s1);

    // main stream: q+k projections (combined), post, scores, softmax
    mma_qk<<<dim3(16, 20), 256>>>(S->xnorm, wq, wk, S->qraw, S->kraw);
    qkvpost_qk<<<BT_ * (NH_ + NKV_), 256>>>(S->qraw, S->kraw, qnw, knw, cosb, sinb, S->q, S->k);
    mma_scores<<<dim3(8, 8, B_ * NH_), 256>>>(S->q, S->k, S->scores);
    softmax_kernel<<<B_ * NH_ * T_, 256>>>(S->scores);

    // join side chain (vT + laurel ready)
    cudaStreamWaitEvent(0, g_evL, 0);
    mma_attnv<<<dim3(8, 2, B_ * NH_), 256>>>(S->scores, S->vT, S->attnout);
    mma_nt1<<<dim3(16, 16), 256>>>(S->attnout, wo, S->attnproj,
                                   NH_ * HD_, NH_ * HD_, NH_ * HD_, H_);

    // fused: post-attn LN + residuals + pre-ffw LN
    fused_mid<<<BT_, 256>>>(S->attnproj, pa_ln, S->pred, S->laurel, pf_ln,
                            S->attnlaurel, S->hn);

    // combined gate+up GEMM
    mma_gateup<<<dim3(16, 128), 256>>>(S->hn, gatew, upw, S->gate, S->up);

    int n4 = (int)(((size_t)BT_ * FF_) / 4);
    gelumul_kernel<<<(n4 + 255) / 256, 256>>>(S->gate, S->up, n4);

    mma_nt1<<<dim3(16, 16), 256>>>(S->gate, downw, S->ffw, FF_, FF_, FF_, H_);

    // fused: post-ffw LN + router + AltUp correct -> out
    fused_post<<<BT_, 256>>>(S->ffw, pw_ln, S->attnlaurel, rnw, rw, ccw, cscal,
                             S->pred, out);

    (void)in_sizes; (void)n_in; (void)out_size;
}

// round 12
// speedup vs baseline: 1.9578x; 1.0170x over previous
#include <cuda_runtime.h>
#include <cstdint>
#include <cstddef>
#include <math.h>

typedef unsigned short u16;

constexpr int B_ = 2, T_ = 1024, H_ = 2048, NH_ = 8, NKV_ = 2, HD_ = 256;
constexpr int FF_ = 8192, LR_ = 64;
constexpr int BT_ = B_ * T_;
constexpr size_t BTH_ = (size_t)BT_ * H_;
constexpr float EPS_ = 1e-6f;

struct Scratch {
    float pred[4 * BTH_];
    float xnorm[BTH_];
    float lrpart[8 * BT_ * LR_];
    float lrbuf[BT_ * LR_];
    float laurel[BTH_];
    float qraw[BTH_];
    float kraw[(size_t)BT_ * NKV_ * HD_];
    float vraw[(size_t)BT_ * NKV_ * HD_];
    float q[BTH_];
    float k[(size_t)BT_ * NKV_ * HD_];
    float vT[(size_t)BT_ * NKV_ * HD_];
    float scores[(size_t)B_ * NH_ * T_ * T_];
    float attnout[BTH_];
    float attnproj[BTH_];
    float attnlaurel[BTH_];
    float hn[BTH_];
    float gate[(size_t)BT_ * FF_];
    float up[(size_t)BT_ * FF_];
    float ffw[BTH_];
};
__device__ Scratch g_scratch;

// ---------- bf16 / fp16 bit helpers ----------
__device__ __forceinline__ uint32_t f2bf(float x) {
    uint32_t u = __float_as_uint(x);
    return (u + 0x7FFFu + ((u >> 16) & 1u)) >> 16;
}
__device__ __forceinline__ float bf2f(uint32_t b) {
    return __uint_as_float(b << 16);
}
__device__ __forceinline__ u16 f2h(float x) {
    u16 h;
    asm("cvt.rn.f16.f32 %0, %1;" : "=h"(h) : "f"(x));
    return h;
}

// ---------- reductions ----------
__device__ __forceinline__ float warpSum(float v) {
#pragma unroll
    for (int o = 16; o > 0; o >>= 1) v += __shfl_xor_sync(0xffffffffu, v, o);
    return v;
}
__device__ __forceinline__ float warpMax(float v) {
#pragma unroll
    for (int o = 16; o > 0; o >>= 1) v = fmaxf(v, __shfl_xor_sync(0xffffffffu, v, o));
    return v;
}
__device__ __forceinline__ float blockSum(float v, float* red) {
    v = warpSum(v);
    int lane = threadIdx.x & 31, w = threadIdx.x >> 5;
    if (lane == 0) red[w] = v;
    __syncthreads();
    int nw = (blockDim.x + 31) >> 5;
    float r = (lane < nw) ? red[lane] : 0.f;
    if (w == 0) {
        r = warpSum(r);
        if (lane == 0) red[0] = r;
    }
    __syncthreads();
    r = red[0];
    __syncthreads();
    return r;
}
__device__ __forceinline__ float blockMax(float v, float* red) {
    v = warpMax(v);
    int lane = threadIdx.x & 31, w = threadIdx.x >> 5;
    if (lane == 0) red[w] = v;
    __syncthreads();
    int nw = (blockDim.x + 31) >> 5;
    float r = (lane < nw) ? red[lane] : -INFINITY;
    if (w == 0) {
        r = warpMax(r);
        if (lane == 0) red[0] = r;
    }
    __syncthreads();
    r = red[0];
    __syncthreads();
    return r;
}

// ===== fused per-token kernels =====
__global__ void fused_pre(const float* __restrict__ hs, const float* __restrict__ rnw,
                          const float* __restrict__ rw, const float* __restrict__ pcw,
                          const float* __restrict__ inw,
                          float* __restrict__ pred, float* __restrict__ xnorm) {
    __shared__ float sx[H_];
    __shared__ float px[H_];
    __shared__ float red[32];
    __shared__ float cf[16];
    size_t off = (size_t)blockIdx.x * H_;
    int tid = threadIdx.x;

    float ls = 0.f;
    for (int i = tid; i < H_; i += blockDim.x) {
        float v = hs[off + i];
        sx[i] = v;
        ls += v;
    }
    float mean = blockSum(ls, red) * (1.f / H_);
    float lv = 0.f;
    for (int i = tid; i < H_; i += blockDim.x) {
        float d = sx[i] - mean;
        lv += d * d;
    }
    float rs = rsqrtf(blockSum(lv, red) * (1.f / H_) + EPS_);

    float a0 = 0.f, a1 = 0.f, a2 = 0.f, a3 = 0.f;
    for (int i = tid; i < H_; i += blockDim.x) {
        float r = (sx[i] - mean) * rs * rnw[i] * (1.f / H_);
        a0 += r * rw[i];
        a1 += r * rw[H_ + i];
        a2 += r * rw[2 * H_ + i];
        a3 += r * rw[3 * H_ + i];
    }
    float t0 = blockSum(a0, red);
    float t1 = blockSum(a1, red);
    float t2 = blockSum(a2, red);
    float t3 = blockSum(a3, red);
    if (tid < 16) {
        float m0 = tanhf(t0), m1 = tanhf(t1), m2 = tanhf(t2), m3 = tanhf(t3);
        cf[tid] = m0 * pcw[tid * 4] + m1 * pcw[tid * 4 + 1]
                + m2 * pcw[tid * 4 + 2] + m3 * pcw[tid * 4 + 3];
    }
    __syncthreads();

    float ps = 0.f;
    for (int i = tid; i < H_; i += blockDim.x) {
        float h0 = sx[i];
        float h1 = hs[BTH_ + off + i];
        float h2 = hs[2 * BTH_ + off + i];
        float h3 = hs[3 * BTH_ + off + i];
        float p0 = h0 + h0 * cf[0] + h1 * cf[1] + h2 * cf[2] + h3 * cf[3];
        pred[off + i] = p0;
        px[i] = p0;
        ps += p0;
        pred[BTH_ + off + i]     = h1 + h0 * cf[4]  + h1 * cf[5]  + h2 * cf[6]  + h3 * cf[7];
        pred[2 * BTH_ + off + i] = h2 + h0 * cf[8]  + h1 * cf[9]  + h2 * cf[10] + h3 * cf[11];
        pred[3 * BTH_ + off + i] = h3 + h0 * cf[12] + h1 * cf[13] + h2 * cf[14] + h3 * cf[15];
    }
    float mean2 = blockSum(ps, red) * (1.f / H_);
    float lv2 = 0.f;
    for (int i = tid; i < H_; i += blockDim.x) {
        float d = px[i] - mean2;
        lv2 += d * d;
    }
    float rs2 = rsqrtf(blockSum(lv2, red) * (1.f / H_) + EPS_);
    for (int i = tid; i < H_; i += blockDim.x) {
        xnorm[off + i] = (px[i] - mean2) * rs2 * inw[i];
    }
}

__global__ void fused_mid(const float* __restrict__ ap, const float* __restrict__ paw,
                          const float* __restrict__ pred, const float* __restrict__ laurel,
                          const float* __restrict__ pfw,
                          float* __restrict__ attnlaurel, float* __restrict__ hn) {
    __shared__ float sx[H_];
    __shared__ float ax[H_];
    __shared__ float red[32];
    size_t off = (size_t)blockIdx.x * H_;
    int tid = threadIdx.x;

    float ls = 0.f;
    for (int i = tid; i < H_; i += blockDim.x) {
        float v = ap[off + i];
        sx[i] = v;
        ls += v;
    }
    float mean = blockSum(ls, red) * (1.f / H_);
    float lv = 0.f;
    for (int i = tid; i < H_; i += blockDim.x) {
        float d = sx[i] - mean;
        lv += d * d;
    }
    float rs = rsqrtf(blockSum(lv, red) * (1.f / H_) + EPS_);

    float ls2 = 0.f;
    for (int i = tid; i < H_; i += blockDim.x) {
        float v = (sx[i] - mean) * rs * paw[i] + pred[off + i] + laurel[off + i];
        v *= 0.7071067811865476f;
        ax[i] = v;
        attnlaurel[off + i] = v;
        ls2 += v;
    }
    float mean2 = blockSum(ls2, red) * (1.f / H_);
    float lv2 = 0.f;
    for (int i = tid; i < H_; i += blockDim.x) {
        float d = ax[i] - mean2;
        lv2 += d * d;
    }
    float rs2 = rsqrtf(blockSum(lv2, red) * (1.f / H_) + EPS_);
    for (int i = tid; i < H_; i += blockDim.x) {
        hn[off + i] = (ax[i] - mean2) * rs2 * pfw[i];
    }
}

__global__ void fused_post(const float* __restrict__ ffw, const float* __restrict__ pww,
                           const float* __restrict__ attnlaurel,
                           const float* __restrict__ rnw, const float* __restrict__ rw,
                           const float* __restrict__ ccw, const float* __restrict__ cscale,
                           const float* __restrict__ pred, float* __restrict__ out) {
    __shared__ float sx[H_];
    __shared__ float ax[H_];
    __shared__ float red[32];
    size_t off = (size_t)blockIdx.x * H_;
    int tid = threadIdx.x;

    float ls = 0.f;
    for (int i = tid; i < H_; i += blockDim.x) {
        float v = ffw[off + i];
        sx[i] = v;
        ls += v;
    }
    float mean = blockSum(ls, red) * (1.f / H_);
    float lv = 0.f;
    for (int i = tid; i < H_; i += blockDim.x) {
        float d = sx[i] - mean;
        lv += d * d;
    }
    float rs = rsqrtf(blockSum(lv, red) * (1.f / H_) + EPS_);

    float as = 0.f;
    for (int i = tid; i < H_; i += blockDim.x) {
        float v = (sx[i] - mean) * rs * pww[i] + attnlaurel[off + i];
        ax[i] = v;
        as += v;
    }
    float mean2 = blockSum(as, red) * (1.f / H_);
    float lv2 = 0.f;
    for (int i = tid; i < H_; i += blockDim.x) {
        float d = ax[i] - mean2;
        lv2 += d * d;
    }
    float rs2 = rsqrtf(blockSum(lv2, red) * (1.f / H_) + EPS_);
    float a0 = 0.f, a1 = 0.f, a2 = 0.f, a3 = 0.f;
    for (int i = tid; i < H_; i += blockDim.x) {
        float r = (ax[i] - mean2) * rs2 * rnw[i] * (1.f / H_);
        a0 += r * rw[i];
        a1 += r * rw[H_ + i];
        a2 += r * rw[2 * H_ + i];
        a3 += r * rw[3 * H_ + i];
    }
    float m0 = tanhf(blockSum(a0, red));
    float m1 = tanhf(blockSum(a1, red));
    float m2 = tanhf(blockSum(a2, red));
    float m3 = tanhf(blockSum(a3, red));
    float cc0 = 1.f + m0 * ccw[0]  + m1 * ccw[1]  + m2 * ccw[2]  + m3 * ccw[3];
    float cc1 = 1.f + m0 * ccw[4]  + m1 * ccw[5]  + m2 * ccw[6]  + m3 * ccw[7];
    float cc2 = 1.f + m0 * ccw[8]  + m1 * ccw[9]  + m2 * ccw[10] + m3 * ccw[11];
    float cc3 = 1.f + m0 * ccw[12] + m1 * ccw[13] + m2 * ccw[14] + m3 * ccw[15];

    for (int f = tid; f < H_; f += blockDim.x) {
        float p0 = pred[off + f];
        float inno = ax[f] - p0;
        out[off + f]            = (inno * cc0 + p0) * cscale[f];
        out[BTH_ + off + f]     = inno * cc1 + pred[BTH_ + off + f];
        out[2 * BTH_ + off + f] = inno * cc2 + pred[2 * BTH_ + off + f];
        out[3 * BTH_ + off + f] = inno * cc3 + pred[3 * BTH_ + off + f];
    }
}

// ---------- remaining elementwise ----------
__global__ void ln_kernel(const float* __restrict__ a, const float* __restrict__ w,
                          const float* __restrict__ add1, const float* __restrict__ add2,
                          float scale, float* __restrict__ dst) {
    __shared__ float sx[H_];
    __shared__ float red[32];
    size_t off = (size_t)blockIdx.x * H_;
    int tid = threadIdx.x;
    float ls = 0.f;
    for (int i = tid; i < H_; i += blockDim.x) {
        float v = a[off + i];
        sx[i] = v;
        ls += v;
    }
    float mean = blockSum(ls, red) * (1.f / H_);
    float lv = 0.f;
    for (int i = tid; i < H_; i += blockDim.x) {
        float d = sx[i] - mean;
        lv += d * d;
    }
    float var = blockSum(lv, red) * (1.f / H_);
    float rs = rsqrtf(var + EPS_);
    for (int i = tid; i < H_; i += blockDim.x) {
        float v = (sx[i] - mean) * rs * w[i];
        if (add1) v += add1[off + i];
        if (add2) v += add2[off + i];
        dst[off + i] = v * scale;
    }
}

__device__ __forceinline__ void qkvpost_body(
    const float* __restrict__ raw, const float* __restrict__ nw,
    const float* __restrict__ cosb, const float* __restrict__ sinb,
    float* __restrict__ out, int nheads, int do_rope, int trans, int idx) {
    __shared__ float sx[HD_];
    __shared__ float red[32];
    int h = idx % nheads;
    int bt = idx / nheads;
    int t = bt % T_, b = bt / T_;
    int d = threadIdx.x;
    float v = raw[(size_t)bt * nheads * HD_ + h * HD_ + d];
    float mean = blockSum(v, red) * (1.f / HD_);
    float c = v - mean;
    float var = blockSum(c * c, red) * (1.f / HD_);
    float ln = c * rsqrtf(var + EPS_) * (nw ? nw[d] : 1.f);
    sx[d] = ln;
    __syncthreads();
    float o = ln;
    if (do_rope) {
        float cs = cosb[(size_t)bt * HD_ + d];
        float sn = sinb[(size_t)bt * HD_ + d];
        float rot = (d < 128) ? -sx[d + 128] : sx[d - 128];
        o = ln * cs + rot * sn;
    }
    if (trans) {
        out[((size_t)(b * nheads + h) * HD_ + d) * T_ + t] = o;
    } else {
        out[((size_t)(b * nheads + h) * T_ + t) * HD_ + d] = o;
    }
}

__global__ void qkvpost_kernel(const float* __restrict__ raw, const float* __restrict__ nw,
                               const float* __restrict__ cosb, const float* __restrict__ sinb,
                               float* __restrict__ out, int nheads, int do_rope, int trans) {
    qkvpost_body(raw, nw, cosb, sinb, out, nheads, do_rope, trans, blockIdx.x);
}

__global__ void qkvpost_qk(const float* __restrict__ qraw, const float* __restrict__ kraw,
                           const float* __restrict__ qnw, const float* __restrict__ knw,
                           const float* __restrict__ cosb, const float* __restrict__ sinb,
                           float* __restrict__ q, float* __restrict__ k) {
    int idx = blockIdx.x;
    if (idx < BT_ * NH_) {
        qkvpost_body(qraw, qnw, cosb, sinb, q, NH_, 1, 0, idx);
    } else {
        qkvpost_body(kraw, knw, cosb, sinb, k, NKV_, 1, 0, idx - BT_ * NH_);
    }
}

__global__ void softmax_kernel(float* __restrict__ scores) {
    __shared__ float sx[T_];
    __shared__ float red[32];
    int q = blockIdx.x % T_;
    size_t off = (size_t)blockIdx.x * T_;
    int tid = threadIdx.x;
    int n = q + 1;
    float lm = -INFINITY;
    for (int i = tid; i < n; i += blockDim.x) {
        float v = scores[off + i];
        sx[i] = v;
        lm = fmaxf(lm, v);
    }
    float gm = blockMax(lm, red);
    float lsum = 0.f;
    for (int i = tid; i < n; i += blockDim.x) {
        float e = __expf(sx[i] - gm);
        sx[i] = e;
        lsum += e;
    }
    float inv = 1.f / blockSum(lsum, red);
    for (int i = tid; i < T_; i += blockDim.x) {
        scores[off + i] = (i < n) ? sx[i] * inv : 0.f;
    }
}

__device__ __forceinline__ float gelu_tanh(float x) {
    return 0.5f * x * (1.f + tanhf(0.7978845608028654f * (x + 0.044715f * x * x * x)));
}

__global__ void gelumul_kernel(float* __restrict__ g, const float* __restrict__ u, int n4) {
    int i = blockIdx.x * blockDim.x + threadIdx.x;
    if (i >= n4) return;
    float4 a = reinterpret_cast<float4*>(g)[i];
    float4 b = reinterpret_cast<const float4*>(u)[i];
    a.x = gelu_tanh(a.x) * b.x;
    a.y = gelu_tanh(a.y) * b.y;
    a.z = gelu_tanh(a.z) * b.z;
    a.w = gelu_tanh(a.w) * b.w;
    reinterpret_cast<float4*>(g)[i] = a;
}

// ===== shared MMA plumbing =====
__device__ __forceinline__ void ldsm4(uint32_t* r, uint32_t addr) {
    asm volatile("ldmatrix.sync.aligned.m8n8.x4.shared.b16 {%0,%1,%2,%3}, [%4];"
                 : "=r"(r[0]), "=r"(r[1]), "=r"(r[2]), "=r"(r[3]) : "r"(addr));
}
__device__ __forceinline__ void mma_bf(float* d, const uint32_t* a, uint32_t b0, uint32_t b1) {
    asm volatile("mma.sync.aligned.m16n8k16.row.col.f32.bf16.bf16.f32 "
                 "{%0,%1,%2,%3}, {%4,%5,%6,%7}, {%8,%9}, {%0,%1,%2,%3};"
                 : "+f"(d[0]), "+f"(d[1]), "+f"(d[2]), "+f"(d[3])
                 : "r"(a[0]), "r"(a[1]), "r"(a[2]), "r"(a[3]), "r"(b0), "r"(b1));
}
__device__ __forceinline__ void mma_fp(float* d, const uint32_t* a, uint32_t b0, uint32_t b1) {
    asm volatile("mma.sync.aligned.m16n8k16.row.col.f32.f16.f16.f32 "
                 "{%0,%1,%2,%3}, {%4,%5,%6,%7}, {%8,%9}, {%0,%1,%2,%3};"
                 : "+f"(d[0]), "+f"(d[1]), "+f"(d[2]), "+f"(d[3])
                 : "r"(a[0]), "r"(a[1]), "r"(a[2]), "r"(a[3]), "r"(b0), "r"(b1));
}
__device__ __forceinline__ void splitStoreBF(float4 v, uint32_t* hi, uint32_t* lo) {
    uint32_t hx = f2bf(v.x), hy = f2bf(v.y), hz = f2bf(v.z), hw = f2bf(v.w);
    uint32_t lx = f2bf(v.x - bf2f(hx));
    uint32_t ly = f2bf(v.y - bf2f(hy));
    uint32_t lz = f2bf(v.z - bf2f(hz));
    uint32_t lw = f2bf(v.w - bf2f(hw));
    hi[0] = hx | (hy << 16);
    hi[1] = hz | (hw << 16);
    lo[0] = lx | (ly << 16);
    lo[1] = lz | (lw << 16);
}
__device__ __forceinline__ void convStoreH(float4 v, uint32_t* hi) {
    u16 hx = f2h(v.x), hy = f2h(v.y), hz = f2h(v.z), hw = f2h(v.w);
    hi[0] = (uint32_t)hx | ((uint32_t)hy << 16);
    hi[1] = (uint32_t)hz | ((uint32_t)hw << 16);
}

constexpr int MBM = 128, MBN = 128, MBK = 32;
constexpr int MLDW = 20;

// ===== 3-pass bf16 core — q/k projections + scores (unchanged) =====
struct MSmem3 {
    uint32_t Ah[MBM][MLDW];
    uint32_t Al[MBM][MLDW];
    uint32_t Bh[MBN][MLDW];
    uint32_t Bl[MBN][MLDW];
};

__device__ __forceinline__ void mma_core3(
    const float* __restrict__ A, const float* __restrict__ B, float* __restrict__ C,
    int K, int lda, int ldb, int ldc, int bm, int bn, MSmem3& s)
{
    const int tid = threadIdx.x;
    const int lane = tid & 31, wid = tid >> 5;
    const int wm = wid & 3, wn = wid >> 2;

    float acc[2][8][4];
#pragma unroll
    for (int i = 0; i < 2; i++)
#pragma unroll
        for (int j = 0; j < 8; j++)
#pragma unroll
            for (int e = 0; e < 4; e++) acc[i][j][e] = 0.f;

    const int lr = tid >> 3;
    const int lc = (tid & 7) * 4;
    const int wc = (tid & 7) * 2;

    const uint32_t sb = (uint32_t)__cvta_generic_to_shared(&s);
    const uint32_t offAl = MBM * MLDW * 4;
    const uint32_t offBh = 2 * MBM * MLDW * 4;
    const uint32_t offBl = 3 * MBM * MLDW * 4;
    const int arow = wm * 32 + (lane & 15);
    const int acol = (lane >> 4) * 8;
    const int brow = wn * 64 + (lane & 7) + ((lane >> 4) << 3);
    const int bcol = ((lane >> 3) & 1) << 3;

    for (int k0 = 0; k0 < K; k0 += MBK) {
#pragma unroll
        for (int p = 0; p < 4; p++) {
            int r = lr + p * 32;
            float4 av = *reinterpret_cast<const float4*>(&A[(size_t)(bm + r) * lda + k0 + lc]);
            splitStoreBF(av, &s.Ah[r][wc], &s.Al[r][wc]);
            float4 bv = *reinterpret_cast<const float4*>(&B[(size_t)(bn + r) * ldb + k0 + lc]);
            splitStoreBF(bv, &s.Bh[r][wc], &s.Bl[r][wc]);
        }
        __syncthreads();

#pragma unroll
        for (int kk = 0; kk < 2; kk++) {
            uint32_t ah[2][4], al[2][4], bh[4][4], bl[4][4];
#pragma unroll
            for (int mf = 0; mf < 2; mf++) {
                uint32_t ao = (uint32_t)(((arow + mf * 16) * MLDW * 4) + (kk * 16 + acol) * 2);
                ldsm4(ah[mf], sb + ao);
                ldsm4(al[mf], sb + offAl + ao);
            }
#pragma unroll
            for (int np = 0; np < 4; np++) {
                uint32_t bo = (uint32_t)(((brow + np * 16) * MLDW * 4) + (kk * 16 + bcol) * 2);
                ldsm4(bh[np], sb + offBh + bo);
                ldsm4(bl[np], sb + offBl + bo);
            }
#pragma unroll
            for (int mf = 0; mf < 2; mf++) {
#pragma unroll
                for (int nf = 0; nf < 8; nf++) {
                    int np = nf >> 1;
                    int hf = (nf & 1) * 2;
                    mma_bf(acc[mf][nf], ah[mf], bh[np][hf], bh[np][hf + 1]);
                    mma_bf(acc[mf][nf], al[mf], bh[np][hf], bh[np][hf + 1]);
                    mma_bf(acc[mf][nf], ah[mf], bl[np][hf], bl[np][hf + 1]);
                }
            }
        }
        __syncthreads();
    }

#pragma unroll
    for (int mf = 0; mf < 2; mf++) {
        int row = bm + wm * 32 + mf * 16 + (lane >> 2);
#pragma unroll
        for (int nf = 0; nf < 8; nf++) {
            int col = bn + wn * 64 + nf * 8 + (lane & 3) * 2;
            *reinterpret_cast<float2*>(&C[(size_t)row * ldc + col]) =
                make_float2(acc[mf][nf][0], acc[mf][nf][1]);
            *reinterpret_cast<float2*>(&C[(size_t)(row + 8) * ldc + col]) =
                make_float2(acc[mf][nf][2], acc[mf][nf][3]);
        }
    }
}

__global__ void __launch_bounds__(256, 2)
mma_qk(const float* __restrict__ A, const float* __restrict__ wq, const float* __restrict__ wk,
       float* __restrict__ qraw, float* __restrict__ kraw) {
    __shared__ MSmem3 s;
    if (blockIdx.y < 16) {
        mma_core3(A, wq, qraw, H_, H_, H_, NH_ * HD_, blockIdx.x * MBM, blockIdx.y * MBN, s);
    } else {
        mma_core3(A, wk, kraw, H_, H_, H_, NKV_ * HD_, blockIdx.x * MBM,
                  (blockIdx.y - 16) * MBN, s);
    }
}

__global__ void __launch_bounds__(256, 2)
mma_scores(const float* __restrict__ q, const float* __restrict__ k, float* __restrict__ sc) {
    if (blockIdx.y > blockIdx.x) return;
    int z = blockIdx.z;
    int b = z >> 3, h = z & 7;
    const float* A = q + (size_t)z * T_ * HD_;
    const float* B = k + (size_t)(b * NKV_ + (h >> 2)) * T_ * HD_;
    float* C = sc + (size_t)z * T_ * T_;
    __shared__ MSmem3 s;
    mma_core3(A, B, C, HD_, HD_, HD_, T_, blockIdx.x * MBM, blockIdx.y * MBN, s);
}

// ===== 1-pass fp16 core — SOFTWARE PIPELINED (double-buffered smem) =====
struct MSmem1 {
    uint32_t Ah[MBM][MLDW];
    uint32_t Bh[MBN][MLDW];
};

__device__ __forceinline__ void mma_core1(
    const float* __restrict__ A, const float* __restrict__ B, float* __restrict__ C,
    int K, int lda, int ldb, int ldc, int bm, int bn, MSmem1 (&s)[2])
{
    const int tid = threadIdx.x;
    const int lane = tid & 31, wid = tid >> 5;
    const int wm = wid & 3, wn = wid >> 2;

    float acc[2][8][4];
#pragma unroll
    for (int i = 0; i < 2; i++)
#pragma unroll
        for (int j = 0; j < 8; j++)
#pragma unroll
            for (int e = 0; e < 4; e++) acc[i][j][e] = 0.f;

    const int lr = tid >> 3;
    const int lc = (tid & 7) * 4;
    const int wc = (tid & 7) * 2;

    const uint32_t sb0 = (uint32_t)__cvta_generic_to_shared(&s[0]);
    const uint32_t stageBytes = (uint32_t)sizeof(MSmem1);
    const uint32_t offBh = MBM * MLDW * 4;
    const int arow = wm * 32 + (lane & 15);
    const int acol = (lane >> 4) * 8;
    const int brow = wn * 64 + (lane & 7) + ((lane >> 4) << 3);
    const int bcol = ((lane >> 3) & 1) << 3;

    float4 av[4], bv[4];
    // prologue: load k-tile 0 and store to stage 0
#pragma unroll
    for (int p = 0; p < 4; p++) {
        int r = lr + p * 32;
        av[p] = *reinterpret_cast<const float4*>(&A[(size_t)(bm + r) * lda + lc]);
        bv[p] = *reinterpret_cast<const float4*>(&B[(size_t)(bn + r) * ldb + lc]);
    }
#pragma unroll
    for (int p = 0; p < 4; p++) {
        int r = lr + p * 32;
        convStoreH(av[p], &s[0].Ah[r][wc]);
        convStoreH(bv[p], &s[0].Bh[r][wc]);
    }
    __syncthreads();

    const int KT = K / MBK;
    for (int kt = 0; kt < KT; kt++) {
        const int cur = kt & 1;
        const uint32_t sb = sb0 + (uint32_t)cur * stageBytes;
        // issue next tile's global loads (latency hides under MMA below)
        if (kt + 1 < KT) {
            int k0 = (kt + 1) * MBK;
#pragma unroll
            for (int p = 0; p < 4; p++) {
                int r = lr + p * 32;
                av[p] = *reinterpret_cast<const float4*>(&A[(size_t)(bm + r) * lda + k0 + lc]);
                bv[p] = *reinterpret_cast<const float4*>(&B[(size_t)(bn + r) * ldb + k0 + lc]);
            }
        }
        // MMA on current stage
#pragma unroll
        for (int kk = 0; kk < 2; kk++) {
            uint32_t ah[2][4], bh[4][4];
#pragma unroll
            for (int mf = 0; mf < 2; mf++) {
                uint32_t ao = (uint32_t)(((arow + mf * 16) * MLDW * 4) + (kk * 16 + acol) * 2);
                ldsm4(ah[mf], sb + ao);
            }
#pragma unroll
            for (int np = 0; np < 4; np++) {
                uint32_t bo = (uint32_t)(((brow + np * 16) * MLDW * 4) + (kk * 16 + bcol) * 2);
                ldsm4(bh[np], sb + offBh + bo);
            }
#pragma unroll
            for (int mf = 0; mf < 2; mf++) {
#pragma unroll
                for (int nf = 0; nf < 8; nf++) {
                    int np = nf >> 1;
                    int hf = (nf & 1) * 2;
                    mma_fp(acc[mf][nf], ah[mf], bh[np][hf], bh[np][hf + 1]);
                }
            }
        }
        // store next tile into alternate stage
        if (kt + 1 < KT) {
            MSmem1& sn = s[cur ^ 1];
#pragma unroll
            for (int p = 0; p < 4; p++) {
                int r = lr + p * 32;
                convStoreH(av[p], &sn.Ah[r][wc]);
                convStoreH(bv[p], &sn.Bh[r][wc]);
            }
        }
        __syncthreads();
    }

#pragma unroll
    for (int mf = 0; mf < 2; mf++) {
        int row = bm + wm * 32 + mf * 16 + (lane >> 2);
#pragma unroll
        for (int nf = 0; nf < 8; nf++) {
            int col = bn + wn * 64 + nf * 8 + (lane & 3) * 2;
            *reinterpret_cast<float2*>(&C[(size_t)row * ldc + col]) =
                make_float2(acc[mf][nf][0], acc[mf][nf][1]);
            *reinterpret_cast<float2*>(&C[(size_t)(row + 8) * ldc + col]) =
                make_float2(acc[mf][nf][2], acc[mf][nf][3]);
        }
    }
}

__global__ void __launch_bounds__(256, 2)
mma_nt1(const float* __restrict__ A, const float* __restrict__ B, float* __restrict__ C,
        int K, int lda, int ldb, int ldc) {
    __shared__ MSmem1 s[2];
    mma_core1(A, B, C, K, lda, ldb, ldc, blockIdx.x * MBM, blockIdx.y * MBN, s);
}

__global__ void __launch_bounds__(256, 2)
mma_gateup(const float* __restrict__ A, const float* __restrict__ gw,
           const float* __restrict__ uw, float* __restrict__ gate, float* __restrict__ up) {
    __shared__ MSmem1 s[2];
    if (blockIdx.y < 64) {
        mma_core1(A, gw, gate, H_, H_, H_, FF_, blockIdx.x * MBM, blockIdx.y * MBN, s);
    } else {
        mma_core1(A, uw, up, H_, H_, H_, FF_, blockIdx.x * MBM, (blockIdx.y - 64) * MBN, s);
    }
}

__global__ void __launch_bounds__(256, 2)
mma_attnv(const float* __restrict__ p, const float* __restrict__ vT, float* __restrict__ o) {
    int z = blockIdx.z;
    int b = z >> 3, h = z & 7;
    const float* A = p + (size_t)z * T_ * T_;
    const float* B = vT + (size_t)(b * NKV_ + (h >> 2)) * HD_ * T_;
    float* C = o + (size_t)b * T_ * H_ + (size_t)h * HD_;
    int bm = blockIdx.x * MBM;
    __shared__ MSmem1 s[2];
    mma_core1(A, B, C, bm + MBM, T_, T_, H_, bm, blockIdx.y * MBN, s);
}

// laurel1: split-K x8
__global__ void __launch_bounds__(256)
laurel1_kernel(const float* __restrict__ A, const float* __restrict__ B, float* __restrict__ P) {
    __shared__ float Bs[64][65];
    __shared__ float As[32][65];
    int tid = threadIdx.x;
    int bm = blockIdx.x * 32;
    int ks = blockIdx.y;
    int kbeg = ks * (H_ / 8), kend = kbeg + H_ / 8;
    float acc0[4] = {0.f, 0.f, 0.f, 0.f};
    float acc1[4] = {0.f, 0.f, 0.f, 0.f};
    int tn = tid & 15;
    int tr = tid >> 4;
    for (int k0 = kbeg; k0 < kend; k0 += 64) {
        for (int i = tid; i < 64 * 64; i += 256) {
            int n = i >> 6, kk = i & 63;
            Bs[n][kk] = B[(size_t)n * H_ + k0 + kk];
        }
        for (int i = tid; i < 32 * 64; i += 256) {
            int r = i >> 6, kk = i & 63;
            As[r][kk] = A[(size_t)(bm + r) * H_ + k0 + kk];
        }
        __syncthreads();
#pragma unroll 8
        for (int kk = 0; kk < 64; kk++) {
            float a0 = As[tr][kk], a1 = As[tr + 16][kk];
#pragma unroll
            for (int j = 0; j < 4; j++) {
                float bv = Bs[tn * 4 + j][kk];
                acc0[j] = fmaf(a0, bv, acc0[j]);
                acc1[j] = fmaf(a1, bv, acc1[j]);
            }
        }
        __syncthreads();
    }
#pragma unroll
    for (int j = 0; j < 4; j++) {
        P[((size_t)ks * BT_ + bm + tr) * LR_ + tn * 4 + j] = acc0[j];
        P[((size_t)ks * BT_ + bm + tr + 16) * LR_ + tn * 4 + j] = acc1[j];
    }
}

__global__ void laurel1_reduce(const float* __restrict__ P, float* __restrict__ out) {
    int i = blockIdx.x * blockDim.x + threadIdx.x;
    if (i >= BT_ * LR_) return;
    float s = 0.f;
#pragma unroll
    for (int k = 0; k < 8; k++) s += P[(size_t)k * BT_ * LR_ + i];
    out[i] = s;
}

// ---------- lazy side stream + events ----------
static cudaStream_t g_s1 = 0;
static cudaEvent_t g_ev0 = 0, g_evL = 0;

extern "C" void kernel_launch(void* const* d_in, const int* in_sizes, int n_in,
                              void* d_out, int out_size) {
    const float* hs    = (const float*)d_in[0];
    const float* cosb  = (const float*)d_in[1];
    const float* sinb  = (const float*)d_in[2];
    const float* wq    = (const float*)d_in[3];
    const float* wk    = (const float*)d_in[4];
    const float* wv    = (const float*)d_in[5];
    const float* wo    = (const float*)d_in[6];
    const float* qnw   = (const float*)d_in[7];
    const float* knw   = (const float*)d_in[8];
    const float* in_ln = (const float*)d_in[9];
    const float* pa_ln = (const float*)d_in[10];
    const float* pf_ln = (const float*)d_in[11];
    const float* pw_ln = (const float*)d_in[12];
    const float* gatew = (const float*)d_in[13];
    const float* upw   = (const float*)d_in[14];
    const float* downw = (const float*)d_in[15];
    const float* llw   = (const float*)d_in[16];
    const float* lrw   = (const float*)d_in[17];
    const float* lnw   = (const float*)d_in[18];
    const float* rnw   = (const float*)d_in[19];
    const float* rw    = (const float*)d_in[20];
    const float* pcw   = (const float*)d_in[21];
    const float* ccw   = (const float*)d_in[22];
    const float* cscal = (const float*)d_in[23];
    float* out = (float*)d_out;

    Scratch* S = 0;
    cudaGetSymbolAddress((void**)&S, g_scratch);

    if (!g_s1) {
        cudaStreamCreateWithFlags(&g_s1, cudaStreamNonBlocking);
        cudaEventCreateWithFlags(&g_ev0, cudaEventDisableTiming);
        cudaEventCreateWithFlags(&g_evL, cudaEventDisableTiming);
    }

    fused_pre<<<BT_, 256>>>(hs, rnw, rw, pcw, in_ln, S->pred, S->xnorm);

    // fork: laurel chain + v chain on side stream
    cudaEventRecord(g_ev0, 0);
    cudaStreamWaitEvent(g_s1, g_ev0, 0);
    laurel1_kernel<<<dim3(BT_ / 32, 8), 256, 0, g_s1>>>(S->xnorm, llw, S->lrpart);
    laurel1_reduce<<<(BT_ * LR_ + 255) / 256, 256, 0, g_s1>>>(S->lrpart, S->lrbuf);
    mma_nt1<<<dim3(16, 16), 256, 0, g_s1>>>(S->lrbuf, lrw, S->laurel, LR_, LR_, LR_, H_);
    ln_kernel<<<BT_, 256, 0, g_s1>>>(S->laurel, lnw, S->xnorm, (const float*)0, 1.f, S->laurel);
    mma_nt1<<<dim3(16, 4), 256, 0, g_s1>>>(S->xnorm, wv, S->vraw, H_, H_, H_, NKV_ * HD_);
    qkvpost_kernel<<<BT_ * NKV_, 256, 0, g_s1>>>(S->vraw, (const float*)0, cosb, sinb,
                                                 S->vT, NKV_, 0, 1);
    cudaEventRecord(g_evL, g_s1);

    // main: q+k projections (combined), post, scores, softmax
    mma_qk<<<dim3(16, 20), 256>>>(S->xnorm, wq, wk, S->qraw, S->kraw);
    qkvpost_qk<<<BT_ * (NH_ + NKV_), 256>>>(S->qraw, S->kraw, qnw, knw, cosb, sinb, S->q, S->k);
    mma_scores<<<dim3(8, 8, B_ * NH_), 256>>>(S->q, S->k, S->scores);
    softmax_kernel<<<B_ * NH_ * T_, 256>>>(S->scores);

    cudaStreamWaitEvent(0, g_evL, 0);
    mma_attnv<<<dim3(8, 2, B_ * NH_), 256>>>(S->scores, S->vT, S->attnout);
    mma_nt1<<<dim3(16, 16), 256>>>(S->attnout, wo, S->attnproj,
                                   NH_ * HD_, NH_ * HD_, NH_ * HD_, H_);

    fused_mid<<<BT_, 256>>>(S->attnproj, pa_ln, S->pred, S->laurel, pf_ln,
                            S->attnlaurel, S->hn);

    mma_gateup<<<dim3(16, 128), 256>>>(S->hn, gatew, upw, S->gate, S->up);

    int n4 = (int)(((size_t)BT_ * FF_) / 4);
    gelumul_kernel<<<(n4 + 255) / 256, 256>>>(S->gate, S->up, n4);

    mma_nt1<<<dim3(16, 16), 256>>>(S->gate, downw, S->ffw, FF_, FF_, FF_, H_);

    fused_post<<<BT_, 256>>>(S->ffw, pw_ln, S->attnlaurel, rnw, rw, ccw, cscal,
                             S->pred, out);

    (void)in_sizes; (void)n_in; (void)out_size;
}